// round 4
// baseline (speedup 1.0000x reference)
#include <cuda_runtime.h>
#include <math.h>

#define N_CFG 400000
#define E_CFG 1600000
#define N_FUNC 8000
#define N_FCG 9600
#define E_FCG 80000
#define NB 8
#define D_H 128
#define VOCAB 10002

// ---------------- scratch (device globals) ----------------------------------
__device__ float g_a [(size_t)N_CFG * D_H];   // ping (also A0/A1 halves)
__device__ float g_b [(size_t)N_CFG * D_H];   // pong (also B0/B1 halves)
__device__ int   g_deg[N_CFG];
__device__ float g_dis[N_CFG];
__device__ int   g_rowptr[N_CFG];
__device__ int   g_cursor[N_CFG];
__device__ int   g_csr[E_CFG];
__device__ int   g_fdeg[N_FCG];
__device__ float g_fdis[N_FCG];
__device__ int   g_frowptr[N_FCG];
__device__ int   g_fcursor[N_FCG];
__device__ int   g_fcsr[E_FCG];
__device__ int   g_bsum[512];
__device__ int   g_fstart[N_FUNC + 1];
__device__ int   g_bstart[NB + 1];
__device__ float g_pool[N_FUNC * D_H];
__device__ float g_fx [N_FCG * D_H];
__device__ float g_fz [N_FCG * D_H];
__device__ float g_fy [N_FCG * D_H];
__device__ float g_g  [NB * D_H];

// ---------------- degree / norm ---------------------------------------------
__global__ void zerodeg_kernel() {
    int i = blockIdx.x * blockDim.x + threadIdx.x;
    if (i < N_CFG) g_deg[i] = 0;
    if (i < N_FCG) g_fdeg[i] = 0;
}
__global__ void degi_kernel(const int* __restrict__ ei, int E, int* __restrict__ deg) {
    int i = blockIdx.x * blockDim.x + threadIdx.x;
    if (i < E) atomicAdd(&deg[ei[E + i]], 1);
}
__global__ void dis_kernel(const int* __restrict__ deg, float* __restrict__ dis, int n) {
    int i = blockIdx.x * blockDim.x + threadIdx.x;
    if (i < n) dis[i] = rsqrtf((float)deg[i] + 1.0f);
}

// ---------------- CSR build: scan + fill ------------------------------------
__global__ void scan_local(const int* __restrict__ cnt, int n, int* __restrict__ out,
                           int* __restrict__ bsum) {
    __shared__ int s[256];
    int base = blockIdx.x * 1024;
    int t = threadIdx.x;
    int v[4], sum = 0;
#pragma unroll
    for (int j = 0; j < 4; j++) {
        int i = base + t * 4 + j;
        v[j] = (i < n) ? cnt[i] : 0;
        sum += v[j];
    }
    s[t] = sum;
    __syncthreads();
    for (int off = 1; off < 256; off <<= 1) {
        int x = (t >= off) ? s[t - off] : 0;
        __syncthreads();
        s[t] += x;
        __syncthreads();
    }
    if (t == 255) bsum[blockIdx.x] = s[255];
    int run = (t > 0) ? s[t - 1] : 0;
#pragma unroll
    for (int j = 0; j < 4; j++) {
        int i = base + t * 4 + j;
        if (i < n) out[i] = run;
        run += v[j];
    }
}
__global__ void scan_bsum(int* __restrict__ bsum, int nb) {
    __shared__ int s[512];
    int t = threadIdx.x;
    s[t] = (t < nb) ? bsum[t] : 0;
    __syncthreads();
    for (int off = 1; off < 512; off <<= 1) {
        int x = (t >= off) ? s[t - off] : 0;
        __syncthreads();
        s[t] += x;
        __syncthreads();
    }
    if (t < nb) bsum[t] = (t > 0) ? s[t - 1] : 0;
}
__global__ void scan_add(int* __restrict__ out, const int* __restrict__ bsum, int n,
                         int* __restrict__ cursor) {
    int i = blockIdx.x * blockDim.x + threadIdx.x;
    if (i < n) {
        int v = out[i] + bsum[i >> 10];
        out[i] = v;
        cursor[i] = v;
    }
}
__global__ void fill_csr(const int* __restrict__ ei, int E, int* __restrict__ cursor,
                         int* __restrict__ csr) {
    int i = blockIdx.x * blockDim.x + threadIdx.x;
    if (i < E) {
        int r = ei[i], c = ei[E + i];
        int slot = atomicAdd(&cursor[c], 1);
        csr[slot] = r;
    }
}

__global__ void seg_bounds(const int* __restrict__ seg, int n, int nseg, int* __restrict__ start) {
    int f = blockIdx.x * blockDim.x + threadIdx.x;
    if (f > nseg) return;
    int lo = 0, hi = n;
    while (lo < hi) {
        int mid = (lo + hi) >> 1;
        if (seg[mid] < f) lo = mid + 1; else hi = mid;
    }
    start[f] = lo;
}

// ---------------- GEMM: H = relu(X @ W + b) [* dis[row]] --------------------
// 128x128 block tile, 8x8 thread tile, fma.rn.f32x2, X staged DUPLICATED {a,a}.
// SPLIT_IN : X read from two half-width (stride-64) arrays X0 (k<64), X1 (k>=64)
// SPLIT_OUT: H written to two half-width (stride-64) arrays H0 (c<64), H1 (c>=64)
#define KC 16
template<int K, bool SCALE, bool SPLIT_IN, bool SPLIT_OUT>
__global__ __launch_bounds__(256, 2) void gemmx_kernel(
    const float* __restrict__ X0, const float* __restrict__ X1,
    const float* __restrict__ W,
    const float* __restrict__ bias, const float* __restrict__ dis,
    float* __restrict__ H0, float* __restrict__ H1, int N) {
    __shared__ float2 Xs2[KC * 130];          // duplicated {a,a}, pitch 130
    __shared__ float  Ws[KC * 128];
    const int row0 = blockIdx.x * 128;
    const int tx = threadIdx.x & 15;
    const int ty = threadIdx.x >> 4;
    const int c0 = tx * 8, r0 = ty * 8;

    unsigned long long acc2[8][4];
#pragma unroll
    for (int r = 0; r < 8; r++)
#pragma unroll
        for (int j = 0; j < 4; j++) acc2[r][j] = 0ULL;

    const int xstride = SPLIT_IN ? 64 : K;

    for (int kc = 0; kc < K; kc += KC) {
        const float* Xp = (SPLIT_IN && kc >= 64) ? X1 : X0;
        const int kk = SPLIT_IN ? (kc & 63) : kc;
#pragma unroll
        for (int i = threadIdx.x; i < 128 * KC; i += 256) {
            int k = i & (KC - 1), r = i >> 4;
            float v = Xp[(size_t)(row0 + r) * xstride + kk + k];
            Xs2[k * 130 + r] = make_float2(v, v);
        }
#pragma unroll
        for (int i = threadIdx.x; i < KC * 128; i += 256) {
            int c = i & 127, k = i >> 7;
            Ws[k * 128 + c] = W[(size_t)(kc + k) * 128 + c];
        }
        __syncthreads();
#pragma unroll 4
        for (int k = 0; k < KC; k++) {
            const ulonglong2* xp = (const ulonglong2*)&Xs2[k * 130 + r0];
            ulonglong2 x01 = xp[0], x23 = xp[1], x45 = xp[2], x67 = xp[3];
            ulonglong2 wl = *(const ulonglong2*)&Ws[k * 128 + c0];
            ulonglong2 wh = *(const ulonglong2*)&Ws[k * 128 + c0 + 4];
            unsigned long long a2[8] = {x01.x, x01.y, x23.x, x23.y,
                                        x45.x, x45.y, x67.x, x67.y};
            unsigned long long w2[4] = {wl.x, wl.y, wh.x, wh.y};
#pragma unroll
            for (int r = 0; r < 8; r++)
#pragma unroll
                for (int j = 0; j < 4; j++)
                    asm("fma.rn.f32x2 %0, %1, %2, %0;"
                        : "+l"(acc2[r][j]) : "l"(a2[r]), "l"(w2[j]));
        }
        __syncthreads();
    }

    float bb[8];
#pragma unroll
    for (int j = 0; j < 8; j++) bb[j] = bias[c0 + j];
#pragma unroll
    for (int r = 0; r < 8; r++) {
        int gr = row0 + r0 + r;
        if (gr >= N) return;
        float s = SCALE ? dis[gr] : 1.0f;
        float o[8];
#pragma unroll
        for (int j = 0; j < 4; j++) {
            float lo, hi;
            asm("mov.b64 {%0, %1}, %2;" : "=f"(lo), "=f"(hi) : "l"(acc2[r][j]));
            o[2 * j]     = fmaxf(lo + bb[2 * j], 0.f) * s;
            o[2 * j + 1] = fmaxf(hi + bb[2 * j + 1], 0.f) * s;
        }
        if (SPLIT_OUT) {
            float* Hp = (c0 < 64) ? H0 : H1;
            int cc = c0 & 63;
            *(float4*)&Hp[(size_t)gr * 64 + cc]     = make_float4(o[0], o[1], o[2], o[3]);
            *(float4*)&Hp[(size_t)gr * 64 + cc + 4] = make_float4(o[4], o[5], o[6], o[7]);
        } else {
            *(float4*)&H0[(size_t)gr * 128 + c0]     = make_float4(o[0], o[1], o[2], o[3]);
            *(float4*)&H0[(size_t)gr * 128 + c0 + 4] = make_float4(o[4], o[5], o[6], o[7]);
        }
    }
}

// ---------------- gather 64ch, dis folded on the fly (layer 1) ---------------
// out[v] = (x[v]*dis[v] + sum_u x[u]*dis[u]) * dis[v]
__global__ __launch_bounds__(256) void gather64_kernel(
    const int* __restrict__ rowptr, const int* __restrict__ deg,
    const int* __restrict__ csr, const float* __restrict__ x,
    const float* __restrict__ dis, float* __restrict__ out, int n) {
    int node = (blockIdx.x * 256 + threadIdx.x) >> 5;
    int lane = threadIdx.x & 31;
    if (node >= n) return;
    const float2* x2 = (const float2*)x;
    float dn = dis[node];
    float2 v = x2[(size_t)node * 32 + lane];
    float2 acc; acc.x = v.x * dn; acc.y = v.y * dn;
    int start = rowptr[node], d = deg[node];
    for (int e = 0; e < d; e++) {
        int u = csr[start + e];
        float du = dis[u];
        float2 w = x2[(size_t)u * 32 + lane];
        acc.x += w.x * du; acc.y += w.y * du;
    }
    acc.x *= dn; acc.y *= dn;
    ((float2*)out)[(size_t)node * 32 + lane] = acc;
}

// ---------------- gather 64ch, prescaled input (layer-2 halves) --------------
// out[v] = (h[v] + sum_u h[u]) * dis[v]     (h already has dis[row] folded)
__global__ __launch_bounds__(256) void gather64pre_kernel(
    const int* __restrict__ rowptr, const int* __restrict__ deg,
    const int* __restrict__ csr, const float* __restrict__ h,
    const float* __restrict__ dis, float* __restrict__ out, int n) {
    int node = (blockIdx.x * 256 + threadIdx.x) >> 5;
    int lane = threadIdx.x & 31;
    if (node >= n) return;
    const float2* h2 = (const float2*)h;
    float2 acc = h2[(size_t)node * 32 + lane];
    int start = rowptr[node], d = deg[node];
    for (int e = 0; e < d; e++) {
        int u = csr[start + e];
        float2 w = h2[(size_t)u * 32 + lane];
        acc.x += w.x; acc.y += w.y;
    }
    float dn = dis[node];
    acc.x *= dn; acc.y *= dn;
    ((float2*)out)[(size_t)node * 32 + lane] = acc;
}

// ---------------- gather 128ch (FCG, dis folded on the fly) ------------------
__global__ __launch_bounds__(256) void gather128_kernel(
    const int* __restrict__ rowptr, const int* __restrict__ deg,
    const int* __restrict__ csr, const float* __restrict__ hs,
    const float* __restrict__ dis, float* __restrict__ out, int n) {
    int node = (blockIdx.x * 256 + threadIdx.x) >> 5;
    int lane = threadIdx.x & 31;
    if (node >= n) return;
    const float4* hs4 = (const float4*)hs;
    float dn = dis[node];
    float4 acc = hs4[(size_t)node * 32 + lane];
    acc.x *= dn; acc.y *= dn; acc.z *= dn; acc.w *= dn;
    int start = rowptr[node], d = deg[node];
    for (int e = 0; e < d; e++) {
        int u = csr[start + e];
        float4 v = hs4[(size_t)u * 32 + lane];
        float du = dis[u];
        acc.x += v.x * du; acc.y += v.y * du;
        acc.z += v.z * du; acc.w += v.w * du;
    }
    acc.x *= dn; acc.y *= dn; acc.z *= dn; acc.w *= dn;
    ((float4*)out)[(size_t)node * 32 + lane] = acc;
}

// ---------------- function-level mean pool -----------------------------------
__global__ __launch_bounds__(256) void poolseg_kernel(
    const float* __restrict__ x, const int* __restrict__ start,
    float* __restrict__ pool, int nseg) {
    int f = (blockIdx.x * 256 + threadIdx.x) >> 5;
    int lane = threadIdx.x & 31;
    if (f >= nseg) return;
    int s = start[f], e = start[f + 1];
    const float4* x4 = (const float4*)x;
    float4 acc = make_float4(0.f, 0.f, 0.f, 0.f);
    for (int i = s; i < e; i++) {
        float4 v = x4[(size_t)i * 32 + lane];
        acc.x += v.x; acc.y += v.y; acc.z += v.z; acc.w += v.w;
    }
    float inv = 1.0f / (float)max(e - s, 1);
    acc.x *= inv; acc.y *= inv; acc.z *= inv; acc.w *= inv;
    ((float4*)pool)[(size_t)f * 32 + lane] = acc;
}

__global__ void assemble_kernel(const float* __restrict__ pool, const float* __restrict__ emb,
                                const int* __restrict__ src, const int* __restrict__ isext,
                                float* __restrict__ fx) {
    int i = blockIdx.x * blockDim.x + threadIdx.x;
    if (i >= N_FCG * D_H) return;
    int row = i >> 7, j = i & 127;
    int s = src[row];
    float v;
    if (isext[row] == 1) {
        int k = min(max(s, 0), VOCAB - 1);
        v = emb[(size_t)k * D_H + j];
    } else {
        int k = min(max(s, 0), N_FUNC - 1);
        v = pool[(size_t)k * D_H + j];
    }
    fx[i] = v;
}

__global__ __launch_bounds__(128) void gpool_kernel(
    const float* __restrict__ y, const int* __restrict__ start, float* __restrict__ g) {
    int b = blockIdx.x, col = threadIdx.x;
    int s = start[b], e = start[b + 1];
    float acc = 0.f;
    for (int i = s; i < e; i++) acc += y[(size_t)i * 128 + col];
    g[b * 128 + col] = acc / (float)max(e - s, 1);
}

__global__ __launch_bounds__(256) void head_kernel(
    const float* __restrict__ g,
    const float* __restrict__ Wp1, const float* __restrict__ bp1,
    const float* __restrict__ Wp2, const float* __restrict__ bp2,
    const float* __restrict__ Wp3, const float* __restrict__ bp3,
    float* __restrict__ out) {
    __shared__ float G[NB * 128], H1[NB * 64], H2[NB * 32];
    int t = threadIdx.x;
    for (int i = t; i < NB * 128; i += 256) G[i] = g[i];
    __syncthreads();
    for (int i = t; i < NB * 64; i += 256) {
        int r = i >> 6, c = i & 63;
        float a = bp1[c];
        for (int k = 0; k < 128; k++) a += G[r * 128 + k] * Wp1[k * 64 + c];
        H1[i] = fmaxf(a, 0.f);
    }
    __syncthreads();
    for (int i = t; i < NB * 32; i += 256) {
        int r = i >> 5, c = i & 31;
        float a = bp2[c];
        for (int k = 0; k < 64; k++) a += H1[r * 64 + k] * Wp2[k * 32 + c];
        H2[i] = fmaxf(a, 0.f);
    }
    __syncthreads();
    if (t < NB) {
        float a = bp3[0];
        for (int k = 0; k < 32; k++) a += H2[t * 32 + k] * Wp3[k];
        out[t] = 1.0f / (1.0f + expf(-a));
    }
}

// ---------------- launch ----------------------------------------------------
extern "C" void kernel_launch(void* const* d_in, const int* in_sizes, int n_in,
                              void* d_out, int out_size) {
    const float* cfg_x  = (const float*)d_in[0];
    const int*   cfg_ei = (const int*)  d_in[1];
    const int*   n2f    = (const int*)  d_in[2];
    const int*   fcg_ei = (const int*)  d_in[3];
    const int*   fbatch = (const int*)  d_in[4];
    const int*   fsrc   = (const int*)  d_in[5];
    const int*   fext   = (const int*)  d_in[6];
    const float* W1  = (const float*)d_in[7];
    const float* b1  = (const float*)d_in[8];
    const float* W2  = (const float*)d_in[9];
    const float* b2  = (const float*)d_in[10];
    const float* emb = (const float*)d_in[11];
    const float* Wf  = (const float*)d_in[12];
    const float* bf  = (const float*)d_in[13];
    const float* Wp1 = (const float*)d_in[14];
    const float* bp1 = (const float*)d_in[15];
    const float* Wp2 = (const float*)d_in[16];
    const float* bp2 = (const float*)d_in[17];
    const float* Wp3 = (const float*)d_in[18];
    const float* bp3 = (const float*)d_in[19];
    float* out = (float*)d_out;

    void *p;
    cudaGetSymbolAddress(&p, g_a);       float* A      = (float*)p;
    cudaGetSymbolAddress(&p, g_b);       float* Bb     = (float*)p;
    cudaGetSymbolAddress(&p, g_deg);     int*   deg    = (int*)p;
    cudaGetSymbolAddress(&p, g_dis);     float* dis    = (float*)p;
    cudaGetSymbolAddress(&p, g_rowptr);  int*   rowptr = (int*)p;
    cudaGetSymbolAddress(&p, g_cursor);  int*   cursor = (int*)p;
    cudaGetSymbolAddress(&p, g_csr);     int*   csr    = (int*)p;
    cudaGetSymbolAddress(&p, g_fdeg);    int*   fdeg   = (int*)p;
    cudaGetSymbolAddress(&p, g_fdis);    float* fdis   = (float*)p;
    cudaGetSymbolAddress(&p, g_frowptr); int*   frowptr= (int*)p;
    cudaGetSymbolAddress(&p, g_fcursor); int*   fcursor= (int*)p;
    cudaGetSymbolAddress(&p, g_fcsr);    int*   fcsr   = (int*)p;
    cudaGetSymbolAddress(&p, g_bsum);    int*   bsum   = (int*)p;
    cudaGetSymbolAddress(&p, g_fstart);  int*   fstart = (int*)p;
    cudaGetSymbolAddress(&p, g_bstart);  int*   bstart = (int*)p;
    cudaGetSymbolAddress(&p, g_pool);    float* pool   = (float*)p;
    cudaGetSymbolAddress(&p, g_fx);      float* fx     = (float*)p;
    cudaGetSymbolAddress(&p, g_fz);      float* fz     = (float*)p;
    cudaGetSymbolAddress(&p, g_fy);      float* fy     = (float*)p;
    cudaGetSymbolAddress(&p, g_g);       float* gg     = (float*)p;

    float* A0 = A;                          // ch 0-63   [N_CFG x 64]
    float* A1 = A + (size_t)N_CFG * 64;     // ch 64-127 [N_CFG x 64]
    float* B0 = Bb;
    float* B1 = Bb + (size_t)N_CFG * 64;

    // degrees + norms
    zerodeg_kernel<<<(N_CFG + 255) / 256, 256>>>();
    degi_kernel<<<(E_CFG + 255) / 256, 256>>>(cfg_ei, E_CFG, deg);
    degi_kernel<<<(E_FCG + 255) / 256, 256>>>(fcg_ei, E_FCG, fdeg);
    dis_kernel<<<(N_CFG + 255) / 256, 256>>>(deg, dis, N_CFG);
    dis_kernel<<<(N_FCG + 255) / 256, 256>>>(fdeg, fdis, N_FCG);

    // CSR build (CFG)
    const int NBLK_CFG = (N_CFG + 1023) / 1024;
    scan_local<<<NBLK_CFG, 256>>>(deg, N_CFG, rowptr, bsum);
    scan_bsum<<<1, 512>>>(bsum, NBLK_CFG);
    scan_add<<<(N_CFG + 255) / 256, 256>>>(rowptr, bsum, N_CFG, cursor);
    fill_csr<<<(E_CFG + 255) / 256, 256>>>(cfg_ei, E_CFG, cursor, csr);

    // CSR build (FCG)
    const int NBLK_FCG = (N_FCG + 1023) / 1024;
    scan_local<<<NBLK_FCG, 256>>>(fdeg, N_FCG, frowptr, bsum);
    scan_bsum<<<1, 512>>>(bsum, NBLK_FCG);
    scan_add<<<(N_FCG + 255) / 256, 256>>>(frowptr, bsum, N_FCG, fcursor);
    fill_csr<<<(E_FCG + 255) / 256, 256>>>(fcg_ei, E_FCG, fcursor, fcsr);

    // sorted-segment bounds
    seg_bounds<<<(N_FUNC + 256) / 256, 256>>>(n2f, N_CFG, N_FUNC, fstart);
    seg_bounds<<<1, 32>>>(fbatch, N_FCG, NB, bstart);

    // CFG layer 1: z1 = Ahat(cfg_x) [64ch] -> hs2 = relu(z1@W1+b1)*dis, split halves
    gather64_kernel<<<(N_CFG * 32 + 255) / 256, 256>>>(rowptr, deg, csr, cfg_x, dis, Bb, N_CFG);
    gemmx_kernel<64, true, false, true><<<N_CFG / 128, 256>>>(Bb, nullptr, W1, b1, dis, A0, A1, N_CFG);

    // CFG layer 2: per-half aggregation (each half 102MB -> L2 resident), then GEMM
    gather64pre_kernel<<<(N_CFG * 32 + 255) / 256, 256>>>(rowptr, deg, csr, A0, dis, B0, N_CFG);
    gather64pre_kernel<<<(N_CFG * 32 + 255) / 256, 256>>>(rowptr, deg, csr, A1, dis, B1, N_CFG);
    gemmx_kernel<128, false, true, false><<<N_CFG / 128, 256>>>(B0, B1, W2, b2, dis, A, nullptr, N_CFG);

    // function-level mean pool
    poolseg_kernel<<<(N_FUNC * 32 + 255) / 256, 256>>>(A, fstart, pool, N_FUNC);

    // FCG features + FCG layer
    assemble_kernel<<<(N_FCG * D_H) / 256, 256>>>(pool, emb, fsrc, fext, fx);
    gather128_kernel<<<(N_FCG * 32 + 255) / 256, 256>>>(frowptr, fdeg, fcsr, fx, fdis, fz, N_FCG);
    gemmx_kernel<128, false, false, false><<<N_FCG / 128, 256>>>(fz, nullptr, Wf, bf, fdis, fy, nullptr, N_FCG);

    // binary-level mean pool + head
    gpool_kernel<<<NB, 128>>>(fy, bstart, gg);
    head_kernel<<<1, 256>>>(gg, Wp1, bp1, Wp2, bp2, Wp3, bp3, out);
}

// round 5
// speedup vs baseline: 1.1174x; 1.1174x over previous
#include <cuda_runtime.h>
#include <math.h>

#define N_CFG 400000
#define E_CFG 1600000
#define N_FUNC 8000
#define N_FCG 9600
#define E_FCG 80000
#define NB 8
#define D_H 128
#define VOCAB 10002

// ---------------- scratch (device globals) ----------------------------------
__device__ float g_a [(size_t)N_CFG * D_H];   // ping
__device__ float g_b [(size_t)N_CFG * D_H];   // pong
__device__ int   g_deg[N_CFG];
__device__ float g_dis[N_CFG];
__device__ int   g_rowptr[N_CFG];
__device__ int   g_cursor[N_CFG];
__device__ int   g_csr[E_CFG];
__device__ int   g_fdeg[N_FCG];
__device__ float g_fdis[N_FCG];
__device__ int   g_frowptr[N_FCG];
__device__ int   g_fcursor[N_FCG];
__device__ int   g_fcsr[E_FCG];
__device__ int   g_bsum[512];
__device__ int   g_fstart[N_FUNC + 1];
__device__ int   g_bstart[NB + 1];
__device__ float g_pool[N_FUNC * D_H];
__device__ float g_fx [N_FCG * D_H];
__device__ float g_fz [N_FCG * D_H];
__device__ float g_fy [N_FCG * D_H];
__device__ float g_g  [NB * D_H];

// ---------------- degree / norm ---------------------------------------------
__global__ void zerodeg_kernel() {
    int i = blockIdx.x * blockDim.x + threadIdx.x;
    if (i < N_CFG) g_deg[i] = 0;
    if (i < N_FCG) g_fdeg[i] = 0;
}
__global__ void degi_kernel(const int* __restrict__ ei, int E, int* __restrict__ deg) {
    int i = blockIdx.x * blockDim.x + threadIdx.x;
    if (i < E) atomicAdd(&deg[ei[E + i]], 1);
}
__global__ void dis_kernel(const int* __restrict__ deg, float* __restrict__ dis, int n) {
    int i = blockIdx.x * blockDim.x + threadIdx.x;
    if (i < n) dis[i] = rsqrtf((float)deg[i] + 1.0f);
}

// ---------------- CSR build: scan + fill ------------------------------------
__global__ void scan_local(const int* __restrict__ cnt, int n, int* __restrict__ out,
                           int* __restrict__ bsum) {
    __shared__ int s[256];
    int base = blockIdx.x * 1024;
    int t = threadIdx.x;
    int v[4], sum = 0;
#pragma unroll
    for (int j = 0; j < 4; j++) {
        int i = base + t * 4 + j;
        v[j] = (i < n) ? cnt[i] : 0;
        sum += v[j];
    }
    s[t] = sum;
    __syncthreads();
    for (int off = 1; off < 256; off <<= 1) {
        int x = (t >= off) ? s[t - off] : 0;
        __syncthreads();
        s[t] += x;
        __syncthreads();
    }
    if (t == 255) bsum[blockIdx.x] = s[255];
    int run = (t > 0) ? s[t - 1] : 0;
#pragma unroll
    for (int j = 0; j < 4; j++) {
        int i = base + t * 4 + j;
        if (i < n) out[i] = run;
        run += v[j];
    }
}
__global__ void scan_bsum(int* __restrict__ bsum, int nb) {
    __shared__ int s[512];
    int t = threadIdx.x;
    s[t] = (t < nb) ? bsum[t] : 0;
    __syncthreads();
    for (int off = 1; off < 512; off <<= 1) {
        int x = (t >= off) ? s[t - off] : 0;
        __syncthreads();
        s[t] += x;
        __syncthreads();
    }
    if (t < nb) bsum[t] = (t > 0) ? s[t - 1] : 0;
}
__global__ void scan_add(int* __restrict__ out, const int* __restrict__ bsum, int n,
                         int* __restrict__ cursor) {
    int i = blockIdx.x * blockDim.x + threadIdx.x;
    if (i < n) {
        int v = out[i] + bsum[i >> 10];
        out[i] = v;
        cursor[i] = v;
    }
}
__global__ void fill_csr(const int* __restrict__ ei, int E, int* __restrict__ cursor,
                         int* __restrict__ csr) {
    int i = blockIdx.x * blockDim.x + threadIdx.x;
    if (i < E) {
        int r = ei[i], c = ei[E + i];
        int slot = atomicAdd(&cursor[c], 1);
        csr[slot] = r;
    }
}

__global__ void seg_bounds(const int* __restrict__ seg, int n, int nseg, int* __restrict__ start) {
    int f = blockIdx.x * blockDim.x + threadIdx.x;
    if (f > nseg) return;
    int lo = 0, hi = n;
    while (lo < hi) {
        int mid = (lo + hi) >> 1;
        if (seg[mid] < f) lo = mid + 1; else hi = mid;
    }
    start[f] = lo;
}

// ---------------- GEMM: H = relu(X @ W + b) [* dis[row]] --------------------
// 128x128 block tile, 8x8 thread tile, fma.rn.f32x2, X staged DUPLICATED {a,a}.
#define KC 16
template<int K, bool SCALE>
__global__ __launch_bounds__(256, 2) void gemmx_kernel(
    const float* __restrict__ X, const float* __restrict__ W,
    const float* __restrict__ bias, const float* __restrict__ dis,
    float* __restrict__ H, int N) {
    __shared__ float2 Xs2[KC * 130];          // duplicated {a,a}, pitch 130
    __shared__ float  Ws[KC * 128];
    const int row0 = blockIdx.x * 128;
    const int tx = threadIdx.x & 15;
    const int ty = threadIdx.x >> 4;
    const int c0 = tx * 8, r0 = ty * 8;

    unsigned long long acc2[8][4];
#pragma unroll
    for (int r = 0; r < 8; r++)
#pragma unroll
        for (int j = 0; j < 4; j++) acc2[r][j] = 0ULL;

    for (int kc = 0; kc < K; kc += KC) {
#pragma unroll
        for (int i = threadIdx.x; i < 128 * KC; i += 256) {
            int k = i & (KC - 1), r = i >> 4;
            float v = X[(size_t)(row0 + r) * K + kc + k];
            Xs2[k * 130 + r] = make_float2(v, v);
        }
#pragma unroll
        for (int i = threadIdx.x; i < KC * 128; i += 256) {
            int c = i & 127, k = i >> 7;
            Ws[k * 128 + c] = W[(size_t)(kc + k) * 128 + c];
        }
        __syncthreads();
#pragma unroll 4
        for (int k = 0; k < KC; k++) {
            const ulonglong2* xp = (const ulonglong2*)&Xs2[k * 130 + r0];
            ulonglong2 x01 = xp[0], x23 = xp[1], x45 = xp[2], x67 = xp[3];
            ulonglong2 wl = *(const ulonglong2*)&Ws[k * 128 + c0];
            ulonglong2 wh = *(const ulonglong2*)&Ws[k * 128 + c0 + 4];
            unsigned long long a2[8] = {x01.x, x01.y, x23.x, x23.y,
                                        x45.x, x45.y, x67.x, x67.y};
            unsigned long long w2[4] = {wl.x, wl.y, wh.x, wh.y};
#pragma unroll
            for (int r = 0; r < 8; r++)
#pragma unroll
                for (int j = 0; j < 4; j++)
                    asm("fma.rn.f32x2 %0, %1, %2, %0;"
                        : "+l"(acc2[r][j]) : "l"(a2[r]), "l"(w2[j]));
        }
        __syncthreads();
    }

    float bb[8];
#pragma unroll
    for (int j = 0; j < 8; j++) bb[j] = bias[c0 + j];
#pragma unroll
    for (int r = 0; r < 8; r++) {
        int gr = row0 + r0 + r;
        if (gr >= N) return;
        float s = SCALE ? dis[gr] : 1.0f;
        float o[8];
#pragma unroll
        for (int j = 0; j < 4; j++) {
            float lo, hi;
            asm("mov.b64 {%0, %1}, %2;" : "=f"(lo), "=f"(hi) : "l"(acc2[r][j]));
            o[2 * j]     = fmaxf(lo + bb[2 * j], 0.f) * s;
            o[2 * j + 1] = fmaxf(hi + bb[2 * j + 1], 0.f) * s;
        }
        *(float4*)&H[(size_t)gr * 128 + c0]     = make_float4(o[0], o[1], o[2], o[3]);
        *(float4*)&H[(size_t)gr * 128 + c0 + 4] = make_float4(o[4], o[5], o[6], o[7]);
    }
}

// ---------------- gather 64ch, dis folded (layer 1), edge loop unrolled x4 ---
// out[v] = (x[v]*dis[v] + sum_u x[u]*dis[u]) * dis[v]
__global__ __launch_bounds__(256) void gather64_kernel(
    const int* __restrict__ rowptr, const int* __restrict__ deg,
    const int* __restrict__ csr, const float* __restrict__ x,
    const float* __restrict__ dis, float* __restrict__ out, int n) {
    int node = (blockIdx.x * 256 + threadIdx.x) >> 5;
    int lane = threadIdx.x & 31;
    if (node >= n) return;
    const float2* x2 = (const float2*)x;
    float dn = dis[node];
    float2 v = x2[(size_t)node * 32 + lane];
    float ax = v.x * dn, ay = v.y * dn;
    float bx = 0.f, by = 0.f;
    int e = rowptr[node];
    int end = e + deg[node];
    for (; e + 4 <= end; e += 4) {
        int u0 = csr[e], u1 = csr[e + 1], u2 = csr[e + 2], u3 = csr[e + 3];
        float d0 = dis[u0], d1 = dis[u1], d2 = dis[u2], d3 = dis[u3];
        float2 w0 = x2[(size_t)u0 * 32 + lane];
        float2 w1 = x2[(size_t)u1 * 32 + lane];
        float2 w2 = x2[(size_t)u2 * 32 + lane];
        float2 w3 = x2[(size_t)u3 * 32 + lane];
        ax += w0.x * d0; ay += w0.y * d0;
        bx += w1.x * d1; by += w1.y * d1;
        ax += w2.x * d2; ay += w2.y * d2;
        bx += w3.x * d3; by += w3.y * d3;
    }
    for (; e < end; e++) {
        int u = csr[e];
        float du = dis[u];
        float2 w = x2[(size_t)u * 32 + lane];
        ax += w.x * du; ay += w.y * du;
    }
    float2 acc;
    acc.x = (ax + bx) * dn; acc.y = (ay + by) * dn;
    ((float2*)out)[(size_t)node * 32 + lane] = acc;
}

// ---------------- gather 128ch, prescaled input (layer 2), unrolled x4 -------
// out[v] = (h[v] + sum_u h[u]) * dis[v]     (h already has dis[row] folded)
__global__ __launch_bounds__(256) void gather128pre_kernel(
    const int* __restrict__ rowptr, const int* __restrict__ deg,
    const int* __restrict__ csr, const float* __restrict__ h,
    const float* __restrict__ dis, float* __restrict__ out, int n) {
    int node = (blockIdx.x * 256 + threadIdx.x) >> 5;
    int lane = threadIdx.x & 31;
    if (node >= n) return;
    const float4* h4 = (const float4*)h;
    float4 a = h4[(size_t)node * 32 + lane];
    float4 b = make_float4(0.f, 0.f, 0.f, 0.f);
    int e = rowptr[node];
    int end = e + deg[node];
    for (; e + 4 <= end; e += 4) {
        int u0 = csr[e], u1 = csr[e + 1], u2 = csr[e + 2], u3 = csr[e + 3];
        float4 w0 = h4[(size_t)u0 * 32 + lane];
        float4 w1 = h4[(size_t)u1 * 32 + lane];
        float4 w2 = h4[(size_t)u2 * 32 + lane];
        float4 w3 = h4[(size_t)u3 * 32 + lane];
        a.x += w0.x; a.y += w0.y; a.z += w0.z; a.w += w0.w;
        b.x += w1.x; b.y += w1.y; b.z += w1.z; b.w += w1.w;
        a.x += w2.x; a.y += w2.y; a.z += w2.z; a.w += w2.w;
        b.x += w3.x; b.y += w3.y; b.z += w3.z; b.w += w3.w;
    }
    for (; e < end; e++) {
        int u = csr[e];
        float4 w = h4[(size_t)u * 32 + lane];
        a.x += w.x; a.y += w.y; a.z += w.z; a.w += w.w;
    }
    float dn = dis[node];
    float4 acc;
    acc.x = (a.x + b.x) * dn; acc.y = (a.y + b.y) * dn;
    acc.z = (a.z + b.z) * dn; acc.w = (a.w + b.w) * dn;
    ((float4*)out)[(size_t)node * 32 + lane] = acc;
}

// ---------------- gather 128ch (FCG, dis folded on the fly) ------------------
__global__ __launch_bounds__(256) void gather128_kernel(
    const int* __restrict__ rowptr, const int* __restrict__ deg,
    const int* __restrict__ csr, const float* __restrict__ hs,
    const float* __restrict__ dis, float* __restrict__ out, int n) {
    int node = (blockIdx.x * 256 + threadIdx.x) >> 5;
    int lane = threadIdx.x & 31;
    if (node >= n) return;
    const float4* hs4 = (const float4*)hs;
    float dn = dis[node];
    float4 acc = hs4[(size_t)node * 32 + lane];
    acc.x *= dn; acc.y *= dn; acc.z *= dn; acc.w *= dn;
    int start = rowptr[node], d = deg[node];
    for (int e = 0; e < d; e++) {
        int u = csr[start + e];
        float4 v = hs4[(size_t)u * 32 + lane];
        float du = dis[u];
        acc.x += v.x * du; acc.y += v.y * du;
        acc.z += v.z * du; acc.w += v.w * du;
    }
    acc.x *= dn; acc.y *= dn; acc.z *= dn; acc.w *= dn;
    ((float4*)out)[(size_t)node * 32 + lane] = acc;
}

// ---------------- function-level mean pool -----------------------------------
__global__ __launch_bounds__(256) void poolseg_kernel(
    const float* __restrict__ x, const int* __restrict__ start,
    float* __restrict__ pool, int nseg) {
    int f = (blockIdx.x * 256 + threadIdx.x) >> 5;
    int lane = threadIdx.x & 31;
    if (f >= nseg) return;
    int s = start[f], e = start[f + 1];
    const float4* x4 = (const float4*)x;
    float4 acc = make_float4(0.f, 0.f, 0.f, 0.f);
    for (int i = s; i < e; i++) {
        float4 v = x4[(size_t)i * 32 + lane];
        acc.x += v.x; acc.y += v.y; acc.z += v.z; acc.w += v.w;
    }
    float inv = 1.0f / (float)max(e - s, 1);
    acc.x *= inv; acc.y *= inv; acc.z *= inv; acc.w *= inv;
    ((float4*)pool)[(size_t)f * 32 + lane] = acc;
}

__global__ void assemble_kernel(const float* __restrict__ pool, const float* __restrict__ emb,
                                const int* __restrict__ src, const int* __restrict__ isext,
                                float* __restrict__ fx) {
    int i = blockIdx.x * blockDim.x + threadIdx.x;
    if (i >= N_FCG * D_H) return;
    int row = i >> 7, j = i & 127;
    int s = src[row];
    float v;
    if (isext[row] == 1) {
        int k = min(max(s, 0), VOCAB - 1);
        v = emb[(size_t)k * D_H + j];
    } else {
        int k = min(max(s, 0), N_FUNC - 1);
        v = pool[(size_t)k * D_H + j];
    }
    fx[i] = v;
}

__global__ __launch_bounds__(128) void gpool_kernel(
    const float* __restrict__ y, const int* __restrict__ start, float* __restrict__ g) {
    int b = blockIdx.x, col = threadIdx.x;
    int s = start[b], e = start[b + 1];
    float acc = 0.f;
    for (int i = s; i < e; i++) acc += y[(size_t)i * 128 + col];
    g[b * 128 + col] = acc / (float)max(e - s, 1);
}

__global__ __launch_bounds__(256) void head_kernel(
    const float* __restrict__ g,
    const float* __restrict__ Wp1, const float* __restrict__ bp1,
    const float* __restrict__ Wp2, const float* __restrict__ bp2,
    const float* __restrict__ Wp3, const float* __restrict__ bp3,
    float* __restrict__ out) {
    __shared__ float G[NB * 128], H1[NB * 64], H2[NB * 32];
    int t = threadIdx.x;
    for (int i = t; i < NB * 128; i += 256) G[i] = g[i];
    __syncthreads();
    for (int i = t; i < NB * 64; i += 256) {
        int r = i >> 6, c = i & 63;
        float a = bp1[c];
        for (int k = 0; k < 128; k++) a += G[r * 128 + k] * Wp1[k * 64 + c];
        H1[i] = fmaxf(a, 0.f);
    }
    __syncthreads();
    for (int i = t; i < NB * 32; i += 256) {
        int r = i >> 5, c = i & 31;
        float a = bp2[c];
        for (int k = 0; k < 64; k++) a += H1[r * 64 + k] * Wp2[k * 32 + c];
        H2[i] = fmaxf(a, 0.f);
    }
    __syncthreads();
    if (t < NB) {
        float a = bp3[0];
        for (int k = 0; k < 32; k++) a += H2[t * 32 + k] * Wp3[k];
        out[t] = 1.0f / (1.0f + expf(-a));
    }
}

// ---------------- launch ----------------------------------------------------
extern "C" void kernel_launch(void* const* d_in, const int* in_sizes, int n_in,
                              void* d_out, int out_size) {
    const float* cfg_x  = (const float*)d_in[0];
    const int*   cfg_ei = (const int*)  d_in[1];
    const int*   n2f    = (const int*)  d_in[2];
    const int*   fcg_ei = (const int*)  d_in[3];
    const int*   fbatch = (const int*)  d_in[4];
    const int*   fsrc   = (const int*)  d_in[5];
    const int*   fext   = (const int*)  d_in[6];
    const float* W1  = (const float*)d_in[7];
    const float* b1  = (const float*)d_in[8];
    const float* W2  = (const float*)d_in[9];
    const float* b2  = (const float*)d_in[10];
    const float* emb = (const float*)d_in[11];
    const float* Wf  = (const float*)d_in[12];
    const float* bf  = (const float*)d_in[13];
    const float* Wp1 = (const float*)d_in[14];
    const float* bp1 = (const float*)d_in[15];
    const float* Wp2 = (const float*)d_in[16];
    const float* bp2 = (const float*)d_in[17];
    const float* Wp3 = (const float*)d_in[18];
    const float* bp3 = (const float*)d_in[19];
    float* out = (float*)d_out;

    void *p;
    cudaGetSymbolAddress(&p, g_a);       float* A      = (float*)p;
    cudaGetSymbolAddress(&p, g_b);       float* Bb     = (float*)p;
    cudaGetSymbolAddress(&p, g_deg);     int*   deg    = (int*)p;
    cudaGetSymbolAddress(&p, g_dis);     float* dis    = (float*)p;
    cudaGetSymbolAddress(&p, g_rowptr);  int*   rowptr = (int*)p;
    cudaGetSymbolAddress(&p, g_cursor);  int*   cursor = (int*)p;
    cudaGetSymbolAddress(&p, g_csr);     int*   csr    = (int*)p;
    cudaGetSymbolAddress(&p, g_fdeg);    int*   fdeg   = (int*)p;
    cudaGetSymbolAddress(&p, g_fdis);    float* fdis   = (float*)p;
    cudaGetSymbolAddress(&p, g_frowptr); int*   frowptr= (int*)p;
    cudaGetSymbolAddress(&p, g_fcursor); int*   fcursor= (int*)p;
    cudaGetSymbolAddress(&p, g_fcsr);    int*   fcsr   = (int*)p;
    cudaGetSymbolAddress(&p, g_bsum);    int*   bsum   = (int*)p;
    cudaGetSymbolAddress(&p, g_fstart);  int*   fstart = (int*)p;
    cudaGetSymbolAddress(&p, g_bstart);  int*   bstart = (int*)p;
    cudaGetSymbolAddress(&p, g_pool);    float* pool   = (float*)p;
    cudaGetSymbolAddress(&p, g_fx);      float* fx     = (float*)p;
    cudaGetSymbolAddress(&p, g_fz);      float* fz     = (float*)p;
    cudaGetSymbolAddress(&p, g_fy);      float* fy     = (float*)p;
    cudaGetSymbolAddress(&p, g_g);       float* gg     = (float*)p;

    // degrees + norms
    zerodeg_kernel<<<(N_CFG + 255) / 256, 256>>>();
    degi_kernel<<<(E_CFG + 255) / 256, 256>>>(cfg_ei, E_CFG, deg);
    degi_kernel<<<(E_FCG + 255) / 256, 256>>>(fcg_ei, E_FCG, fdeg);
    dis_kernel<<<(N_CFG + 255) / 256, 256>>>(deg, dis, N_CFG);
    dis_kernel<<<(N_FCG + 255) / 256, 256>>>(fdeg, fdis, N_FCG);

    // CSR build (CFG)
    const int NBLK_CFG = (N_CFG + 1023) / 1024;
    scan_local<<<NBLK_CFG, 256>>>(deg, N_CFG, rowptr, bsum);
    scan_bsum<<<1, 512>>>(bsum, NBLK_CFG);
    scan_add<<<(N_CFG + 255) / 256, 256>>>(rowptr, bsum, N_CFG, cursor);
    fill_csr<<<(E_CFG + 255) / 256, 256>>>(cfg_ei, E_CFG, cursor, csr);

    // CSR build (FCG)
    const int NBLK_FCG = (N_FCG + 1023) / 1024;
    scan_local<<<NBLK_FCG, 256>>>(fdeg, N_FCG, frowptr, bsum);
    scan_bsum<<<1, 512>>>(bsum, NBLK_FCG);
    scan_add<<<(N_FCG + 255) / 256, 256>>>(frowptr, bsum, N_FCG, fcursor);
    fill_csr<<<(E_FCG + 255) / 256, 256>>>(fcg_ei, E_FCG, fcursor, fcsr);

    // sorted-segment bounds
    seg_bounds<<<(N_FUNC + 256) / 256, 256>>>(n2f, N_CFG, N_FUNC, fstart);
    seg_bounds<<<1, 32>>>(fbatch, N_FCG, NB, bstart);

    // CFG layer 1: z1 = Ahat(cfg_x) [64ch] -> hs2 = relu(z1@W1+b1)*dis
    gather64_kernel<<<(N_CFG * 32 + 255) / 256, 256>>>(rowptr, deg, csr, cfg_x, dis, Bb, N_CFG);
    gemmx_kernel<64, true><<<N_CFG / 128, 256>>>(Bb, W1, b1, dis, A, N_CFG);

    // CFG layer 2: z2 = Ahat(hs2) (prescaled), then x2 = relu(z2@W2+b2)
    gather128pre_kernel<<<(N_CFG * 32 + 255) / 256, 256>>>(rowptr, deg, csr, A, dis, Bb, N_CFG);
    gemmx_kernel<128, false><<<N_CFG / 128, 256>>>(Bb, W2, b2, dis, A, N_CFG);

    // function-level mean pool
    poolseg_kernel<<<(N_FUNC * 32 + 255) / 256, 256>>>(A, fstart, pool, N_FUNC);

    // FCG features + FCG layer
    assemble_kernel<<<(N_FCG * D_H) / 256, 256>>>(pool, emb, fsrc, fext, fx);
    gather128_kernel<<<(N_FCG * 32 + 255) / 256, 256>>>(frowptr, fdeg, fcsr, fx, fdis, fz, N_FCG);
    gemmx_kernel<128, false><<<N_FCG / 128, 256>>>(fz, Wf, bf, fdis, fy, N_FCG);

    // binary-level mean pool + head
    gpool_kernel<<<NB, 128>>>(fy, bstart, gg);
    head_kernel<<<1, 256>>>(gg, Wp1, bp1, Wp2, bp2, Wp3, bp3, out);
}

// round 6
// speedup vs baseline: 1.2479x; 1.1168x over previous
#include <cuda_runtime.h>
#include <cuda_bf16.h>
#include <math.h>

#define N_CFG 400000
#define E_CFG 1600000
#define N_FUNC 8000
#define N_FCG 9600
#define E_FCG 80000
#define NB 8
#define D_H 128
#define VOCAB 10002

// ---------------- scratch (device globals) ----------------------------------
__device__ float g_a [(size_t)N_CFG * D_H];   // fp32 ping
__device__ float g_b [(size_t)N_CFG * D_H];   // fp32 pong
__device__ __nv_bfloat16 g_hb[(size_t)N_CFG * D_H];  // bf16 hs2 (layer-2 gather src)
__device__ int   g_deg[N_CFG];
__device__ float g_dis[N_CFG];
__device__ int   g_rowptr[N_CFG];
__device__ int   g_cursor[N_CFG];
__device__ int   g_csr[E_CFG];
__device__ int   g_fdeg[N_FCG];
__device__ float g_fdis[N_FCG];
__device__ int   g_frowptr[N_FCG];
__device__ int   g_fcursor[N_FCG];
__device__ int   g_fcsr[E_FCG];
__device__ int   g_bsum[512];
__device__ int   g_fstart[N_FUNC + 1];
__device__ int   g_bstart[NB + 1];
__device__ float g_pool[N_FUNC * D_H];
__device__ float g_fx [N_FCG * D_H];
__device__ float g_fz [N_FCG * D_H];
__device__ float g_fy [N_FCG * D_H];
__device__ float g_g  [NB * D_H];

// ---------------- degree / norm (merged) --------------------------------------
__global__ void zerodeg_kernel() {
    int i = blockIdx.x * blockDim.x + threadIdx.x;
    if (i < N_CFG) g_deg[i] = 0;
    if (i < N_FCG) g_fdeg[i] = 0;
}
__global__ void deg_all_kernel(const int* __restrict__ cei, const int* __restrict__ fei) {
    int i = blockIdx.x * blockDim.x + threadIdx.x;
    if (i < E_CFG) {
        atomicAdd(&g_deg[cei[E_CFG + i]], 1);
    } else if (i < E_CFG + E_FCG) {
        atomicAdd(&g_fdeg[fei[E_FCG + (i - E_CFG)]], 1);
    }
}
__global__ void dis_all_kernel() {
    int i = blockIdx.x * blockDim.x + threadIdx.x;
    if (i < N_CFG) g_dis[i] = rsqrtf((float)g_deg[i] + 1.0f);
    else if (i < N_CFG + N_FCG) {
        int j = i - N_CFG;
        g_fdis[j] = rsqrtf((float)g_fdeg[j] + 1.0f);
    }
}

// ---------------- CSR build: scan + fill ------------------------------------
__global__ void scan_local(const int* __restrict__ cnt, int n, int* __restrict__ out,
                           int* __restrict__ bsum) {
    __shared__ int s[256];
    int base = blockIdx.x * 1024;
    int t = threadIdx.x;
    int v[4], sum = 0;
#pragma unroll
    for (int j = 0; j < 4; j++) {
        int i = base + t * 4 + j;
        v[j] = (i < n) ? cnt[i] : 0;
        sum += v[j];
    }
    s[t] = sum;
    __syncthreads();
    for (int off = 1; off < 256; off <<= 1) {
        int x = (t >= off) ? s[t - off] : 0;
        __syncthreads();
        s[t] += x;
        __syncthreads();
    }
    if (t == 255) bsum[blockIdx.x] = s[255];
    int run = (t > 0) ? s[t - 1] : 0;
#pragma unroll
    for (int j = 0; j < 4; j++) {
        int i = base + t * 4 + j;
        if (i < n) out[i] = run;
        run += v[j];
    }
}
__global__ void scan_bsum(int* __restrict__ bsum, int nb) {
    __shared__ int s[512];
    int t = threadIdx.x;
    s[t] = (t < nb) ? bsum[t] : 0;
    __syncthreads();
    for (int off = 1; off < 512; off <<= 1) {
        int x = (t >= off) ? s[t - off] : 0;
        __syncthreads();
        s[t] += x;
        __syncthreads();
    }
    if (t < nb) bsum[t] = (t > 0) ? s[t - 1] : 0;
}
__global__ void scan_add(int* __restrict__ out, const int* __restrict__ bsum, int n,
                         int* __restrict__ cursor) {
    int i = blockIdx.x * blockDim.x + threadIdx.x;
    if (i < n) {
        int v = out[i] + bsum[i >> 10];
        out[i] = v;
        cursor[i] = v;
    }
}
__global__ void fill_csr(const int* __restrict__ ei, int E, int* __restrict__ cursor,
                         int* __restrict__ csr) {
    int i = blockIdx.x * blockDim.x + threadIdx.x;
    if (i < E) {
        int r = ei[i], c = ei[E + i];
        int slot = atomicAdd(&cursor[c], 1);
        csr[slot] = r;
    }
}

// merged segment bounds: fstart (N_FUNC+1 via n2f) + bstart (NB+1 via fbatch)
__global__ void bounds_all_kernel(const int* __restrict__ n2f, const int* __restrict__ fbatch) {
    int i = blockIdx.x * blockDim.x + threadIdx.x;
    if (i <= N_FUNC) {
        int lo = 0, hi = N_CFG;
        while (lo < hi) {
            int mid = (lo + hi) >> 1;
            if (n2f[mid] < i) lo = mid + 1; else hi = mid;
        }
        g_fstart[i] = lo;
    } else {
        int f = i - (N_FUNC + 1);
        if (f <= NB) {
            int lo = 0, hi = N_FCG;
            while (lo < hi) {
                int mid = (lo + hi) >> 1;
                if (fbatch[mid] < f) lo = mid + 1; else hi = mid;
            }
            g_bstart[f] = lo;
        }
    }
}

// ---------------- GEMM: H = relu(X @ W + b) [* dis[row]] --------------------
// 128x128 block tile, 8x8 thread tile, fma.rn.f32x2 packed math. (R2 config)
// OUTBF16: write output as bf16 instead of fp32.
template<int K, bool SCALE, bool OUTBF16>
__global__ __launch_bounds__(256, 2) void gemmx_kernel(
    const float* __restrict__ X, const float* __restrict__ W,
    const float* __restrict__ bias, const float* __restrict__ dis,
    float* __restrict__ H, __nv_bfloat16* __restrict__ HB, int N) {
    __shared__ float Xs[32 * 132];   // transposed: Xs[k][r], pitch 132
    __shared__ float Ws[32 * 128];   // Ws[k][c]
    const int row0 = blockIdx.x * 128;
    const int tx = threadIdx.x & 15;
    const int ty = threadIdx.x >> 4;
    const int c0 = tx * 8, r0 = ty * 8;

    unsigned long long acc2[8][4];
#pragma unroll
    for (int r = 0; r < 8; r++)
#pragma unroll
        for (int j = 0; j < 4; j++) acc2[r][j] = 0ULL;

    for (int kc = 0; kc < K; kc += 32) {
#pragma unroll
        for (int i = threadIdx.x; i < 128 * 32; i += 256) {
            int k = i & 31, r = i >> 5;
            Xs[k * 132 + r] = X[(size_t)(row0 + r) * K + kc + k];
        }
#pragma unroll
        for (int i = threadIdx.x; i < 32 * 128; i += 256) {
            int c = i & 127, k = i >> 7;
            Ws[k * 128 + c] = W[(size_t)(kc + k) * 128 + c];
        }
        __syncthreads();
#pragma unroll 4
        for (int k = 0; k < 32; k++) {
            float4 al = *(const float4*)&Xs[k * 132 + r0];
            float4 ah = *(const float4*)&Xs[k * 132 + r0 + 4];
            ulonglong2 wl = *(const ulonglong2*)&Ws[k * 128 + c0];
            ulonglong2 wh = *(const ulonglong2*)&Ws[k * 128 + c0 + 4];
            unsigned long long w2[4];
            w2[0] = wl.x; w2[1] = wl.y; w2[2] = wh.x; w2[3] = wh.y;
            float a[8];
            a[0] = al.x; a[1] = al.y; a[2] = al.z; a[3] = al.w;
            a[4] = ah.x; a[5] = ah.y; a[6] = ah.z; a[7] = ah.w;
#pragma unroll
            for (int r = 0; r < 8; r++) {
                unsigned long long a2;
                asm("mov.b64 %0, {%1, %1};" : "=l"(a2) : "f"(a[r]));
#pragma unroll
                for (int j = 0; j < 4; j++)
                    asm("fma.rn.f32x2 %0, %1, %2, %0;"
                        : "+l"(acc2[r][j]) : "l"(a2), "l"(w2[j]));
            }
        }
        __syncthreads();
    }

    float bb[8];
#pragma unroll
    for (int j = 0; j < 8; j++) bb[j] = bias[c0 + j];
#pragma unroll
    for (int r = 0; r < 8; r++) {
        int gr = row0 + r0 + r;
        if (gr >= N) return;
        float s = SCALE ? dis[gr] : 1.0f;
        float o[8];
#pragma unroll
        for (int j = 0; j < 4; j++) {
            float lo, hi;
            asm("mov.b64 {%0, %1}, %2;" : "=f"(lo), "=f"(hi) : "l"(acc2[r][j]));
            o[2 * j]     = fmaxf(lo + bb[2 * j], 0.f) * s;
            o[2 * j + 1] = fmaxf(hi + bb[2 * j + 1], 0.f) * s;
        }
        if (OUTBF16) {
            __nv_bfloat162 q0 = __float22bfloat162_rn(make_float2(o[0], o[1]));
            __nv_bfloat162 q1 = __float22bfloat162_rn(make_float2(o[2], o[3]));
            __nv_bfloat162 q2 = __float22bfloat162_rn(make_float2(o[4], o[5]));
            __nv_bfloat162 q3 = __float22bfloat162_rn(make_float2(o[6], o[7]));
            uint4 pk;
            pk.x = *(unsigned*)&q0; pk.y = *(unsigned*)&q1;
            pk.z = *(unsigned*)&q2; pk.w = *(unsigned*)&q3;
            *(uint4*)&HB[(size_t)gr * 128 + c0] = pk;
        } else {
            *(float4*)&H[(size_t)gr * 128 + c0]     = make_float4(o[0], o[1], o[2], o[3]);
            *(float4*)&H[(size_t)gr * 128 + c0 + 4] = make_float4(o[4], o[5], o[6], o[7]);
        }
    }
}

// ---------------- gather 64ch, dis folded on the fly (layer 1) ---------------
// out[v] = (x[v]*dis[v] + sum_u x[u]*dis[u]) * dis[v]
__global__ __launch_bounds__(256) void gather64_kernel(
    const int* __restrict__ rowptr, const int* __restrict__ deg,
    const int* __restrict__ csr, const float* __restrict__ x,
    const float* __restrict__ dis, float* __restrict__ out, int n) {
    int node = (blockIdx.x * 256 + threadIdx.x) >> 5;
    int lane = threadIdx.x & 31;
    if (node >= n) return;
    const float2* x2 = (const float2*)x;
    float dn = dis[node];
    float2 v = x2[(size_t)node * 32 + lane];
    float2 acc; acc.x = v.x * dn; acc.y = v.y * dn;
    int start = rowptr[node], d = deg[node];
    for (int e = 0; e < d; e++) {
        int u = csr[start + e];
        float du = dis[u];
        float2 w = x2[(size_t)u * 32 + lane];
        acc.x += w.x * du; acc.y += w.y * du;
    }
    acc.x *= dn; acc.y *= dn;
    ((float2*)out)[(size_t)node * 32 + lane] = acc;
}

// ---------------- gather 128ch bf16 src, prescaled (layer 2) ------------------
// out[v] = (h[v] + sum_u h[u]) * dis[v]   (h bf16, already has dis[row] folded)
__global__ __launch_bounds__(256) void gather128bf_kernel(
    const int* __restrict__ rowptr, const int* __restrict__ deg,
    const int* __restrict__ csr, const __nv_bfloat16* __restrict__ hb,
    const float* __restrict__ dis, float* __restrict__ out, int n) {
    int node = (blockIdx.x * 256 + threadIdx.x) >> 5;
    int lane = threadIdx.x & 31;
    if (node >= n) return;
    const uint2* h8 = (const uint2*)hb;   // 4 bf16 per uint2; 32 uint2 per row
    float a0, a1, a2, a3;
    {
        uint2 raw = h8[(size_t)node * 32 + lane];
        float2 f0 = __bfloat1622float2(*reinterpret_cast<const __nv_bfloat162*>(&raw.x));
        float2 f1 = __bfloat1622float2(*reinterpret_cast<const __nv_bfloat162*>(&raw.y));
        a0 = f0.x; a1 = f0.y; a2 = f1.x; a3 = f1.y;
    }
    int start = rowptr[node], d = deg[node];
    for (int e = 0; e < d; e++) {
        int u = csr[start + e];
        uint2 raw = h8[(size_t)u * 32 + lane];
        float2 f0 = __bfloat1622float2(*reinterpret_cast<const __nv_bfloat162*>(&raw.x));
        float2 f1 = __bfloat1622float2(*reinterpret_cast<const __nv_bfloat162*>(&raw.y));
        a0 += f0.x; a1 += f0.y; a2 += f1.x; a3 += f1.y;
    }
    float dn = dis[node];
    ((float4*)out)[(size_t)node * 32 + lane] =
        make_float4(a0 * dn, a1 * dn, a2 * dn, a3 * dn);
}

// ---------------- gather 128ch fp32 (FCG, dis folded on the fly) --------------
__global__ __launch_bounds__(256) void gather128_kernel(
    const int* __restrict__ rowptr, const int* __restrict__ deg,
    const int* __restrict__ csr, const float* __restrict__ hs,
    const float* __restrict__ dis, float* __restrict__ out, int n) {
    int node = (blockIdx.x * 256 + threadIdx.x) >> 5;
    int lane = threadIdx.x & 31;
    if (node >= n) return;
    const float4* hs4 = (const float4*)hs;
    float dn = dis[node];
    float4 acc = hs4[(size_t)node * 32 + lane];
    acc.x *= dn; acc.y *= dn; acc.z *= dn; acc.w *= dn;
    int start = rowptr[node], d = deg[node];
    for (int e = 0; e < d; e++) {
        int u = csr[start + e];
        float4 v = hs4[(size_t)u * 32 + lane];
        float du = dis[u];
        acc.x += v.x * du; acc.y += v.y * du;
        acc.z += v.z * du; acc.w += v.w * du;
    }
    acc.x *= dn; acc.y *= dn; acc.z *= dn; acc.w *= dn;
    ((float4*)out)[(size_t)node * 32 + lane] = acc;
}

// ---------------- function-level mean pool -----------------------------------
__global__ __launch_bounds__(256) void poolseg_kernel(
    const float* __restrict__ x, const int* __restrict__ start,
    float* __restrict__ pool, int nseg) {
    int f = (blockIdx.x * 256 + threadIdx.x) >> 5;
    int lane = threadIdx.x & 31;
    if (f >= nseg) return;
    int s = start[f], e = start[f + 1];
    const float4* x4 = (const float4*)x;
    float4 acc = make_float4(0.f, 0.f, 0.f, 0.f);
    for (int i = s; i < e; i++) {
        float4 v = x4[(size_t)i * 32 + lane];
        acc.x += v.x; acc.y += v.y; acc.z += v.z; acc.w += v.w;
    }
    float inv = 1.0f / (float)max(e - s, 1);
    acc.x *= inv; acc.y *= inv; acc.z *= inv; acc.w *= inv;
    ((float4*)pool)[(size_t)f * 32 + lane] = acc;
}

__global__ void assemble_kernel(const float* __restrict__ pool, const float* __restrict__ emb,
                                const int* __restrict__ src, const int* __restrict__ isext,
                                float* __restrict__ fx) {
    int i = blockIdx.x * blockDim.x + threadIdx.x;
    if (i >= N_FCG * D_H) return;
    int row = i >> 7, j = i & 127;
    int s = src[row];
    float v;
    if (isext[row] == 1) {
        int k = min(max(s, 0), VOCAB - 1);
        v = emb[(size_t)k * D_H + j];
    } else {
        int k = min(max(s, 0), N_FUNC - 1);
        v = pool[(size_t)k * D_H + j];
    }
    fx[i] = v;
}

__global__ __launch_bounds__(128) void gpool_kernel(
    const float* __restrict__ y, const int* __restrict__ start, float* __restrict__ g) {
    int b = blockIdx.x, col = threadIdx.x;
    int s = start[b], e = start[b + 1];
    float acc = 0.f;
    for (int i = s; i < e; i++) acc += y[(size_t)i * 128 + col];
    g[b * 128 + col] = acc / (float)max(e - s, 1);
}

__global__ __launch_bounds__(256) void head_kernel(
    const float* __restrict__ g,
    const float* __restrict__ Wp1, const float* __restrict__ bp1,
    const float* __restrict__ Wp2, const float* __restrict__ bp2,
    const float* __restrict__ Wp3, const float* __restrict__ bp3,
    float* __restrict__ out) {
    __shared__ float G[NB * 128], H1[NB * 64], H2[NB * 32];
    int t = threadIdx.x;
    for (int i = t; i < NB * 128; i += 256) G[i] = g[i];
    __syncthreads();
    for (int i = t; i < NB * 64; i += 256) {
        int r = i >> 6, c = i & 63;
        float a = bp1[c];
        for (int k = 0; k < 128; k++) a += G[r * 128 + k] * Wp1[k * 64 + c];
        H1[i] = fmaxf(a, 0.f);
    }
    __syncthreads();
    for (int i = t; i < NB * 32; i += 256) {
        int r = i >> 5, c = i & 31;
        float a = bp2[c];
        for (int k = 0; k < 64; k++) a += H1[r * 64 + k] * Wp2[k * 32 + c];
        H2[i] = fmaxf(a, 0.f);
    }
    __syncthreads();
    if (t < NB) {
        float a = bp3[0];
        for (int k = 0; k < 32; k++) a += H2[t * 32 + k] * Wp3[k];
        out[t] = 1.0f / (1.0f + expf(-a));
    }
}

// ---------------- launch ----------------------------------------------------
extern "C" void kernel_launch(void* const* d_in, const int* in_sizes, int n_in,
                              void* d_out, int out_size) {
    const float* cfg_x  = (const float*)d_in[0];
    const int*   cfg_ei = (const int*)  d_in[1];
    const int*   n2f    = (const int*)  d_in[2];
    const int*   fcg_ei = (const int*)  d_in[3];
    const int*   fbatch = (const int*)  d_in[4];
    const int*   fsrc   = (const int*)  d_in[5];
    const int*   fext   = (const int*)  d_in[6];
    const float* W1  = (const float*)d_in[7];
    const float* b1  = (const float*)d_in[8];
    const float* W2  = (const float*)d_in[9];
    const float* b2  = (const float*)d_in[10];
    const float* emb = (const float*)d_in[11];
    const float* Wf  = (const float*)d_in[12];
    const float* bf  = (const float*)d_in[13];
    const float* Wp1 = (const float*)d_in[14];
    const float* bp1 = (const float*)d_in[15];
    const float* Wp2 = (const float*)d_in[16];
    const float* bp2 = (const float*)d_in[17];
    const float* Wp3 = (const float*)d_in[18];
    const float* bp3 = (const float*)d_in[19];
    float* out = (float*)d_out;

    void *p;
    cudaGetSymbolAddress(&p, g_a);       float* A      = (float*)p;
    cudaGetSymbolAddress(&p, g_b);       float* Bb     = (float*)p;
    cudaGetSymbolAddress(&p, g_hb);      __nv_bfloat16* HB = (__nv_bfloat16*)p;
    cudaGetSymbolAddress(&p, g_deg);     int*   deg    = (int*)p;
    cudaGetSymbolAddress(&p, g_dis);     float* dis    = (float*)p;
    cudaGetSymbolAddress(&p, g_rowptr);  int*   rowptr = (int*)p;
    cudaGetSymbolAddress(&p, g_cursor);  int*   cursor = (int*)p;
    cudaGetSymbolAddress(&p, g_csr);     int*   csr    = (int*)p;
    cudaGetSymbolAddress(&p, g_fdeg);    int*   fdeg   = (int*)p;
    cudaGetSymbolAddress(&p, g_fdis);    float* fdis   = (float*)p;
    cudaGetSymbolAddress(&p, g_frowptr); int*   frowptr= (int*)p;
    cudaGetSymbolAddress(&p, g_fcursor); int*   fcursor= (int*)p;
    cudaGetSymbolAddress(&p, g_fcsr);    int*   fcsr   = (int*)p;
    cudaGetSymbolAddress(&p, g_bsum);    int*   bsum   = (int*)p;
    cudaGetSymbolAddress(&p, g_fstart);  int*   fstart = (int*)p;
    cudaGetSymbolAddress(&p, g_bstart);  int*   bstart = (int*)p;
    cudaGetSymbolAddress(&p, g_pool);    float* pool   = (float*)p;
    cudaGetSymbolAddress(&p, g_fx);      float* fx     = (float*)p;
    cudaGetSymbolAddress(&p, g_fz);      float* fz     = (float*)p;
    cudaGetSymbolAddress(&p, g_fy);      float* fy     = (float*)p;
    cudaGetSymbolAddress(&p, g_g);       float* gg     = (float*)p;

    // degrees + norms (merged)
    zerodeg_kernel<<<(N_CFG + 255) / 256, 256>>>();
    deg_all_kernel<<<(E_CFG + E_FCG + 255) / 256, 256>>>(cfg_ei, fcg_ei);
    dis_all_kernel<<<(N_CFG + N_FCG + 255) / 256, 256>>>();

    // CSR build (CFG)
    const int NBLK_CFG = (N_CFG + 1023) / 1024;
    scan_local<<<NBLK_CFG, 256>>>(deg, N_CFG, rowptr, bsum);
    scan_bsum<<<1, 512>>>(bsum, NBLK_CFG);
    scan_add<<<(N_CFG + 255) / 256, 256>>>(rowptr, bsum, N_CFG, cursor);
    fill_csr<<<(E_CFG + 255) / 256, 256>>>(cfg_ei, E_CFG, cursor, csr);

    // CSR build (FCG)
    const int NBLK_FCG = (N_FCG + 1023) / 1024;
    scan_local<<<NBLK_FCG, 256>>>(fdeg, N_FCG, frowptr, bsum);
    scan_bsum<<<1, 512>>>(bsum, NBLK_FCG);
    scan_add<<<(N_FCG + 255) / 256, 256>>>(frowptr, bsum, N_FCG, fcursor);
    fill_csr<<<(E_FCG + 255) / 256, 256>>>(fcg_ei, E_FCG, fcursor, fcsr);

    // segment bounds (merged)
    bounds_all_kernel<<<(N_FUNC + NB + 2 + 255) / 256, 256>>>(n2f, fbatch);

    // CFG layer 1: z1 = Ahat(cfg_x) [64ch] -> hs2 = relu(z1@W1+b1)*dis  (bf16)
    gather64_kernel<<<(N_CFG * 32 + 255) / 256, 256>>>(rowptr, deg, csr, cfg_x, dis, Bb, N_CFG);
    gemmx_kernel<64, true, true><<<N_CFG / 128, 256>>>(Bb, W1, b1, dis, nullptr, HB, N_CFG);

    // CFG layer 2: z2 = Ahat(hs2) (bf16 src, L2-resident), x2 = relu(z2@W2+b2)
    gather128bf_kernel<<<(N_CFG * 32 + 255) / 256, 256>>>(rowptr, deg, csr, HB, dis, Bb, N_CFG);
    gemmx_kernel<128, false, false><<<N_CFG / 128, 256>>>(Bb, W2, b2, dis, A, nullptr, N_CFG);

    // function-level mean pool
    poolseg_kernel<<<(N_FUNC * 32 + 255) / 256, 256>>>(A, fstart, pool, N_FUNC);

    // FCG features + FCG layer
    assemble_kernel<<<(N_FCG * D_H) / 256, 256>>>(pool, emb, fsrc, fext, fx);
    gather128_kernel<<<(N_FCG * 32 + 255) / 256, 256>>>(frowptr, fdeg, fcsr, fx, fdis, fz, N_FCG);
    gemmx_kernel<128, false, false><<<N_FCG / 128, 256>>>(fz, Wf, bf, fdis, fy, nullptr, N_FCG);

    // binary-level mean pool + head
    gpool_kernel<<<NB, 128>>>(fy, bstart, gg);
    head_kernel<<<1, 256>>>(gg, Wp1, bp1, Wp2, bp2, Wp3, bp3, out);
}

// round 7
// speedup vs baseline: 1.2642x; 1.0131x over previous
#include <cuda_runtime.h>
#include <cuda_bf16.h>
#include <math.h>

#define N_CFG 400000
#define E_CFG 1600000
#define N_FUNC 8000
#define N_FCG 9600
#define E_FCG 80000
#define NB 8
#define D_H 128
#define VOCAB 10002

// ---------------- scratch (device globals) ----------------------------------
__device__ float g_a [(size_t)N_CFG * D_H];   // fp32 (x2 output)
__device__ float g_b [(size_t)N_CFG * D_H];   // aliased bf16 scratch (see launch)
__device__ __nv_bfloat16 g_hb[(size_t)N_CFG * D_H];  // bf16 hs2 (layer-2 gather src)
__device__ int   g_deg[N_CFG];
__device__ float g_dis[N_CFG];
__device__ int   g_rowptr[N_CFG];
__device__ int   g_cursor[N_CFG];
__device__ int   g_csr[E_CFG];
__device__ int   g_fdeg[N_FCG];
__device__ float g_fdis[N_FCG];
__device__ int   g_frowptr[N_FCG];
__device__ int   g_fcursor[N_FCG];
__device__ int   g_fcsr[E_FCG];
__device__ int   g_bsum[512];
__device__ int   g_fstart[N_FUNC + 1];
__device__ int   g_bstart[NB + 1];
__device__ float g_pool[N_FUNC * D_H];
__device__ float g_fx [N_FCG * D_H];
__device__ float g_fz [N_FCG * D_H];
__device__ float g_fy [N_FCG * D_H];
__device__ float g_g  [NB * D_H];

static __device__ __forceinline__ unsigned pack_bf2(float a, float b) {
    __nv_bfloat162 h = __float22bfloat162_rn(make_float2(a, b));
    return *reinterpret_cast<unsigned*>(&h);
}
static __device__ __forceinline__ float2 unpack_bf2(unsigned u) {
    return __bfloat1622float2(*reinterpret_cast<const __nv_bfloat162*>(&u));
}

// ---------------- degree / norm (merged) --------------------------------------
__global__ void zerodeg_kernel() {
    int i = blockIdx.x * blockDim.x + threadIdx.x;
    if (i < N_CFG) g_deg[i] = 0;
    if (i < N_FCG) g_fdeg[i] = 0;
}
__global__ void deg_all_kernel(const int* __restrict__ cei, const int* __restrict__ fei) {
    int i = blockIdx.x * blockDim.x + threadIdx.x;
    if (i < E_CFG) {
        atomicAdd(&g_deg[cei[E_CFG + i]], 1);
    } else if (i < E_CFG + E_FCG) {
        atomicAdd(&g_fdeg[fei[E_FCG + (i - E_CFG)]], 1);
    }
}
__global__ void dis_all_kernel() {
    int i = blockIdx.x * blockDim.x + threadIdx.x;
    if (i < N_CFG) g_dis[i] = rsqrtf((float)g_deg[i] + 1.0f);
    else if (i < N_CFG + N_FCG) {
        int j = i - N_CFG;
        g_fdis[j] = rsqrtf((float)g_fdeg[j] + 1.0f);
    }
}

// ---------------- CSR build: scan + fill ------------------------------------
__global__ void scan_local(const int* __restrict__ cnt, int n, int* __restrict__ out,
                           int* __restrict__ bsum) {
    __shared__ int s[256];
    int base = blockIdx.x * 1024;
    int t = threadIdx.x;
    int v[4], sum = 0;
#pragma unroll
    for (int j = 0; j < 4; j++) {
        int i = base + t * 4 + j;
        v[j] = (i < n) ? cnt[i] : 0;
        sum += v[j];
    }
    s[t] = sum;
    __syncthreads();
    for (int off = 1; off < 256; off <<= 1) {
        int x = (t >= off) ? s[t - off] : 0;
        __syncthreads();
        s[t] += x;
        __syncthreads();
    }
    if (t == 255) bsum[blockIdx.x] = s[255];
    int run = (t > 0) ? s[t - 1] : 0;
#pragma unroll
    for (int j = 0; j < 4; j++) {
        int i = base + t * 4 + j;
        if (i < n) out[i] = run;
        run += v[j];
    }
}
__global__ void scan_bsum(int* __restrict__ bsum, int nb) {
    __shared__ int s[512];
    int t = threadIdx.x;
    s[t] = (t < nb) ? bsum[t] : 0;
    __syncthreads();
    for (int off = 1; off < 512; off <<= 1) {
        int x = (t >= off) ? s[t - off] : 0;
        __syncthreads();
        s[t] += x;
        __syncthreads();
    }
    if (t < nb) bsum[t] = (t > 0) ? s[t - 1] : 0;
}
__global__ void scan_add(int* __restrict__ out, const int* __restrict__ bsum, int n,
                         int* __restrict__ cursor) {
    int i = blockIdx.x * blockDim.x + threadIdx.x;
    if (i < n) {
        int v = out[i] + bsum[i >> 10];
        out[i] = v;
        cursor[i] = v;
    }
}
__global__ void fill_csr(const int* __restrict__ ei, int E, int* __restrict__ cursor,
                         int* __restrict__ csr) {
    int i = blockIdx.x * blockDim.x + threadIdx.x;
    if (i < E) {
        int r = ei[i], c = ei[E + i];
        int slot = atomicAdd(&cursor[c], 1);
        csr[slot] = r;
    }
}

__global__ void bounds_all_kernel(const int* __restrict__ n2f, const int* __restrict__ fbatch) {
    int i = blockIdx.x * blockDim.x + threadIdx.x;
    if (i <= N_FUNC) {
        int lo = 0, hi = N_CFG;
        while (lo < hi) {
            int mid = (lo + hi) >> 1;
            if (n2f[mid] < i) lo = mid + 1; else hi = mid;
        }
        g_fstart[i] = lo;
    } else {
        int f = i - (N_FUNC + 1);
        if (f <= NB) {
            int lo = 0, hi = N_FCG;
            while (lo < hi) {
                int mid = (lo + hi) >> 1;
                if (fbatch[mid] < f) lo = mid + 1; else hi = mid;
            }
            g_bstart[f] = lo;
        }
    }
}

// ---------------- cfg_x -> bf16 with dis prefolded ---------------------------
// xb[row, 2j:2j+2] = bf16(cfg_x[row, 2j:2j+2] * dis[row])
__global__ void tobf_kernel(const float2* __restrict__ x2, const float* __restrict__ dis,
                            unsigned* __restrict__ xb) {
    int i = blockIdx.x * blockDim.x + threadIdx.x;   // over N_CFG*32 float2s
    if (i >= N_CFG * 32) return;
    int row = i >> 5;
    float d = dis[row];
    float2 v = x2[i];
    xb[i] = pack_bf2(v.x * d, v.y * d);
}

// ---------------- GEMM: H = relu(X @ W + b) [* dis[row]] --------------------
// 128x128 block tile, 8x8 thread tile, fma.rn.f32x2 packed math. (R2 config)
// TX = float (fp32 X) or __nv_bfloat16 (bf16 X, converted during staging).
template<int K, bool SCALE, bool OUTBF16, typename TX>
__global__ __launch_bounds__(256, 2) void gemmx_kernel(
    const TX* __restrict__ X, const float* __restrict__ W,
    const float* __restrict__ bias, const float* __restrict__ dis,
    float* __restrict__ H, __nv_bfloat16* __restrict__ HB, int N) {
    __shared__ float Xs[32 * 132];   // transposed: Xs[k][r], pitch 132
    __shared__ float Ws[32 * 128];   // Ws[k][c]
    const int row0 = blockIdx.x * 128;
    const int tx = threadIdx.x & 15;
    const int ty = threadIdx.x >> 4;
    const int c0 = tx * 8, r0 = ty * 8;

    unsigned long long acc2[8][4];
#pragma unroll
    for (int r = 0; r < 8; r++)
#pragma unroll
        for (int j = 0; j < 4; j++) acc2[r][j] = 0ULL;

    for (int kc = 0; kc < K; kc += 32) {
        if (sizeof(TX) == 2) {
            const unsigned* Xu = (const unsigned*)X;
#pragma unroll
            for (int i = threadIdx.x; i < 128 * 16; i += 256) {
                int k2 = i & 15, r = i >> 4;
                unsigned raw = Xu[(size_t)(row0 + r) * (K / 2) + (kc >> 1) + k2];
                float2 f = unpack_bf2(raw);
                Xs[(k2 * 2) * 132 + r]     = f.x;
                Xs[(k2 * 2 + 1) * 132 + r] = f.y;
            }
        } else {
            const float* Xf = (const float*)X;
#pragma unroll
            for (int i = threadIdx.x; i < 128 * 32; i += 256) {
                int k = i & 31, r = i >> 5;
                Xs[k * 132 + r] = Xf[(size_t)(row0 + r) * K + kc + k];
            }
        }
#pragma unroll
        for (int i = threadIdx.x; i < 32 * 128; i += 256) {
            int c = i & 127, k = i >> 7;
            Ws[k * 128 + c] = W[(size_t)(kc + k) * 128 + c];
        }
        __syncthreads();
#pragma unroll 4
        for (int k = 0; k < 32; k++) {
            float4 al = *(const float4*)&Xs[k * 132 + r0];
            float4 ah = *(const float4*)&Xs[k * 132 + r0 + 4];
            ulonglong2 wl = *(const ulonglong2*)&Ws[k * 128 + c0];
            ulonglong2 wh = *(const ulonglong2*)&Ws[k * 128 + c0 + 4];
            unsigned long long w2[4];
            w2[0] = wl.x; w2[1] = wl.y; w2[2] = wh.x; w2[3] = wh.y;
            float a[8];
            a[0] = al.x; a[1] = al.y; a[2] = al.z; a[3] = al.w;
            a[4] = ah.x; a[5] = ah.y; a[6] = ah.z; a[7] = ah.w;
#pragma unroll
            for (int r = 0; r < 8; r++) {
                unsigned long long a2;
                asm("mov.b64 %0, {%1, %1};" : "=l"(a2) : "f"(a[r]));
#pragma unroll
                for (int j = 0; j < 4; j++)
                    asm("fma.rn.f32x2 %0, %1, %2, %0;"
                        : "+l"(acc2[r][j]) : "l"(a2), "l"(w2[j]));
            }
        }
        __syncthreads();
    }

    float bb[8];
#pragma unroll
    for (int j = 0; j < 8; j++) bb[j] = bias[c0 + j];
#pragma unroll
    for (int r = 0; r < 8; r++) {
        int gr = row0 + r0 + r;
        if (gr >= N) return;
        float s = SCALE ? dis[gr] : 1.0f;
        float o[8];
#pragma unroll
        for (int j = 0; j < 4; j++) {
            float lo, hi;
            asm("mov.b64 {%0, %1}, %2;" : "=f"(lo), "=f"(hi) : "l"(acc2[r][j]));
            o[2 * j]     = fmaxf(lo + bb[2 * j], 0.f) * s;
            o[2 * j + 1] = fmaxf(hi + bb[2 * j + 1], 0.f) * s;
        }
        if (OUTBF16) {
            uint4 pk;
            pk.x = pack_bf2(o[0], o[1]); pk.y = pack_bf2(o[2], o[3]);
            pk.z = pack_bf2(o[4], o[5]); pk.w = pack_bf2(o[6], o[7]);
            *(uint4*)&HB[(size_t)gr * 128 + c0] = pk;
        } else {
            *(float4*)&H[(size_t)gr * 128 + c0]     = make_float4(o[0], o[1], o[2], o[3]);
            *(float4*)&H[(size_t)gr * 128 + c0 + 4] = make_float4(o[4], o[5], o[6], o[7]);
        }
    }
}

// ---------------- gather 64ch bf16 src (layer 1), prescaled ------------------
// z1[v] = (xb[v] + sum_u xb[u]) * dis[v]   (xb = x*dis, bf16) -> bf16 out
__global__ __launch_bounds__(256) void gather64bf_kernel(
    const int* __restrict__ rowptr, const int* __restrict__ deg,
    const int* __restrict__ csr, const unsigned* __restrict__ xb,
    const float* __restrict__ dis, unsigned* __restrict__ out, int n) {
    int node = (blockIdx.x * 256 + threadIdx.x) >> 5;
    int lane = threadIdx.x & 31;
    if (node >= n) return;
    float2 acc = unpack_bf2(xb[(size_t)node * 32 + lane]);
    int start = rowptr[node], d = deg[node];
    for (int e = 0; e < d; e++) {
        int u = csr[start + e];
        float2 w = unpack_bf2(xb[(size_t)u * 32 + lane]);
        acc.x += w.x; acc.y += w.y;
    }
    float dn = dis[node];
    out[(size_t)node * 32 + lane] = pack_bf2(acc.x * dn, acc.y * dn);
}

// ---------------- gather 128ch bf16 src, prescaled (layer 2) -> bf16 out -----
__global__ __launch_bounds__(256) void gather128bf_kernel(
    const int* __restrict__ rowptr, const int* __restrict__ deg,
    const int* __restrict__ csr, const __nv_bfloat16* __restrict__ hb,
    const float* __restrict__ dis, uint2* __restrict__ out, int n) {
    int node = (blockIdx.x * 256 + threadIdx.x) >> 5;
    int lane = threadIdx.x & 31;
    if (node >= n) return;
    const uint2* h8 = (const uint2*)hb;   // 4 bf16 per uint2; 32 uint2 per row
    float a0, a1, a2, a3;
    {
        uint2 raw = h8[(size_t)node * 32 + lane];
        float2 f0 = unpack_bf2(raw.x), f1 = unpack_bf2(raw.y);
        a0 = f0.x; a1 = f0.y; a2 = f1.x; a3 = f1.y;
    }
    int start = rowptr[node], d = deg[node];
    for (int e = 0; e < d; e++) {
        int u = csr[start + e];
        uint2 raw = h8[(size_t)u * 32 + lane];
        float2 f0 = unpack_bf2(raw.x), f1 = unpack_bf2(raw.y);
        a0 += f0.x; a1 += f0.y; a2 += f1.x; a3 += f1.y;
    }
    float dn = dis[node];
    uint2 pk;
    pk.x = pack_bf2(a0 * dn, a1 * dn);
    pk.y = pack_bf2(a2 * dn, a3 * dn);
    out[(size_t)node * 32 + lane] = pk;
}

// ---------------- gather 128ch fp32 (FCG, dis folded on the fly) --------------
__global__ __launch_bounds__(256) void gather128_kernel(
    const int* __restrict__ rowptr, const int* __restrict__ deg,
    const int* __restrict__ csr, const float* __restrict__ hs,
    const float* __restrict__ dis, float* __restrict__ out, int n) {
    int node = (blockIdx.x * 256 + threadIdx.x) >> 5;
    int lane = threadIdx.x & 31;
    if (node >= n) return;
    const float4* hs4 = (const float4*)hs;
    float dn = dis[node];
    float4 acc = hs4[(size_t)node * 32 + lane];
    acc.x *= dn; acc.y *= dn; acc.z *= dn; acc.w *= dn;
    int start = rowptr[node], d = deg[node];
    for (int e = 0; e < d; e++) {
        int u = csr[start + e];
        float4 v = hs4[(size_t)u * 32 + lane];
        float du = dis[u];
        acc.x += v.x * du; acc.y += v.y * du;
        acc.z += v.z * du; acc.w += v.w * du;
    }
    acc.x *= dn; acc.y *= dn; acc.z *= dn; acc.w *= dn;
    ((float4*)out)[(size_t)node * 32 + lane] = acc;
}

// ---------------- function-level mean pool -----------------------------------
__global__ __launch_bounds__(256) void poolseg_kernel(
    const float* __restrict__ x, const int* __restrict__ start,
    float* __restrict__ pool, int nseg) {
    int f = (blockIdx.x * 256 + threadIdx.x) >> 5;
    int lane = threadIdx.x & 31;
    if (f >= nseg) return;
    int s = start[f], e = start[f + 1];
    const float4* x4 = (const float4*)x;
    float4 acc = make_float4(0.f, 0.f, 0.f, 0.f);
    for (int i = s; i < e; i++) {
        float4 v = x4[(size_t)i * 32 + lane];
        acc.x += v.x; acc.y += v.y; acc.z += v.z; acc.w += v.w;
    }
    float inv = 1.0f / (float)max(e - s, 1);
    acc.x *= inv; acc.y *= inv; acc.z *= inv; acc.w *= inv;
    ((float4*)pool)[(size_t)f * 32 + lane] = acc;
}

__global__ void assemble_kernel(const float* __restrict__ pool, const float* __restrict__ emb,
                                const int* __restrict__ src, const int* __restrict__ isext,
                                float* __restrict__ fx) {
    int i = blockIdx.x * blockDim.x + threadIdx.x;
    if (i >= N_FCG * D_H) return;
    int row = i >> 7, j = i & 127;
    int s = src[row];
    float v;
    if (isext[row] == 1) {
        int k = min(max(s, 0), VOCAB - 1);
        v = emb[(size_t)k * D_H + j];
    } else {
        int k = min(max(s, 0), N_FUNC - 1);
        v = pool[(size_t)k * D_H + j];
    }
    fx[i] = v;
}

__global__ __launch_bounds__(128) void gpool_kernel(
    const float* __restrict__ y, const int* __restrict__ start, float* __restrict__ g) {
    int b = blockIdx.x, col = threadIdx.x;
    int s = start[b], e = start[b + 1];
    float acc = 0.f;
    for (int i = s; i < e; i++) acc += y[(size_t)i * 128 + col];
    g[b * 128 + col] = acc / (float)max(e - s, 1);
}

__global__ __launch_bounds__(256) void head_kernel(
    const float* __restrict__ g,
    const float* __restrict__ Wp1, const float* __restrict__ bp1,
    const float* __restrict__ Wp2, const float* __restrict__ bp2,
    const float* __restrict__ Wp3, const float* __restrict__ bp3,
    float* __restrict__ out) {
    __shared__ float G[NB * 128], H1[NB * 64], H2[NB * 32];
    int t = threadIdx.x;
    for (int i = t; i < NB * 128; i += 256) G[i] = g[i];
    __syncthreads();
    for (int i = t; i < NB * 64; i += 256) {
        int r = i >> 6, c = i & 63;
        float a = bp1[c];
        for (int k = 0; k < 128; k++) a += G[r * 128 + k] * Wp1[k * 64 + c];
        H1[i] = fmaxf(a, 0.f);
    }
    __syncthreads();
    for (int i = t; i < NB * 32; i += 256) {
        int r = i >> 5, c = i & 31;
        float a = bp2[c];
        for (int k = 0; k < 64; k++) a += H1[r * 64 + k] * Wp2[k * 32 + c];
        H2[i] = fmaxf(a, 0.f);
    }
    __syncthreads();
    if (t < NB) {
        float a = bp3[0];
        for (int k = 0; k < 32; k++) a += H2[t * 32 + k] * Wp3[k];
        out[t] = 1.0f / (1.0f + expf(-a));
    }
}

// ---------------- launch ----------------------------------------------------
extern "C" void kernel_launch(void* const* d_in, const int* in_sizes, int n_in,
                              void* d_out, int out_size) {
    const float* cfg_x  = (const float*)d_in[0];
    const int*   cfg_ei = (const int*)  d_in[1];
    const int*   n2f    = (const int*)  d_in[2];
    const int*   fcg_ei = (const int*)  d_in[3];
    const int*   fbatch = (const int*)  d_in[4];
    const int*   fsrc   = (const int*)  d_in[5];
    const int*   fext   = (const int*)  d_in[6];
    const float* W1  = (const float*)d_in[7];
    const float* b1  = (const float*)d_in[8];
    const float* W2  = (const float*)d_in[9];
    const float* b2  = (const float*)d_in[10];
    const float* emb = (const float*)d_in[11];
    const float* Wf  = (const float*)d_in[12];
    const float* bf  = (const float*)d_in[13];
    const float* Wp1 = (const float*)d_in[14];
    const float* bp1 = (const float*)d_in[15];
    const float* Wp2 = (const float*)d_in[16];
    const float* bp2 = (const float*)d_in[17];
    const float* Wp3 = (const float*)d_in[18];
    const float* bp3 = (const float*)d_in[19];
    float* out = (float*)d_out;

    void *p;
    cudaGetSymbolAddress(&p, g_a);       float* A      = (float*)p;
    cudaGetSymbolAddress(&p, g_b);       float* Bb     = (float*)p;
    cudaGetSymbolAddress(&p, g_hb);      __nv_bfloat16* HB = (__nv_bfloat16*)p;
    cudaGetSymbolAddress(&p, g_deg);     int*   deg    = (int*)p;
    cudaGetSymbolAddress(&p, g_dis);     float* dis    = (float*)p;
    cudaGetSymbolAddress(&p, g_rowptr);  int*   rowptr = (int*)p;
    cudaGetSymbolAddress(&p, g_cursor);  int*   cursor = (int*)p;
    cudaGetSymbolAddress(&p, g_csr);     int*   csr    = (int*)p;
    cudaGetSymbolAddress(&p, g_fdeg);    int*   fdeg   = (int*)p;
    cudaGetSymbolAddress(&p, g_fdis);    float* fdis   = (float*)p;
    cudaGetSymbolAddress(&p, g_frowptr); int*   frowptr= (int*)p;
    cudaGetSymbolAddress(&p, g_fcursor); int*   fcursor= (int*)p;
    cudaGetSymbolAddress(&p, g_fcsr);    int*   fcsr   = (int*)p;
    cudaGetSymbolAddress(&p, g_bsum);    int*   bsum   = (int*)p;
    cudaGetSymbolAddress(&p, g_fstart);  int*   fstart = (int*)p;
    cudaGetSymbolAddress(&p, g_bstart);  int*   bstart = (int*)p;
    cudaGetSymbolAddress(&p, g_pool);    float* pool   = (float*)p;
    cudaGetSymbolAddress(&p, g_fx);      float* fx     = (float*)p;
    cudaGetSymbolAddress(&p, g_fz);      float* fz     = (float*)p;
    cudaGetSymbolAddress(&p, g_fy);      float* fy     = (float*)p;
    cudaGetSymbolAddress(&p, g_g);       float* gg     = (float*)p;

    // bf16 scratch aliased into g_b (disjoint lifetimes):
    unsigned* xb  = (unsigned*)Bb;                       // cfg_x*dis, 64ch bf16
    unsigned* z1b = (unsigned*)Bb + (size_t)N_CFG * 32;  // gather1 out, 64ch bf16
    uint2*    z2b = (uint2*)Bb;                          // gather2 out, 128ch bf16 (after xb/z1b dead)

    // degrees + norms (merged)
    zerodeg_kernel<<<(N_CFG + 255) / 256, 256>>>();
    deg_all_kernel<<<(E_CFG + E_FCG + 255) / 256, 256>>>(cfg_ei, fcg_ei);
    dis_all_kernel<<<(N_CFG + N_FCG + 255) / 256, 256>>>();

    // CSR build (CFG)
    const int NBLK_CFG = (N_CFG + 1023) / 1024;
    scan_local<<<NBLK_CFG, 256>>>(deg, N_CFG, rowptr, bsum);
    scan_bsum<<<1, 512>>>(bsum, NBLK_CFG);
    scan_add<<<(N_CFG + 255) / 256, 256>>>(rowptr, bsum, N_CFG, cursor);
    fill_csr<<<(E_CFG + 255) / 256, 256>>>(cfg_ei, E_CFG, cursor, csr);

    // CSR build (FCG)
    const int NBLK_FCG = (N_FCG + 1023) / 1024;
    scan_local<<<NBLK_FCG, 256>>>(fdeg, N_FCG, frowptr, bsum);
    scan_bsum<<<1, 512>>>(bsum, NBLK_FCG);
    scan_add<<<(N_FCG + 255) / 256, 256>>>(frowptr, bsum, N_FCG, fcursor);
    fill_csr<<<(E_FCG + 255) / 256, 256>>>(fcg_ei, E_FCG, fcursor, fcsr);

    // segment bounds (merged)
    bounds_all_kernel<<<(N_FUNC + NB + 2 + 255) / 256, 256>>>(n2f, fbatch);

    // CFG layer 1 (all-bf16 edge path):
    tobf_kernel<<<(N_CFG * 32 + 255) / 256, 256>>>((const float2*)cfg_x, dis, xb);
    gather64bf_kernel<<<(N_CFG * 32 + 255) / 256, 256>>>(rowptr, deg, csr, xb, dis, z1b, N_CFG);
    gemmx_kernel<64, true, true, __nv_bfloat16><<<N_CFG / 128, 256>>>(
        (const __nv_bfloat16*)z1b, W1, b1, dis, nullptr, HB, N_CFG);

    // CFG layer 2: z2 = Ahat(hs2) (bf16 src+dst), x2 = relu(z2@W2+b2) fp32
    gather128bf_kernel<<<(N_CFG * 32 + 255) / 256, 256>>>(rowptr, deg, csr, HB, dis, z2b, N_CFG);
    gemmx_kernel<128, false, false, __nv_bfloat16><<<N_CFG / 128, 256>>>(
        (const __nv_bfloat16*)z2b, W2, b2, dis, A, nullptr, N_CFG);

    // function-level mean pool
    poolseg_kernel<<<(N_FUNC * 32 + 255) / 256, 256>>>(A, fstart, pool, N_FUNC);

    // FCG features + FCG layer (fp32)
    assemble_kernel<<<(N_FCG * D_H) / 256, 256>>>(pool, emb, fsrc, fext, fx);
    gather128_kernel<<<(N_FCG * 32 + 255) / 256, 256>>>(frowptr, fdeg, fcsr, fx, fdis, fz, N_FCG);
    gemmx_kernel<128, false, false, float><<<N_FCG / 128, 256>>>(
        fz, Wf, bf, fdis, fy, nullptr, N_FCG);

    // binary-level mean pool + head
    gpool_kernel<<<NB, 128>>>(fy, bstart, gg);
    head_kernel<<<1, 256>>>(gg, Wp1, bp1, Wp2, bp2, Wp3, bp3, out);
}

// round 8
// speedup vs baseline: 1.7552x; 1.3884x over previous
#include <cuda_runtime.h>
#include <cuda_bf16.h>
#include <mma.h>
#include <math.h>

using namespace nvcuda;

#define N_CFG 400000
#define E_CFG 1600000
#define N_FUNC 8000
#define N_FCG 9600
#define E_FCG 80000
#define NB 8
#define D_H 128
#define VOCAB 10002

// ---------------- scratch (device globals) ----------------------------------
__device__ float g_a [(size_t)N_CFG * D_H];   // fp32 (x2 output)
__device__ float g_b [(size_t)N_CFG * D_H];   // aliased bf16 scratch
__device__ __nv_bfloat16 g_hb[(size_t)N_CFG * D_H];  // bf16 hs2
__device__ __nv_bfloat16 g_wb1[64 * 128];
__device__ __nv_bfloat16 g_wb2[128 * 128];
__device__ int   g_deg[N_CFG];
__device__ float g_dis[N_CFG];
__device__ int   g_rowptr[N_CFG];
__device__ int   g_cursor[N_CFG];
__device__ int   g_csr[E_CFG];
__device__ int   g_fdeg[N_FCG];
__device__ float g_fdis[N_FCG];
__device__ int   g_frowptr[N_FCG];
__device__ int   g_fcursor[N_FCG];
__device__ int   g_fcsr[E_FCG];
__device__ int   g_bsum[512];
__device__ int   g_fstart[N_FUNC + 1];
__device__ int   g_bstart[NB + 1];
__device__ float g_pool[N_FUNC * D_H];
__device__ float g_fx [N_FCG * D_H];
__device__ float g_fz [N_FCG * D_H];
__device__ float g_fy [N_FCG * D_H];
__device__ float g_g  [NB * D_H];

static __device__ __forceinline__ unsigned pack_bf2(float a, float b) {
    __nv_bfloat162 h = __float22bfloat162_rn(make_float2(a, b));
    return *reinterpret_cast<unsigned*>(&h);
}
static __device__ __forceinline__ float2 unpack_bf2(unsigned u) {
    return __bfloat1622float2(*reinterpret_cast<const __nv_bfloat162*>(&u));
}

// ---------------- degree / norm (merged) --------------------------------------
__global__ void zerodeg_kernel() {
    int i = blockIdx.x * blockDim.x + threadIdx.x;
    if (i < N_CFG) g_deg[i] = 0;
    if (i < N_FCG) g_fdeg[i] = 0;
}
__global__ void deg_all_kernel(const int* __restrict__ cei, const int* __restrict__ fei) {
    int i = blockIdx.x * blockDim.x + threadIdx.x;
    if (i < E_CFG) {
        atomicAdd(&g_deg[cei[E_CFG + i]], 1);
    } else if (i < E_CFG + E_FCG) {
        atomicAdd(&g_fdeg[fei[E_FCG + (i - E_CFG)]], 1);
    }
}
__global__ void dis_all_kernel() {
    int i = blockIdx.x * blockDim.x + threadIdx.x;
    if (i < N_CFG) g_dis[i] = rsqrtf((float)g_deg[i] + 1.0f);
    else if (i < N_CFG + N_FCG) {
        int j = i - N_CFG;
        g_fdis[j] = rsqrtf((float)g_fdeg[j] + 1.0f);
    }
}

// W1,W2 -> bf16 (once)
__global__ void wtobf_kernel(const float* __restrict__ W1, const float* __restrict__ W2) {
    int i = blockIdx.x * blockDim.x + threadIdx.x;
    if (i < 64 * 128) g_wb1[i] = __float2bfloat16(W1[i]);
    else if (i < 64 * 128 + 128 * 128) g_wb2[i - 64 * 128] = __float2bfloat16(W2[i - 64 * 128]);
}

// ---------------- CSR build: scan + fill ------------------------------------
__global__ void scan_local(const int* __restrict__ cnt, int n, int* __restrict__ out,
                           int* __restrict__ bsum) {
    __shared__ int s[256];
    int base = blockIdx.x * 1024;
    int t = threadIdx.x;
    int v[4], sum = 0;
#pragma unroll
    for (int j = 0; j < 4; j++) {
        int i = base + t * 4 + j;
        v[j] = (i < n) ? cnt[i] : 0;
        sum += v[j];
    }
    s[t] = sum;
    __syncthreads();
    for (int off = 1; off < 256; off <<= 1) {
        int x = (t >= off) ? s[t - off] : 0;
        __syncthreads();
        s[t] += x;
        __syncthreads();
    }
    if (t == 255) bsum[blockIdx.x] = s[255];
    int run = (t > 0) ? s[t - 1] : 0;
#pragma unroll
    for (int j = 0; j < 4; j++) {
        int i = base + t * 4 + j;
        if (i < n) out[i] = run;
        run += v[j];
    }
}
__global__ void scan_bsum(int* __restrict__ bsum, int nb) {
    __shared__ int s[512];
    int t = threadIdx.x;
    s[t] = (t < nb) ? bsum[t] : 0;
    __syncthreads();
    for (int off = 1; off < 512; off <<= 1) {
        int x = (t >= off) ? s[t - off] : 0;
        __syncthreads();
        s[t] += x;
        __syncthreads();
    }
    if (t < nb) bsum[t] = (t > 0) ? s[t - 1] : 0;
}
__global__ void scan_add(int* __restrict__ out, const int* __restrict__ bsum, int n,
                         int* __restrict__ cursor) {
    int i = blockIdx.x * blockDim.x + threadIdx.x;
    if (i < n) {
        int v = out[i] + bsum[i >> 10];
        out[i] = v;
        cursor[i] = v;
    }
}
__global__ void fill_csr(const int* __restrict__ ei, int E, int* __restrict__ cursor,
                         int* __restrict__ csr) {
    int i = blockIdx.x * blockDim.x + threadIdx.x;
    if (i < E) {
        int r = ei[i], c = ei[E + i];
        int slot = atomicAdd(&cursor[c], 1);
        csr[slot] = r;
    }
}

__global__ void bounds_all_kernel(const int* __restrict__ n2f, const int* __restrict__ fbatch) {
    int i = blockIdx.x * blockDim.x + threadIdx.x;
    if (i <= N_FUNC) {
        int lo = 0, hi = N_CFG;
        while (lo < hi) {
            int mid = (lo + hi) >> 1;
            if (n2f[mid] < i) lo = mid + 1; else hi = mid;
        }
        g_fstart[i] = lo;
    } else {
        int f = i - (N_FUNC + 1);
        if (f <= NB) {
            int lo = 0, hi = N_FCG;
            while (lo < hi) {
                int mid = (lo + hi) >> 1;
                if (fbatch[mid] < f) lo = mid + 1; else hi = mid;
            }
            g_bstart[f] = lo;
        }
    }
}

// ---------------- cfg_x -> bf16 with dis prefolded ---------------------------
__global__ void tobf_kernel(const float2* __restrict__ x2, const float* __restrict__ dis,
                            unsigned* __restrict__ xb) {
    int i = blockIdx.x * blockDim.x + threadIdx.x;
    if (i >= N_CFG * 32) return;
    int row = i >> 5;
    float d = dis[row];
    float2 v = x2[i];
    xb[i] = pack_bf2(v.x * d, v.y * d);
}

// ---------------- WMMA bf16 GEMM: H = relu(X @ W + b) [* dis] ----------------
// block 128x128, 8 warps (2 row-groups x 4 col-groups), each warp 64x32.
template<int K, bool SCALE, bool OUTBF16>
__global__ __launch_bounds__(256, 2) void gemmw_kernel(
    const __nv_bfloat16* __restrict__ X, const __nv_bfloat16* __restrict__ Wb,
    const float* __restrict__ bias, const float* __restrict__ dis,
    float* __restrict__ H, __nv_bfloat16* __restrict__ HB, int N) {
    constexpr int AP = 40;    // A smem pitch (bf16 elems)
    constexpr int WP = 136;   // W smem pitch
    __shared__ __nv_bfloat16 As[128 * AP];   // 10240 B
    __shared__ __nv_bfloat16 Ws[32 * WP];    //  8704 B
    __shared__ float Eb[8][16 * 20];         // 10240 B epilogue buffers
    __shared__ float Bs[128];

    const int tid = threadIdx.x;
    const int warp = tid >> 5, lane = tid & 31;
    const int wr = warp >> 2;       // 0..1 -> 64-row group
    const int wc = warp & 3;        // 0..3 -> 32-col group
    const int row0 = blockIdx.x * 128;

    if (tid < 128) Bs[tid] = bias[tid];

    wmma::fragment<wmma::accumulator, 16, 16, 16, float> acc[4][2];
#pragma unroll
    for (int i = 0; i < 4; i++)
#pragma unroll
        for (int j = 0; j < 2; j++) wmma::fill_fragment(acc[i][j], 0.0f);

    const unsigned* Xu = (const unsigned*)X;
    const unsigned* Wu = (const unsigned*)Wb;
    unsigned* Asu = (unsigned*)As;
    unsigned* Wsu = (unsigned*)Ws;

    for (int kc = 0; kc < K; kc += 32) {
#pragma unroll
        for (int i = tid; i < 128 * 16; i += 256) {
            int r = i >> 4, k2 = i & 15;
            Asu[r * (AP / 2) + k2] = Xu[(size_t)(row0 + r) * (K / 2) + (kc >> 1) + k2];
        }
#pragma unroll
        for (int i = tid; i < 32 * 64; i += 256) {
            int k = i >> 6, c2 = i & 63;
            Wsu[k * (WP / 2) + c2] = Wu[(size_t)(kc + k) * 64 + c2];
        }
        __syncthreads();
#pragma unroll
        for (int ks = 0; ks < 32; ks += 16) {
            wmma::fragment<wmma::matrix_a, 16, 16, 16, __nv_bfloat16, wmma::row_major> af[4];
            wmma::fragment<wmma::matrix_b, 16, 16, 16, __nv_bfloat16, wmma::row_major> bf[2];
#pragma unroll
            for (int i = 0; i < 4; i++)
                wmma::load_matrix_sync(af[i], &As[(wr * 64 + i * 16) * AP + ks], AP);
#pragma unroll
            for (int j = 0; j < 2; j++)
                wmma::load_matrix_sync(bf[j], &Ws[ks * WP + wc * 32 + j * 16], WP);
#pragma unroll
            for (int i = 0; i < 4; i++)
#pragma unroll
                for (int j = 0; j < 2; j++)
                    wmma::mma_sync(acc[i][j], af[i], bf[j], acc[i][j]);
        }
        __syncthreads();
    }

    // epilogue: per 16x16 tile via per-warp smem buffer
    const int r = lane >> 1, c8 = (lane & 1) * 8;
#pragma unroll
    for (int i = 0; i < 4; i++) {
#pragma unroll
        for (int j = 0; j < 2; j++) {
            wmma::store_matrix_sync(&Eb[warp][0], acc[i][j], 20, wmma::mem_row_major);
            __syncwarp();
            int gr = row0 + wr * 64 + i * 16 + r;
            int gc = wc * 32 + j * 16 + c8;
            float s = SCALE ? dis[gr] : 1.0f;
            float o[8];
#pragma unroll
            for (int q = 0; q < 8; q++)
                o[q] = fmaxf(Eb[warp][r * 20 + c8 + q] + Bs[gc + q], 0.0f) * s;
            if (OUTBF16) {
                uint4 pk;
                pk.x = pack_bf2(o[0], o[1]); pk.y = pack_bf2(o[2], o[3]);
                pk.z = pack_bf2(o[4], o[5]); pk.w = pack_bf2(o[6], o[7]);
                *(uint4*)&HB[(size_t)gr * 128 + gc] = pk;
            } else {
                *(float4*)&H[(size_t)gr * 128 + gc]     = make_float4(o[0], o[1], o[2], o[3]);
                *(float4*)&H[(size_t)gr * 128 + gc + 4] = make_float4(o[4], o[5], o[6], o[7]);
            }
            __syncwarp();
        }
    }
}

// ---------------- FFMA2 GEMM (fp32, small FCG matmul) ------------------------
template<int K, bool SCALE>
__global__ __launch_bounds__(256, 2) void gemmx_kernel(
    const float* __restrict__ X, const float* __restrict__ W,
    const float* __restrict__ bias, const float* __restrict__ dis,
    float* __restrict__ H, int N) {
    __shared__ float Xs[32 * 132];
    __shared__ float Ws[32 * 128];
    const int row0 = blockIdx.x * 128;
    const int tx = threadIdx.x & 15;
    const int ty = threadIdx.x >> 4;
    const int c0 = tx * 8, r0 = ty * 8;

    unsigned long long acc2[8][4];
#pragma unroll
    for (int r = 0; r < 8; r++)
#pragma unroll
        for (int j = 0; j < 4; j++) acc2[r][j] = 0ULL;

    for (int kc = 0; kc < K; kc += 32) {
#pragma unroll
        for (int i = threadIdx.x; i < 128 * 32; i += 256) {
            int k = i & 31, r = i >> 5;
            int gr = row0 + r;
            Xs[k * 132 + r] = (gr < N) ? X[(size_t)gr * K + kc + k] : 0.f;
        }
#pragma unroll
        for (int i = threadIdx.x; i < 32 * 128; i += 256) {
            int c = i & 127, k = i >> 7;
            Ws[k * 128 + c] = W[(size_t)(kc + k) * 128 + c];
        }
        __syncthreads();
#pragma unroll 4
        for (int k = 0; k < 32; k++) {
            float4 al = *(const float4*)&Xs[k * 132 + r0];
            float4 ah = *(const float4*)&Xs[k * 132 + r0 + 4];
            ulonglong2 wl = *(const ulonglong2*)&Ws[k * 128 + c0];
            ulonglong2 wh = *(const ulonglong2*)&Ws[k * 128 + c0 + 4];
            unsigned long long w2[4];
            w2[0] = wl.x; w2[1] = wl.y; w2[2] = wh.x; w2[3] = wh.y;
            float a[8];
            a[0] = al.x; a[1] = al.y; a[2] = al.z; a[3] = al.w;
            a[4] = ah.x; a[5] = ah.y; a[6] = ah.z; a[7] = ah.w;
#pragma unroll
            for (int r = 0; r < 8; r++) {
                unsigned long long a2;
                asm("mov.b64 %0, {%1, %1};" : "=l"(a2) : "f"(a[r]));
#pragma unroll
                for (int j = 0; j < 4; j++)
                    asm("fma.rn.f32x2 %0, %1, %2, %0;"
                        : "+l"(acc2[r][j]) : "l"(a2), "l"(w2[j]));
            }
        }
        __syncthreads();
    }

    float bb[8];
#pragma unroll
    for (int j = 0; j < 8; j++) bb[j] = bias[c0 + j];
#pragma unroll
    for (int r = 0; r < 8; r++) {
        int gr = row0 + r0 + r;
        if (gr >= N) return;
        float s = SCALE ? dis[gr] : 1.0f;
        float o[8];
#pragma unroll
        for (int j = 0; j < 4; j++) {
            float lo, hi;
            asm("mov.b64 {%0, %1}, %2;" : "=f"(lo), "=f"(hi) : "l"(acc2[r][j]));
            o[2 * j]     = fmaxf(lo + bb[2 * j], 0.f) * s;
            o[2 * j + 1] = fmaxf(hi + bb[2 * j + 1], 0.f) * s;
        }
        *(float4*)&H[(size_t)gr * 128 + c0]     = make_float4(o[0], o[1], o[2], o[3]);
        *(float4*)&H[(size_t)gr * 128 + c0 + 4] = make_float4(o[4], o[5], o[6], o[7]);
    }
}

// ---------------- gather 64ch bf16 src (layer 1), prescaled ------------------
__global__ __launch_bounds__(256) void gather64bf_kernel(
    const int* __restrict__ rowptr, const int* __restrict__ deg,
    const int* __restrict__ csr, const unsigned* __restrict__ xb,
    const float* __restrict__ dis, unsigned* __restrict__ out, int n) {
    int node = (blockIdx.x * 256 + threadIdx.x) >> 5;
    int lane = threadIdx.x & 31;
    if (node >= n) return;
    float2 acc = unpack_bf2(xb[(size_t)node * 32 + lane]);
    int start = rowptr[node], d = deg[node];
    for (int e = 0; e < d; e++) {
        int u = csr[start + e];
        float2 w = unpack_bf2(xb[(size_t)u * 32 + lane]);
        acc.x += w.x; acc.y += w.y;
    }
    float dn = dis[node];
    out[(size_t)node * 32 + lane] = pack_bf2(acc.x * dn, acc.y * dn);
}

// ---------------- gather 128ch bf16 src, prescaled (layer 2) -> bf16 out -----
__global__ __launch_bounds__(256) void gather128bf_kernel(
    const int* __restrict__ rowptr, const int* __restrict__ deg,
    const int* __restrict__ csr, const __nv_bfloat16* __restrict__ hb,
    const float* __restrict__ dis, uint2* __restrict__ out, int n) {
    int node = (blockIdx.x * 256 + threadIdx.x) >> 5;
    int lane = threadIdx.x & 31;
    if (node >= n) return;
    const uint2* h8 = (const uint2*)hb;
    float a0, a1, a2, a3;
    {
        uint2 raw = h8[(size_t)node * 32 + lane];
        float2 f0 = unpack_bf2(raw.x), f1 = unpack_bf2(raw.y);
        a0 = f0.x; a1 = f0.y; a2 = f1.x; a3 = f1.y;
    }
    int start = rowptr[node], d = deg[node];
    for (int e = 0; e < d; e++) {
        int u = csr[start + e];
        uint2 raw = h8[(size_t)u * 32 + lane];
        float2 f0 = unpack_bf2(raw.x), f1 = unpack_bf2(raw.y);
        a0 += f0.x; a1 += f0.y; a2 += f1.x; a3 += f1.y;
    }
    float dn = dis[node];
    uint2 pk;
    pk.x = pack_bf2(a0 * dn, a1 * dn);
    pk.y = pack_bf2(a2 * dn, a3 * dn);
    out[(size_t)node * 32 + lane] = pk;
}

// ---------------- gather 128ch fp32 (FCG) -------------------------------------
__global__ __launch_bounds__(256) void gather128_kernel(
    const int* __restrict__ rowptr, const int* __restrict__ deg,
    const int* __restrict__ csr, const float* __restrict__ hs,
    const float* __restrict__ dis, float* __restrict__ out, int n) {
    int node = (blockIdx.x * 256 + threadIdx.x) >> 5;
    int lane = threadIdx.x & 31;
    if (node >= n) return;
    const float4* hs4 = (const float4*)hs;
    float dn = dis[node];
    float4 acc = hs4[(size_t)node * 32 + lane];
    acc.x *= dn; acc.y *= dn; acc.z *= dn; acc.w *= dn;
    int start = rowptr[node], d = deg[node];
    for (int e = 0; e < d; e++) {
        int u = csr[start + e];
        float4 v = hs4[(size_t)u * 32 + lane];
        float du = dis[u];
        acc.x += v.x * du; acc.y += v.y * du;
        acc.z += v.z * du; acc.w += v.w * du;
    }
    acc.x *= dn; acc.y *= dn; acc.z *= dn; acc.w *= dn;
    ((float4*)out)[(size_t)node * 32 + lane] = acc;
}

// ---------------- function-level mean pool -----------------------------------
__global__ __launch_bounds__(256) void poolseg_kernel(
    const float* __restrict__ x, const int* __restrict__ start,
    float* __restrict__ pool, int nseg) {
    int f = (blockIdx.x * 256 + threadIdx.x) >> 5;
    int lane = threadIdx.x & 31;
    if (f >= nseg) return;
    int s = start[f], e = start[f + 1];
    const float4* x4 = (const float4*)x;
    float4 acc = make_float4(0.f, 0.f, 0.f, 0.f);
    for (int i = s; i < e; i++) {
        float4 v = x4[(size_t)i * 32 + lane];
        acc.x += v.x; acc.y += v.y; acc.z += v.z; acc.w += v.w;
    }
    float inv = 1.0f / (float)max(e - s, 1);
    acc.x *= inv; acc.y *= inv; acc.z *= inv; acc.w *= inv;
    ((float4*)pool)[(size_t)f * 32 + lane] = acc;
}

__global__ void assemble_kernel(const float* __restrict__ pool, const float* __restrict__ emb,
                                const int* __restrict__ src, const int* __restrict__ isext,
                                float* __restrict__ fx) {
    int i = blockIdx.x * blockDim.x + threadIdx.x;
    if (i >= N_FCG * D_H) return;
    int row = i >> 7, j = i & 127;
    int s = src[row];
    float v;
    if (isext[row] == 1) {
        int k = min(max(s, 0), VOCAB - 1);
        v = emb[(size_t)k * D_H + j];
    } else {
        int k = min(max(s, 0), N_FUNC - 1);
        v = pool[(size_t)k * D_H + j];
    }
    fx[i] = v;
}

__global__ __launch_bounds__(128) void gpool_kernel(
    const float* __restrict__ y, const int* __restrict__ start, float* __restrict__ g) {
    int b = blockIdx.x, col = threadIdx.x;
    int s = start[b], e = start[b + 1];
    float acc = 0.f;
    for (int i = s; i < e; i++) acc += y[(size_t)i * 128 + col];
    g[b * 128 + col] = acc / (float)max(e - s, 1);
}

__global__ __launch_bounds__(256) void head_kernel(
    const float* __restrict__ g,
    const float* __restrict__ Wp1, const float* __restrict__ bp1,
    const float* __restrict__ Wp2, const float* __restrict__ bp2,
    const float* __restrict__ Wp3, const float* __restrict__ bp3,
    float* __restrict__ out) {
    __shared__ float G[NB * 128], H1[NB * 64], H2[NB * 32];
    int t = threadIdx.x;
    for (int i = t; i < NB * 128; i += 256) G[i] = g[i];
    __syncthreads();
    for (int i = t; i < NB * 64; i += 256) {
        int r = i >> 6, c = i & 63;
        float a = bp1[c];
        for (int k = 0; k < 128; k++) a += G[r * 128 + k] * Wp1[k * 64 + c];
        H1[i] = fmaxf(a, 0.f);
    }
    __syncthreads();
    for (int i = t; i < NB * 32; i += 256) {
        int r = i >> 5, c = i & 31;
        float a = bp2[c];
        for (int k = 0; k < 64; k++) a += H1[r * 64 + k] * Wp2[k * 32 + c];
        H2[i] = fmaxf(a, 0.f);
    }
    __syncthreads();
    if (t < NB) {
        float a = bp3[0];
        for (int k = 0; k < 32; k++) a += H2[t * 32 + k] * Wp3[k];
        out[t] = 1.0f / (1.0f + expf(-a));
    }
}

// ---------------- launch ----------------------------------------------------
extern "C" void kernel_launch(void* const* d_in, const int* in_sizes, int n_in,
                              void* d_out, int out_size) {
    const float* cfg_x  = (const float*)d_in[0];
    const int*   cfg_ei = (const int*)  d_in[1];
    const int*   n2f    = (const int*)  d_in[2];
    const int*   fcg_ei = (const int*)  d_in[3];
    const int*   fbatch = (const int*)  d_in[4];
    const int*   fsrc   = (const int*)  d_in[5];
    const int*   fext   = (const int*)  d_in[6];
    const float* W1  = (const float*)d_in[7];
    const float* b1  = (const float*)d_in[8];
    const float* W2  = (const float*)d_in[9];
    const float* b2  = (const float*)d_in[10];
    const float* emb = (const float*)d_in[11];
    const float* Wf  = (const float*)d_in[12];
    const float* bf  = (const float*)d_in[13];
    const float* Wp1 = (const float*)d_in[14];
    const float* bp1 = (const float*)d_in[15];
    const float* Wp2 = (const float*)d_in[16];
    const float* bp2 = (const float*)d_in[17];
    const float* Wp3 = (const float*)d_in[18];
    const float* bp3 = (const float*)d_in[19];
    float* out = (float*)d_out;

    void *p;
    cudaGetSymbolAddress(&p, g_a);       float* A      = (float*)p;
    cudaGetSymbolAddress(&p, g_b);       float* Bb     = (float*)p;
    cudaGetSymbolAddress(&p, g_hb);      __nv_bfloat16* HB = (__nv_bfloat16*)p;
    cudaGetSymbolAddress(&p, g_wb1);     __nv_bfloat16* Wb1 = (__nv_bfloat16*)p;
    cudaGetSymbolAddress(&p, g_wb2);     __nv_bfloat16* Wb2 = (__nv_bfloat16*)p;
    cudaGetSymbolAddress(&p, g_deg);     int*   deg    = (int*)p;
    cudaGetSymbolAddress(&p, g_dis);     float* dis    = (float*)p;
    cudaGetSymbolAddress(&p, g_rowptr);  int*   rowptr = (int*)p;
    cudaGetSymbolAddress(&p, g_cursor);  int*   cursor = (int*)p;
    cudaGetSymbolAddress(&p, g_csr);     int*   csr    = (int*)p;
    cudaGetSymbolAddress(&p, g_fdeg);    int*   fdeg   = (int*)p;
    cudaGetSymbolAddress(&p, g_fdis);    float* fdis   = (float*)p;
    cudaGetSymbolAddress(&p, g_frowptr); int*   frowptr= (int*)p;
    cudaGetSymbolAddress(&p, g_fcursor); int*   fcursor= (int*)p;
    cudaGetSymbolAddress(&p, g_fcsr);    int*   fcsr   = (int*)p;
    cudaGetSymbolAddress(&p, g_bsum);    int*   bsum   = (int*)p;
    cudaGetSymbolAddress(&p, g_fstart);  int*   fstart = (int*)p;
    cudaGetSymbolAddress(&p, g_bstart);  int*   bstart = (int*)p;
    cudaGetSymbolAddress(&p, g_pool);    float* pool   = (float*)p;
    cudaGetSymbolAddress(&p, g_fx);      float* fx     = (float*)p;
    cudaGetSymbolAddress(&p, g_fz);      float* fz     = (float*)p;
    cudaGetSymbolAddress(&p, g_fy);      float* fy     = (float*)p;
    cudaGetSymbolAddress(&p, g_g);       float* gg     = (float*)p;

    // bf16 scratch aliased into g_b (disjoint lifetimes)
    unsigned* xb  = (unsigned*)Bb;                       // cfg_x*dis, 64ch bf16
    unsigned* z1b = (unsigned*)Bb + (size_t)N_CFG * 32;  // gather1 out, 64ch bf16
    uint2*    z2b = (uint2*)Bb;                          // gather2 out, 128ch bf16

    // degrees + norms + weight conversion
    zerodeg_kernel<<<(N_CFG + 255) / 256, 256>>>();
    deg_all_kernel<<<(E_CFG + E_FCG + 255) / 256, 256>>>(cfg_ei, fcg_ei);
    dis_all_kernel<<<(N_CFG + N_FCG + 255) / 256, 256>>>();
    wtobf_kernel<<<(64 * 128 + 128 * 128 + 255) / 256, 256>>>(W1, W2);

    // CSR build (CFG)
    const int NBLK_CFG = (N_CFG + 1023) / 1024;
    scan_local<<<NBLK_CFG, 256>>>(deg, N_CFG, rowptr, bsum);
    scan_bsum<<<1, 512>>>(bsum, NBLK_CFG);
    scan_add<<<(N_CFG + 255) / 256, 256>>>(rowptr, bsum, N_CFG, cursor);
    fill_csr<<<(E_CFG + 255) / 256, 256>>>(cfg_ei, E_CFG, cursor, csr);

    // CSR build (FCG)
    const int NBLK_FCG = (N_FCG + 1023) / 1024;
    scan_local<<<NBLK_FCG, 256>>>(fdeg, N_FCG, frowptr, bsum);
    scan_bsum<<<1, 512>>>(bsum, NBLK_FCG);
    scan_add<<<(N_FCG + 255) / 256, 256>>>(frowptr, bsum, N_FCG, fcursor);
    fill_csr<<<(E_FCG + 255) / 256, 256>>>(fcg_ei, E_FCG, fcursor, fcsr);

    // segment bounds
    bounds_all_kernel<<<(N_FUNC + NB + 2 + 255) / 256, 256>>>(n2f, fbatch);

    // CFG layer 1 (bf16 edge path + WMMA GEMM):
    tobf_kernel<<<(N_CFG * 32 + 255) / 256, 256>>>((const float2*)cfg_x, dis, xb);
    gather64bf_kernel<<<(N_CFG * 32 + 255) / 256, 256>>>(rowptr, deg, csr, xb, dis, z1b, N_CFG);
    gemmw_kernel<64, true, true><<<N_CFG / 128, 256>>>(
        (const __nv_bfloat16*)z1b, Wb1, b1, dis, nullptr, HB, N_CFG);

    // CFG layer 2: gather bf16 -> WMMA GEMM -> fp32
    gather128bf_kernel<<<(N_CFG * 32 + 255) / 256, 256>>>(rowptr, deg, csr, HB, dis, z2b, N_CFG);
    gemmw_kernel<128, false, false><<<N_CFG / 128, 256>>>(
        (const __nv_bfloat16*)z2b, Wb2, b2, dis, A, nullptr, N_CFG);

    // function-level mean pool
    poolseg_kernel<<<(N_FUNC * 32 + 255) / 256, 256>>>(A, fstart, pool, N_FUNC);

    // FCG features + FCG layer (fp32 FFMA2)
    assemble_kernel<<<(N_FCG * D_H) / 256, 256>>>(pool, emb, fsrc, fext, fx);
    gather128_kernel<<<(N_FCG * 32 + 255) / 256, 256>>>(frowptr, fdeg, fcsr, fx, fdis, fz, N_FCG);
    gemmx_kernel<128, false><<<(N_FCG + 127) / 128, 256>>>(fz, Wf, bf, fdis, fy, N_FCG);

    // binary-level mean pool + head
    gpool_kernel<<<NB, 128>>>(fy, bstart, gg);
    head_kernel<<<1, 256>>>(gg, Wp1, bp1, Wp2, bp2, Wp3, bp3, out);
}

// round 9
// speedup vs baseline: 1.8494x; 1.0537x over previous
#include <cuda_runtime.h>
#include <cuda_bf16.h>
#include <mma.h>
#include <math.h>

using namespace nvcuda;

#define N_CFG 400000
#define E_CFG 1600000
#define N_FUNC 8000
#define N_FCG 9600
#define E_FCG 80000
#define NB 8
#define D_H 128
#define VOCAB 10002
#define FULLMASK 0xffffffffu

// ---------------- scratch (device globals) ----------------------------------
__device__ float g_a [(size_t)N_CFG * D_H];
__device__ float g_b [(size_t)N_CFG * D_H];
__device__ __nv_bfloat16 g_hb[(size_t)N_CFG * D_H];
__device__ __nv_bfloat16 g_wb1[64 * 128];
__device__ __nv_bfloat16 g_wb2[128 * 128];
__device__ int   g_deg[N_CFG];
__device__ float g_dis[N_CFG];
__device__ int   g_rowptr[N_CFG];
__device__ int   g_cursor[N_CFG];
__device__ int   g_csr[E_CFG];
__device__ int   g_fdeg[N_FCG];
__device__ float g_fdis[N_FCG];
__device__ int   g_frowptr[N_FCG];
__device__ int   g_fcursor[N_FCG];
__device__ int   g_fcsr[E_FCG];
__device__ int   g_bsum[512];
__device__ int   g_fstart[N_FUNC + 1];
__device__ int   g_bstart[NB + 1];
__device__ float g_pool[N_FUNC * D_H];
__device__ float g_fx [N_FCG * D_H];
__device__ float g_fz [N_FCG * D_H];
__device__ float g_fy [N_FCG * D_H];
__device__ float g_g  [NB * D_H];

static __device__ __forceinline__ unsigned pack_bf2(float a, float b) {
    __nv_bfloat162 h = __float22bfloat162_rn(make_float2(a, b));
    return *reinterpret_cast<unsigned*>(&h);
}
static __device__ __forceinline__ float2 unpack_bf2(unsigned u) {
    return __bfloat1622float2(*reinterpret_cast<const __nv_bfloat162*>(&u));
}

// ---------------- degree / norm (merged) --------------------------------------
__global__ void zerodeg_kernel() {
    int i = blockIdx.x * blockDim.x + threadIdx.x;
    if (i < N_CFG) g_deg[i] = 0;
    if (i < N_FCG) g_fdeg[i] = 0;
}
__global__ void deg_all_kernel(const int* __restrict__ cei, const int* __restrict__ fei) {
    int i = blockIdx.x * blockDim.x + threadIdx.x;
    if (i < E_CFG) {
        atomicAdd(&g_deg[cei[E_CFG + i]], 1);
    } else if (i < E_CFG + E_FCG) {
        atomicAdd(&g_fdeg[fei[E_FCG + (i - E_CFG)]], 1);
    }
}
__global__ void dis_all_kernel() {
    int i = blockIdx.x * blockDim.x + threadIdx.x;
    if (i < N_CFG) g_dis[i] = rsqrtf((float)g_deg[i] + 1.0f);
    else if (i < N_CFG + N_FCG) {
        int j = i - N_CFG;
        g_fdis[j] = rsqrtf((float)g_fdeg[j] + 1.0f);
    }
}
__global__ void wtobf_kernel(const float* __restrict__ W1, const float* __restrict__ W2) {
    int i = blockIdx.x * blockDim.x + threadIdx.x;
    if (i < 64 * 128) g_wb1[i] = __float2bfloat16(W1[i]);
    else if (i < 64 * 128 + 128 * 128) g_wb2[i - 64 * 128] = __float2bfloat16(W2[i - 64 * 128]);
}

// ---------------- CSR build ---------------------------------------------------
__global__ void scan_local(const int* __restrict__ cnt, int n, int* __restrict__ out,
                           int* __restrict__ bsum) {
    __shared__ int s[256];
    int base = blockIdx.x * 1024;
    int t = threadIdx.x;
    int v[4], sum = 0;
#pragma unroll
    for (int j = 0; j < 4; j++) {
        int i = base + t * 4 + j;
        v[j] = (i < n) ? cnt[i] : 0;
        sum += v[j];
    }
    s[t] = sum;
    __syncthreads();
    for (int off = 1; off < 256; off <<= 1) {
        int x = (t >= off) ? s[t - off] : 0;
        __syncthreads();
        s[t] += x;
        __syncthreads();
    }
    if (t == 255) bsum[blockIdx.x] = s[255];
    int run = (t > 0) ? s[t - 1] : 0;
#pragma unroll
    for (int j = 0; j < 4; j++) {
        int i = base + t * 4 + j;
        if (i < n) out[i] = run;
        run += v[j];
    }
}
__global__ void scan_bsum(int* __restrict__ bsum, int nb) {
    __shared__ int s[512];
    int t = threadIdx.x;
    s[t] = (t < nb) ? bsum[t] : 0;
    __syncthreads();
    for (int off = 1; off < 512; off <<= 1) {
        int x = (t >= off) ? s[t - off] : 0;
        __syncthreads();
        s[t] += x;
        __syncthreads();
    }
    if (t < nb) bsum[t] = (t > 0) ? s[t - 1] : 0;
}
__global__ void scan_add(int* __restrict__ out, const int* __restrict__ bsum, int n,
                         int* __restrict__ cursor) {
    int i = blockIdx.x * blockDim.x + threadIdx.x;
    if (i < n) {
        int v = out[i] + bsum[i >> 10];
        out[i] = v;
        cursor[i] = v;
    }
}
__global__ void fill_csr(const int* __restrict__ ei, int E, int* __restrict__ cursor,
                         int* __restrict__ csr) {
    int i = blockIdx.x * blockDim.x + threadIdx.x;
    if (i < E) {
        int r = ei[i], c = ei[E + i];
        int slot = atomicAdd(&cursor[c], 1);
        csr[slot] = r;
    }
}
__global__ void bounds_all_kernel(const int* __restrict__ n2f, const int* __restrict__ fbatch) {
    int i = blockIdx.x * blockDim.x + threadIdx.x;
    if (i <= N_FUNC) {
        int lo = 0, hi = N_CFG;
        while (lo < hi) {
            int mid = (lo + hi) >> 1;
            if (n2f[mid] < i) lo = mid + 1; else hi = mid;
        }
        g_fstart[i] = lo;
    } else {
        int f = i - (N_FUNC + 1);
        if (f <= NB) {
            int lo = 0, hi = N_FCG;
            while (lo < hi) {
                int mid = (lo + hi) >> 1;
                if (fbatch[mid] < f) lo = mid + 1; else hi = mid;
            }
            g_bstart[f] = lo;
        }
    }
}

// ---------------- cfg_x -> bf16 with dis prefolded ---------------------------
__global__ void tobf_kernel(const float2* __restrict__ x2, const float* __restrict__ dis,
                            unsigned* __restrict__ xb) {
    int i = blockIdx.x * blockDim.x + threadIdx.x;
    if (i >= N_CFG * 32) return;
    int row = i >> 5;
    float d = dis[row];
    float2 v = x2[i];
    xb[i] = pack_bf2(v.x * d, v.y * d);
}

// ---------------- WMMA bf16 GEMM ---------------------------------------------
template<int K, bool SCALE, bool OUTBF16>
__global__ __launch_bounds__(256, 2) void gemmw_kernel(
    const __nv_bfloat16* __restrict__ X, const __nv_bfloat16* __restrict__ Wb,
    const float* __restrict__ bias, const float* __restrict__ dis,
    float* __restrict__ H, __nv_bfloat16* __restrict__ HB, int N) {
    constexpr int AP = 40;
    constexpr int WP = 136;
    __shared__ __nv_bfloat16 As[128 * AP];
    __shared__ __nv_bfloat16 Ws[32 * WP];
    __shared__ float Eb[8][16 * 20];
    __shared__ float Bs[128];

    const int tid = threadIdx.x;
    const int warp = tid >> 5, lane = tid & 31;
    const int wr = warp >> 2;
    const int wc = warp & 3;
    const int row0 = blockIdx.x * 128;

    if (tid < 128) Bs[tid] = bias[tid];

    wmma::fragment<wmma::accumulator, 16, 16, 16, float> acc[4][2];
#pragma unroll
    for (int i = 0; i < 4; i++)
#pragma unroll
        for (int j = 0; j < 2; j++) wmma::fill_fragment(acc[i][j], 0.0f);

    const unsigned* Xu = (const unsigned*)X;
    const unsigned* Wu = (const unsigned*)Wb;
    unsigned* Asu = (unsigned*)As;
    unsigned* Wsu = (unsigned*)Ws;

    for (int kc = 0; kc < K; kc += 32) {
#pragma unroll
        for (int i = tid; i < 128 * 16; i += 256) {
            int r = i >> 4, k2 = i & 15;
            Asu[r * (AP / 2) + k2] = Xu[(size_t)(row0 + r) * (K / 2) + (kc >> 1) + k2];
        }
#pragma unroll
        for (int i = tid; i < 32 * 64; i += 256) {
            int k = i >> 6, c2 = i & 63;
            Wsu[k * (WP / 2) + c2] = Wu[(size_t)(kc + k) * 64 + c2];
        }
        __syncthreads();
#pragma unroll
        for (int ks = 0; ks < 32; ks += 16) {
            wmma::fragment<wmma::matrix_a, 16, 16, 16, __nv_bfloat16, wmma::row_major> af[4];
            wmma::fragment<wmma::matrix_b, 16, 16, 16, __nv_bfloat16, wmma::row_major> bf[2];
#pragma unroll
            for (int i = 0; i < 4; i++)
                wmma::load_matrix_sync(af[i], &As[(wr * 64 + i * 16) * AP + ks], AP);
#pragma unroll
            for (int j = 0; j < 2; j++)
                wmma::load_matrix_sync(bf[j], &Ws[ks * WP + wc * 32 + j * 16], WP);
#pragma unroll
            for (int i = 0; i < 4; i++)
#pragma unroll
                for (int j = 0; j < 2; j++)
                    wmma::mma_sync(acc[i][j], af[i], bf[j], acc[i][j]);
        }
        __syncthreads();
    }

    const int r = lane >> 1, c8 = (lane & 1) * 8;
#pragma unroll
    for (int i = 0; i < 4; i++) {
#pragma unroll
        for (int j = 0; j < 2; j++) {
            wmma::store_matrix_sync(&Eb[warp][0], acc[i][j], 20, wmma::mem_row_major);
            __syncwarp();
            int gr = row0 + wr * 64 + i * 16 + r;
            int gc = wc * 32 + j * 16 + c8;
            float s = SCALE ? dis[gr] : 1.0f;
            float o[8];
#pragma unroll
            for (int q = 0; q < 8; q++)
                o[q] = fmaxf(Eb[warp][r * 20 + c8 + q] + Bs[gc + q], 0.0f) * s;
            if (OUTBF16) {
                uint4 pk;
                pk.x = pack_bf2(o[0], o[1]); pk.y = pack_bf2(o[2], o[3]);
                pk.z = pack_bf2(o[4], o[5]); pk.w = pack_bf2(o[6], o[7]);
                *(uint4*)&HB[(size_t)gr * 128 + gc] = pk;
            } else {
                *(float4*)&H[(size_t)gr * 128 + gc]     = make_float4(o[0], o[1], o[2], o[3]);
                *(float4*)&H[(size_t)gr * 128 + gc + 4] = make_float4(o[4], o[5], o[6], o[7]);
            }
            __syncwarp();
        }
    }
}

// ---------------- FFMA2 GEMM (fp32, FCG) --------------------------------------
template<int K, bool SCALE>
__global__ __launch_bounds__(256, 2) void gemmx_kernel(
    const float* __restrict__ X, const float* __restrict__ W,
    const float* __restrict__ bias, const float* __restrict__ dis,
    float* __restrict__ H, int N) {
    __shared__ float Xs[32 * 132];
    __shared__ float Ws[32 * 128];
    const int row0 = blockIdx.x * 128;
    const int tx = threadIdx.x & 15;
    const int ty = threadIdx.x >> 4;
    const int c0 = tx * 8, r0 = ty * 8;

    unsigned long long acc2[8][4];
#pragma unroll
    for (int r = 0; r < 8; r++)
#pragma unroll
        for (int j = 0; j < 4; j++) acc2[r][j] = 0ULL;

    for (int kc = 0; kc < K; kc += 32) {
#pragma unroll
        for (int i = threadIdx.x; i < 128 * 32; i += 256) {
            int k = i & 31, r = i >> 5;
            int gr = row0 + r;
            Xs[k * 132 + r] = (gr < N) ? X[(size_t)gr * K + kc + k] : 0.f;
        }
#pragma unroll
        for (int i = threadIdx.x; i < 32 * 128; i += 256) {
            int c = i & 127, k = i >> 7;
            Ws[k * 128 + c] = W[(size_t)(kc + k) * 128 + c];
        }
        __syncthreads();
#pragma unroll 4
        for (int k = 0; k < 32; k++) {
            float4 al = *(const float4*)&Xs[k * 132 + r0];
            float4 ah = *(const float4*)&Xs[k * 132 + r0 + 4];
            ulonglong2 wl = *(const ulonglong2*)&Ws[k * 128 + c0];
            ulonglong2 wh = *(const ulonglong2*)&Ws[k * 128 + c0 + 4];
            unsigned long long w2[4];
            w2[0] = wl.x; w2[1] = wl.y; w2[2] = wh.x; w2[3] = wh.y;
            float a[8];
            a[0] = al.x; a[1] = al.y; a[2] = al.z; a[3] = al.w;
            a[4] = ah.x; a[5] = ah.y; a[6] = ah.z; a[7] = ah.w;
#pragma unroll
            for (int r = 0; r < 8; r++) {
                unsigned long long a2;
                asm("mov.b64 %0, {%1, %1};" : "=l"(a2) : "f"(a[r]));
#pragma unroll
                for (int j = 0; j < 4; j++)
                    asm("fma.rn.f32x2 %0, %1, %2, %0;"
                        : "+l"(acc2[r][j]) : "l"(a2), "l"(w2[j]));
            }
        }
        __syncthreads();
    }

    float bb[8];
#pragma unroll
    for (int j = 0; j < 8; j++) bb[j] = bias[c0 + j];
#pragma unroll
    for (int r = 0; r < 8; r++) {
        int gr = row0 + r0 + r;
        if (gr >= N) return;
        float s = SCALE ? dis[gr] : 1.0f;
        float o[8];
#pragma unroll
        for (int j = 0; j < 4; j++) {
            float lo, hi;
            asm("mov.b64 {%0, %1}, %2;" : "=f"(lo), "=f"(hi) : "l"(acc2[r][j]));
            o[2 * j]     = fmaxf(lo + bb[2 * j], 0.f) * s;
            o[2 * j + 1] = fmaxf(hi + bb[2 * j + 1], 0.f) * s;
        }
        *(float4*)&H[(size_t)gr * 128 + c0]     = make_float4(o[0], o[1], o[2], o[3]);
        *(float4*)&H[(size_t)gr * 128 + c0 + 4] = make_float4(o[4], o[5], o[6], o[7]);
    }
}

// ---------------- gather 64ch bf16, shuffle-broadcast indices ----------------
__global__ __launch_bounds__(256) void gather64bf_kernel(
    const int* __restrict__ rowptr, const int* __restrict__ deg,
    const int* __restrict__ csr, const unsigned* __restrict__ xb,
    const float* __restrict__ dis, unsigned* __restrict__ out, int n) {
    int node = (blockIdx.x * 256 + threadIdx.x) >> 5;
    int lane = threadIdx.x & 31;
    if (node >= n) return;
    int start = rowptr[node], d = deg[node];
    int dm = min(d, 32);
    int uidx = (lane < dm) ? csr[start + lane] : 0;   // one coalesced index load
    float2 acc = unpack_bf2(xb[(size_t)node * 32 + lane]);
    float2 acc2 = make_float2(0.f, 0.f);
    int e = 0;
    for (; e + 2 <= dm; e += 2) {
        int u0 = __shfl_sync(FULLMASK, uidx, e);
        int u1 = __shfl_sync(FULLMASK, uidx, e + 1);
        float2 w0 = unpack_bf2(xb[(size_t)u0 * 32 + lane]);
        float2 w1 = unpack_bf2(xb[(size_t)u1 * 32 + lane]);
        acc.x += w0.x; acc.y += w0.y;
        acc2.x += w1.x; acc2.y += w1.y;
    }
    if (e < dm) {
        int u = __shfl_sync(FULLMASK, uidx, e);
        float2 w = unpack_bf2(xb[(size_t)u * 32 + lane]);
        acc.x += w.x; acc.y += w.y;
    }
    for (e = 32; e < d; e++) {                         // effectively never
        int u = csr[start + e];
        float2 w = unpack_bf2(xb[(size_t)u * 32 + lane]);
        acc.x += w.x; acc.y += w.y;
    }
    float dn = dis[node];
    out[(size_t)node * 32 + lane] = pack_bf2((acc.x + acc2.x) * dn, (acc.y + acc2.y) * dn);
}

// ---------------- gather 128ch bf16, shuffle-broadcast indices ---------------
__global__ __launch_bounds__(256) void gather128bf_kernel(
    const int* __restrict__ rowptr, const int* __restrict__ deg,
    const int* __restrict__ csr, const __nv_bfloat16* __restrict__ hb,
    const float* __restrict__ dis, uint2* __restrict__ out, int n) {
    int node = (blockIdx.x * 256 + threadIdx.x) >> 5;
    int lane = threadIdx.x & 31;
    if (node >= n) return;
    const uint2* h8 = (const uint2*)hb;
    int start = rowptr[node], d = deg[node];
    int dm = min(d, 32);
    int uidx = (lane < dm) ? csr[start + lane] : 0;
    float a0, a1, a2, a3;
    {
        uint2 raw = h8[(size_t)node * 32 + lane];
        float2 f0 = unpack_bf2(raw.x), f1 = unpack_bf2(raw.y);
        a0 = f0.x; a1 = f0.y; a2 = f1.x; a3 = f1.y;
    }
    float b0 = 0.f, b1 = 0.f, b2 = 0.f, b3 = 0.f;
    int e = 0;
    for (; e + 2 <= dm; e += 2) {
        int u0 = __shfl_sync(FULLMASK, uidx, e);
        int u1 = __shfl_sync(FULLMASK, uidx, e + 1);
        uint2 r0 = h8[(size_t)u0 * 32 + lane];
        uint2 r1 = h8[(size_t)u1 * 32 + lane];
        float2 p0 = unpack_bf2(r0.x), p1 = unpack_bf2(r0.y);
        float2 q0 = unpack_bf2(r1.x), q1 = unpack_bf2(r1.y);
        a0 += p0.x; a1 += p0.y; a2 += p1.x; a3 += p1.y;
        b0 += q0.x; b1 += q0.y; b2 += q1.x; b3 += q1.y;
    }
    if (e < dm) {
        int u = __shfl_sync(FULLMASK, uidx, e);
        uint2 raw = h8[(size_t)u * 32 + lane];
        float2 f0 = unpack_bf2(raw.x), f1 = unpack_bf2(raw.y);
        a0 += f0.x; a1 += f0.y; a2 += f1.x; a3 += f1.y;
    }
    for (e = 32; e < d; e++) {
        int u = csr[start + e];
        uint2 raw = h8[(size_t)u * 32 + lane];
        float2 f0 = unpack_bf2(raw.x), f1 = unpack_bf2(raw.y);
        a0 += f0.x; a1 += f0.y; a2 += f1.x; a3 += f1.y;
    }
    float dn = dis[node];
    uint2 pk;
    pk.x = pack_bf2((a0 + b0) * dn, (a1 + b1) * dn);
    pk.y = pack_bf2((a2 + b2) * dn, (a3 + b3) * dn);
    out[(size_t)node * 32 + lane] = pk;
}

// ---------------- gather 128ch fp32 (FCG), shuffle indices -------------------
__global__ __launch_bounds__(256) void gather128_kernel(
    const int* __restrict__ rowptr, const int* __restrict__ deg,
    const int* __restrict__ csr, const float* __restrict__ hs,
    const float* __restrict__ dis, float* __restrict__ out, int n) {
    int node = (blockIdx.x * 256 + threadIdx.x) >> 5;
    int lane = threadIdx.x & 31;
    if (node >= n) return;
    const float4* hs4 = (const float4*)hs;
    int start = rowptr[node], d = deg[node];
    int dm = min(d, 32);
    int uidx = (lane < dm) ? csr[start + lane] : 0;
    float dn = dis[node];
    float4 acc = hs4[(size_t)node * 32 + lane];
    acc.x *= dn; acc.y *= dn; acc.z *= dn; acc.w *= dn;
    for (int e = 0; e < dm; e++) {
        int u = __shfl_sync(FULLMASK, uidx, e);
        float du = dis[u];
        float4 v = hs4[(size_t)u * 32 + lane];
        acc.x += v.x * du; acc.y += v.y * du;
        acc.z += v.z * du; acc.w += v.w * du;
    }
    for (int e = 32; e < d; e++) {
        int u = csr[start + e];
        float du = dis[u];
        float4 v = hs4[(size_t)u * 32 + lane];
        acc.x += v.x * du; acc.y += v.y * du;
        acc.z += v.z * du; acc.w += v.w * du;
    }
    acc.x *= dn; acc.y *= dn; acc.z *= dn; acc.w *= dn;
    ((float4*)out)[(size_t)node * 32 + lane] = acc;
}

// ---------------- function-level mean pool (bf16 input) -----------------------
__global__ __launch_bounds__(256) void poolsegbf_kernel(
    const __nv_bfloat16* __restrict__ x, const int* __restrict__ start,
    float* __restrict__ pool, int nseg) {
    int f = (blockIdx.x * 256 + threadIdx.x) >> 5;
    int lane = threadIdx.x & 31;
    if (f >= nseg) return;
    int s = start[f], e = start[f + 1];
    const uint2* x8 = (const uint2*)x;
    float a0 = 0.f, a1 = 0.f, a2 = 0.f, a3 = 0.f;
    for (int i = s; i < e; i++) {
        uint2 raw = x8[(size_t)i * 32 + lane];
        float2 f0 = unpack_bf2(raw.x), f1 = unpack_bf2(raw.y);
        a0 += f0.x; a1 += f0.y; a2 += f1.x; a3 += f1.y;
    }
    float inv = 1.0f / (float)max(e - s, 1);
    ((float4*)pool)[(size_t)f * 32 + lane] = make_float4(a0 * inv, a1 * inv, a2 * inv, a3 * inv);
}

__global__ void assemble_kernel(const float* __restrict__ pool, const float* __restrict__ emb,
                                const int* __restrict__ src, const int* __restrict__ isext,
                                float* __restrict__ fx) {
    int i = blockIdx.x * blockDim.x + threadIdx.x;
    if (i >= N_FCG * D_H) return;
    int row = i >> 7, j = i & 127;
    int s = src[row];
    float v;
    if (isext[row] == 1) {
        int k = min(max(s, 0), VOCAB - 1);
        v = emb[(size_t)k * D_H + j];
    } else {
        int k = min(max(s, 0), N_FUNC - 1);
        v = pool[(size_t)k * D_H + j];
    }
    fx[i] = v;
}

__global__ __launch_bounds__(128) void gpool_kernel(
    const float* __restrict__ y, const int* __restrict__ start, float* __restrict__ g) {
    int b = blockIdx.x, col = threadIdx.x;
    int s = start[b], e = start[b + 1];
    float acc = 0.f;
    for (int i = s; i < e; i++) acc += y[(size_t)i * 128 + col];
    g[b * 128 + col] = acc / (float)max(e - s, 1);
}

__global__ __launch_bounds__(256) void head_kernel(
    const float* __restrict__ g,
    const float* __restrict__ Wp1, const float* __restrict__ bp1,
    const float* __restrict__ Wp2, const float* __restrict__ bp2,
    const float* __restrict__ Wp3, const float* __restrict__ bp3,
    float* __restrict__ out) {
    __shared__ float G[NB * 128], H1[NB * 64], H2[NB * 32];
    int t = threadIdx.x;
    for (int i = t; i < NB * 128; i += 256) G[i] = g[i];
    __syncthreads();
    for (int i = t; i < NB * 64; i += 256) {
        int r = i >> 6, c = i & 63;
        float a = bp1[c];
        for (int k = 0; k < 128; k++) a += G[r * 128 + k] * Wp1[k * 64 + c];
        H1[i] = fmaxf(a, 0.f);
    }
    __syncthreads();
    for (int i = t; i < NB * 32; i += 256) {
        int r = i >> 5, c = i & 31;
        float a = bp2[c];
        for (int k = 0; k < 64; k++) a += H1[r * 64 + k] * Wp2[k * 32 + c];
        H2[i] = fmaxf(a, 0.f);
    }
    __syncthreads();
    if (t < NB) {
        float a = bp3[0];
        for (int k = 0; k < 32; k++) a += H2[t * 32 + k] * Wp3[k];
        out[t] = 1.0f / (1.0f + expf(-a));
    }
}

// ---------------- launch ----------------------------------------------------
extern "C" void kernel_launch(void* const* d_in, const int* in_sizes, int n_in,
                              void* d_out, int out_size) {
    const float* cfg_x  = (const float*)d_in[0];
    const int*   cfg_ei = (const int*)  d_in[1];
    const int*   n2f    = (const int*)  d_in[2];
    const int*   fcg_ei = (const int*)  d_in[3];
    const int*   fbatch = (const int*)  d_in[4];
    const int*   fsrc   = (const int*)  d_in[5];
    const int*   fext   = (const int*)  d_in[6];
    const float* W1  = (const float*)d_in[7];
    const float* b1  = (const float*)d_in[8];
    const float* W2  = (const float*)d_in[9];
    const float* b2  = (const float*)d_in[10];
    const float* emb = (const float*)d_in[11];
    const float* Wf  = (const float*)d_in[12];
    const float* bf  = (const float*)d_in[13];
    const float* Wp1 = (const float*)d_in[14];
    const float* bp1 = (const float*)d_in[15];
    const float* Wp2 = (const float*)d_in[16];
    const float* bp2 = (const float*)d_in[17];
    const float* Wp3 = (const float*)d_in[18];
    const float* bp3 = (const float*)d_in[19];
    float* out = (float*)d_out;

    void *p;
    cudaGetSymbolAddress(&p, g_a);       float* A      = (float*)p;
    cudaGetSymbolAddress(&p, g_b);       float* Bb     = (float*)p;
    cudaGetSymbolAddress(&p, g_hb);      __nv_bfloat16* HB = (__nv_bfloat16*)p;
    cudaGetSymbolAddress(&p, g_wb1);     __nv_bfloat16* Wb1 = (__nv_bfloat16*)p;
    cudaGetSymbolAddress(&p, g_wb2);     __nv_bfloat16* Wb2 = (__nv_bfloat16*)p;
    cudaGetSymbolAddress(&p, g_deg);     int*   deg    = (int*)p;
    cudaGetSymbolAddress(&p, g_dis);     float* dis    = (float*)p;
    cudaGetSymbolAddress(&p, g_rowptr);  int*   rowptr = (int*)p;
    cudaGetSymbolAddress(&p, g_cursor);  int*   cursor = (int*)p;
    cudaGetSymbolAddress(&p, g_csr);     int*   csr    = (int*)p;
    cudaGetSymbolAddress(&p, g_fdeg);    int*   fdeg   = (int*)p;
    cudaGetSymbolAddress(&p, g_fdis);    float* fdis   = (float*)p;
    cudaGetSymbolAddress(&p, g_frowptr); int*   frowptr= (int*)p;
    cudaGetSymbolAddress(&p, g_fcursor); int*   fcursor= (int*)p;
    cudaGetSymbolAddress(&p, g_fcsr);    int*   fcsr   = (int*)p;
    cudaGetSymbolAddress(&p, g_bsum);    int*   bsum   = (int*)p;
    cudaGetSymbolAddress(&p, g_fstart);  int*   fstart = (int*)p;
    cudaGetSymbolAddress(&p, g_bstart);  int*   bstart = (int*)p;
    cudaGetSymbolAddress(&p, g_pool);    float* pool   = (float*)p;
    cudaGetSymbolAddress(&p, g_fx);      float* fx     = (float*)p;
    cudaGetSymbolAddress(&p, g_fz);      float* fz     = (float*)p;
    cudaGetSymbolAddress(&p, g_fy);      float* fy     = (float*)p;
    cudaGetSymbolAddress(&p, g_g);       float* gg     = (float*)p;

    unsigned* xb  = (unsigned*)Bb;
    unsigned* z1b = (unsigned*)Bb + (size_t)N_CFG * 32;
    uint2*    z2b = (uint2*)Bb;

    zerodeg_kernel<<<(N_CFG + 255) / 256, 256>>>();
    deg_all_kernel<<<(E_CFG + E_FCG + 255) / 256, 256>>>(cfg_ei, fcg_ei);
    dis_all_kernel<<<(N_CFG + N_FCG + 255) / 256, 256>>>();
    wtobf_kernel<<<(64 * 128 + 128 * 128 + 255) / 256, 256>>>(W1, W2);

    const int NBLK_CFG = (N_CFG + 1023) / 1024;
    scan_local<<<NBLK_CFG, 256>>>(deg, N_CFG, rowptr, bsum);
    scan_bsum<<<1, 512>>>(bsum, NBLK_CFG);
    scan_add<<<(N_CFG + 255) / 256, 256>>>(rowptr, bsum, N_CFG, cursor);
    fill_csr<<<(E_CFG + 255) / 256, 256>>>(cfg_ei, E_CFG, cursor, csr);

    const int NBLK_FCG = (N_FCG + 1023) / 1024;
    scan_local<<<NBLK_FCG, 256>>>(fdeg, N_FCG, frowptr, bsum);
    scan_bsum<<<1, 512>>>(bsum, NBLK_FCG);
    scan_add<<<(N_FCG + 255) / 256, 256>>>(frowptr, bsum, N_FCG, fcursor);
    fill_csr<<<(E_FCG + 255) / 256, 256>>>(fcg_ei, E_FCG, fcursor, fcsr);

    bounds_all_kernel<<<(N_FUNC + NB + 2 + 255) / 256, 256>>>(n2f, fbatch);

    // CFG layer 1
    tobf_kernel<<<(N_CFG * 32 + 255) / 256, 256>>>((const float2*)cfg_x, dis, xb);
    gather64bf_kernel<<<(N_CFG * 32 + 255) / 256, 256>>>(rowptr, deg, csr, xb, dis, z1b, N_CFG);
    gemmw_kernel<64, true, true><<<N_CFG / 128, 256>>>(
        (const __nv_bfloat16*)z1b, Wb1, b1, dis, nullptr, HB, N_CFG);

    // CFG layer 2: gather (bf16) -> GEMM -> bf16 out into HB (dead after gather)
    gather128bf_kernel<<<(N_CFG * 32 + 255) / 256, 256>>>(rowptr, deg, csr, HB, dis, z2b, N_CFG);
    gemmw_kernel<128, false, true><<<N_CFG / 128, 256>>>(
        (const __nv_bfloat16*)z2b, Wb2, b2, dis, nullptr, HB, N_CFG);

    // function-level mean pool (bf16 input)
    poolsegbf_kernel<<<(N_FUNC * 32 + 255) / 256, 256>>>(HB, fstart, pool, N_FUNC);

    // FCG features + FCG layer (fp32)
    assemble_kernel<<<(N_FCG * D_H) / 256, 256>>>(pool, emb, fsrc, fext, fx);
    gather128_kernel<<<(N_FCG * 32 + 255) / 256, 256>>>(frowptr, fdeg, fcsr, fx, fdis, fz, N_FCG);
    gemmx_kernel<128, false><<<(N_FCG + 127) / 128, 256>>>(fz, Wf, bf, fdis, fy, N_FCG);

    // binary-level mean pool + head
    gpool_kernel<<<NB, 128>>>(fy, bstart, gg);
    head_kernel<<<1, 256>>>(gg, Wp1, bp1, Wp2, bp2, Wp3, bp3, out);
}

// round 10
// speedup vs baseline: 1.9455x; 1.0519x over previous
#include <cuda_runtime.h>
#include <cuda_bf16.h>
#include <mma.h>
#include <math.h>

using namespace nvcuda;

#define N_CFG 400000
#define E_CFG 1600000
#define N_FUNC 8000
#define N_FCG 9600
#define E_FCG 80000
#define NB 8
#define D_H 128
#define VOCAB 10002
#define FULLMASK 0xffffffffu

// ---------------- scratch (device globals) ----------------------------------
__device__ float g_a [(size_t)N_CFG * D_H];
__device__ float g_b [(size_t)N_CFG * D_H];
__device__ __nv_bfloat16 g_hb[(size_t)N_CFG * D_H];
__device__ __nv_bfloat16 g_wb1[64 * 128];
__device__ __nv_bfloat16 g_wb2[128 * 128];
__device__ int   g_deg[N_CFG];
__device__ float g_dis[N_CFG];
__device__ int   g_rowptr[N_CFG];
__device__ int   g_cursor[N_CFG];
__device__ int   g_csr[E_CFG];
__device__ int   g_fdeg[N_FCG];
__device__ float g_fdis[N_FCG];
__device__ int   g_frowptr[N_FCG];
__device__ int   g_fcursor[N_FCG];
__device__ int   g_fcsr[E_FCG];
__device__ int   g_bsum[512];
__device__ int   g_fstart[N_FUNC + 1];
__device__ int   g_bstart[NB + 1];
__device__ float g_pool[N_FUNC * D_H];
__device__ float g_fx [N_FCG * D_H];
__device__ float g_fz [N_FCG * D_H];
__device__ float g_fy [N_FCG * D_H];
__device__ float g_g  [NB * D_H];

static __device__ __forceinline__ unsigned pack_bf2(float a, float b) {
    __nv_bfloat162 h = __float22bfloat162_rn(make_float2(a, b));
    return *reinterpret_cast<unsigned*>(&h);
}
static __device__ __forceinline__ float2 unpack_bf2(unsigned u) {
    return __bfloat1622float2(*reinterpret_cast<const __nv_bfloat162*>(&u));
}

// ---------------- degree / norm (merged) --------------------------------------
__global__ void zerodeg_kernel() {
    int i = blockIdx.x * blockDim.x + threadIdx.x;
    if (i < N_CFG) g_deg[i] = 0;
    if (i < N_FCG) g_fdeg[i] = 0;
}
__global__ void deg_all_kernel(const int* __restrict__ cei, const int* __restrict__ fei) {
    int i = blockIdx.x * blockDim.x + threadIdx.x;
    if (i < E_CFG) {
        atomicAdd(&g_deg[cei[E_CFG + i]], 1);
    } else if (i < E_CFG + E_FCG) {
        atomicAdd(&g_fdeg[fei[E_FCG + (i - E_CFG)]], 1);
    }
}
__global__ void dis_all_kernel() {
    int i = blockIdx.x * blockDim.x + threadIdx.x;
    if (i < N_CFG) g_dis[i] = rsqrtf((float)g_deg[i] + 1.0f);
    else if (i < N_CFG + N_FCG) {
        int j = i - N_CFG;
        g_fdis[j] = rsqrtf((float)g_fdeg[j] + 1.0f);
    }
}
__global__ void wtobf_kernel(const float* __restrict__ W1, const float* __restrict__ W2) {
    int i = blockIdx.x * blockDim.x + threadIdx.x;
    if (i < 64 * 128) g_wb1[i] = __float2bfloat16(W1[i]);
    else if (i < 64 * 128 + 128 * 128) g_wb2[i - 64 * 128] = __float2bfloat16(W2[i - 64 * 128]);
}

// ---------------- CSR build ---------------------------------------------------
__global__ void scan_local(const int* __restrict__ cnt, int n, int* __restrict__ out,
                           int* __restrict__ bsum) {
    __shared__ int s[256];
    int base = blockIdx.x * 1024;
    int t = threadIdx.x;
    int v[4], sum = 0;
#pragma unroll
    for (int j = 0; j < 4; j++) {
        int i = base + t * 4 + j;
        v[j] = (i < n) ? cnt[i] : 0;
        sum += v[j];
    }
    s[t] = sum;
    __syncthreads();
    for (int off = 1; off < 256; off <<= 1) {
        int x = (t >= off) ? s[t - off] : 0;
        __syncthreads();
        s[t] += x;
        __syncthreads();
    }
    if (t == 255) bsum[blockIdx.x] = s[255];
    int run = (t > 0) ? s[t - 1] : 0;
#pragma unroll
    for (int j = 0; j < 4; j++) {
        int i = base + t * 4 + j;
        if (i < n) out[i] = run;
        run += v[j];
    }
}
__global__ void scan_bsum(int* __restrict__ bsum, int nb) {
    __shared__ int s[512];
    int t = threadIdx.x;
    s[t] = (t < nb) ? bsum[t] : 0;
    __syncthreads();
    for (int off = 1; off < 512; off <<= 1) {
        int x = (t >= off) ? s[t - off] : 0;
        __syncthreads();
        s[t] += x;
        __syncthreads();
    }
    if (t < nb) bsum[t] = (t > 0) ? s[t - 1] : 0;
}
__global__ void scan_add(int* __restrict__ out, const int* __restrict__ bsum, int n,
                         int* __restrict__ cursor) {
    int i = blockIdx.x * blockDim.x + threadIdx.x;
    if (i < n) {
        int v = out[i] + bsum[i >> 10];
        out[i] = v;
        cursor[i] = v;
    }
}
__global__ void fill_csr(const int* __restrict__ ei, int E, int* __restrict__ cursor,
                         int* __restrict__ csr) {
    int i = blockIdx.x * blockDim.x + threadIdx.x;
    if (i < E) {
        int r = ei[i], c = ei[E + i];
        int slot = atomicAdd(&cursor[c], 1);
        csr[slot] = r;
    }
}
__global__ void bounds_all_kernel(const int* __restrict__ n2f, const int* __restrict__ fbatch) {
    int i = blockIdx.x * blockDim.x + threadIdx.x;
    if (i <= N_FUNC) {
        int lo = 0, hi = N_CFG;
        while (lo < hi) {
            int mid = (lo + hi) >> 1;
            if (n2f[mid] < i) lo = mid + 1; else hi = mid;
        }
        g_fstart[i] = lo;
    } else {
        int f = i - (N_FUNC + 1);
        if (f <= NB) {
            int lo = 0, hi = N_FCG;
            while (lo < hi) {
                int mid = (lo + hi) >> 1;
                if (fbatch[mid] < f) lo = mid + 1; else hi = mid;
            }
            g_bstart[f] = lo;
        }
    }
}

// ---------------- cfg_x -> bf16 with dis prefolded ---------------------------
__global__ void tobf_kernel(const float2* __restrict__ x2, const float* __restrict__ dis,
                            unsigned* __restrict__ xb) {
    int i = blockIdx.x * blockDim.x + threadIdx.x;
    if (i >= N_CFG * 32) return;
    int row = i >> 5;
    float d = dis[row];
    float2 v = x2[i];
    xb[i] = pack_bf2(v.x * d, v.y * d);
}

// ---------------- WMMA bf16 GEMM ---------------------------------------------
template<int K, bool SCALE, bool OUTBF16>
__global__ __launch_bounds__(256, 2) void gemmw_kernel(
    const __nv_bfloat16* __restrict__ X, const __nv_bfloat16* __restrict__ Wb,
    const float* __restrict__ bias, const float* __restrict__ dis,
    float* __restrict__ H, __nv_bfloat16* __restrict__ HB, int N) {
    constexpr int AP = 40;
    constexpr int WP = 136;
    __shared__ __nv_bfloat16 As[128 * AP];
    __shared__ __nv_bfloat16 Ws[32 * WP];
    __shared__ float Eb[8][16 * 20];
    __shared__ float Bs[128];

    const int tid = threadIdx.x;
    const int warp = tid >> 5, lane = tid & 31;
    const int wr = warp >> 2;
    const int wc = warp & 3;
    const int row0 = blockIdx.x * 128;

    if (tid < 128) Bs[tid] = bias[tid];

    wmma::fragment<wmma::accumulator, 16, 16, 16, float> acc[4][2];
#pragma unroll
    for (int i = 0; i < 4; i++)
#pragma unroll
        for (int j = 0; j < 2; j++) wmma::fill_fragment(acc[i][j], 0.0f);

    const unsigned* Xu = (const unsigned*)X;
    const unsigned* Wu = (const unsigned*)Wb;
    unsigned* Asu = (unsigned*)As;
    unsigned* Wsu = (unsigned*)Ws;

    for (int kc = 0; kc < K; kc += 32) {
#pragma unroll
        for (int i = tid; i < 128 * 16; i += 256) {
            int r = i >> 4, k2 = i & 15;
            Asu[r * (AP / 2) + k2] = Xu[(size_t)(row0 + r) * (K / 2) + (kc >> 1) + k2];
        }
#pragma unroll
        for (int i = tid; i < 32 * 64; i += 256) {
            int k = i >> 6, c2 = i & 63;
            Wsu[k * (WP / 2) + c2] = Wu[(size_t)(kc + k) * 64 + c2];
        }
        __syncthreads();
#pragma unroll
        for (int ks = 0; ks < 32; ks += 16) {
            wmma::fragment<wmma::matrix_a, 16, 16, 16, __nv_bfloat16, wmma::row_major> af[4];
            wmma::fragment<wmma::matrix_b, 16, 16, 16, __nv_bfloat16, wmma::row_major> bf[2];
#pragma unroll
            for (int i = 0; i < 4; i++)
                wmma::load_matrix_sync(af[i], &As[(wr * 64 + i * 16) * AP + ks], AP);
#pragma unroll
            for (int j = 0; j < 2; j++)
                wmma::load_matrix_sync(bf[j], &Ws[ks * WP + wc * 32 + j * 16], WP);
#pragma unroll
            for (int i = 0; i < 4; i++)
#pragma unroll
                for (int j = 0; j < 2; j++)
                    wmma::mma_sync(acc[i][j], af[i], bf[j], acc[i][j]);
        }
        __syncthreads();
    }

    const int r = lane >> 1, c8 = (lane & 1) * 8;
#pragma unroll
    for (int i = 0; i < 4; i++) {
#pragma unroll
        for (int j = 0; j < 2; j++) {
            wmma::store_matrix_sync(&Eb[warp][0], acc[i][j], 20, wmma::mem_row_major);
            __syncwarp();
            int gr = row0 + wr * 64 + i * 16 + r;
            int gc = wc * 32 + j * 16 + c8;
            float s = SCALE ? dis[gr] : 1.0f;
            float o[8];
#pragma unroll
            for (int q = 0; q < 8; q++)
                o[q] = fmaxf(Eb[warp][r * 20 + c8 + q] + Bs[gc + q], 0.0f) * s;
            if (OUTBF16) {
                uint4 pk;
                pk.x = pack_bf2(o[0], o[1]); pk.y = pack_bf2(o[2], o[3]);
                pk.z = pack_bf2(o[4], o[5]); pk.w = pack_bf2(o[6], o[7]);
                *(uint4*)&HB[(size_t)gr * 128 + gc] = pk;
            } else {
                *(float4*)&H[(size_t)gr * 128 + gc]     = make_float4(o[0], o[1], o[2], o[3]);
                *(float4*)&H[(size_t)gr * 128 + gc + 4] = make_float4(o[4], o[5], o[6], o[7]);
            }
            __syncwarp();
        }
    }
}

// ---------------- FFMA2 GEMM (fp32, FCG) --------------------------------------
template<int K, bool SCALE>
__global__ __launch_bounds__(256, 2) void gemmx_kernel(
    const float* __restrict__ X, const float* __restrict__ W,
    const float* __restrict__ bias, const float* __restrict__ dis,
    float* __restrict__ H, int N) {
    __shared__ float Xs[32 * 132];
    __shared__ float Ws[32 * 128];
    const int row0 = blockIdx.x * 128;
    const int tx = threadIdx.x & 15;
    const int ty = threadIdx.x >> 4;
    const int c0 = tx * 8, r0 = ty * 8;

    unsigned long long acc2[8][4];
#pragma unroll
    for (int r = 0; r < 8; r++)
#pragma unroll
        for (int j = 0; j < 4; j++) acc2[r][j] = 0ULL;

    for (int kc = 0; kc < K; kc += 32) {
#pragma unroll
        for (int i = threadIdx.x; i < 128 * 32; i += 256) {
            int k = i & 31, r = i >> 5;
            int gr = row0 + r;
            Xs[k * 132 + r] = (gr < N) ? X[(size_t)gr * K + kc + k] : 0.f;
        }
#pragma unroll
        for (int i = threadIdx.x; i < 32 * 128; i += 256) {
            int c = i & 127, k = i >> 7;
            Ws[k * 128 + c] = W[(size_t)(kc + k) * 128 + c];
        }
        __syncthreads();
#pragma unroll 4
        for (int k = 0; k < 32; k++) {
            float4 al = *(const float4*)&Xs[k * 132 + r0];
            float4 ah = *(const float4*)&Xs[k * 132 + r0 + 4];
            ulonglong2 wl = *(const ulonglong2*)&Ws[k * 128 + c0];
            ulonglong2 wh = *(const ulonglong2*)&Ws[k * 128 + c0 + 4];
            unsigned long long w2[4];
            w2[0] = wl.x; w2[1] = wl.y; w2[2] = wh.x; w2[3] = wh.y;
            float a[8];
            a[0] = al.x; a[1] = al.y; a[2] = al.z; a[3] = al.w;
            a[4] = ah.x; a[5] = ah.y; a[6] = ah.z; a[7] = ah.w;
#pragma unroll
            for (int r = 0; r < 8; r++) {
                unsigned long long a2;
                asm("mov.b64 %0, {%1, %1};" : "=l"(a2) : "f"(a[r]));
#pragma unroll
                for (int j = 0; j < 4; j++)
                    asm("fma.rn.f32x2 %0, %1, %2, %0;"
                        : "+l"(acc2[r][j]) : "l"(a2), "l"(w2[j]));
            }
        }
        __syncthreads();
    }

    float bb[8];
#pragma unroll
    for (int j = 0; j < 8; j++) bb[j] = bias[c0 + j];
#pragma unroll
    for (int r = 0; r < 8; r++) {
        int gr = row0 + r0 + r;
        if (gr >= N) return;
        float s = SCALE ? dis[gr] : 1.0f;
        float o[8];
#pragma unroll
        for (int j = 0; j < 4; j++) {
            float lo, hi;
            asm("mov.b64 {%0, %1}, %2;" : "=f"(lo), "=f"(hi) : "l"(acc2[r][j]));
            o[2 * j]     = fmaxf(lo + bb[2 * j], 0.f) * s;
            o[2 * j + 1] = fmaxf(hi + bb[2 * j + 1], 0.f) * s;
        }
        *(float4*)&H[(size_t)gr * 128 + c0]     = make_float4(o[0], o[1], o[2], o[3]);
        *(float4*)&H[(size_t)gr * 128 + c0 + 4] = make_float4(o[4], o[5], o[6], o[7]);
    }
}

// ---------------- gather 64ch bf16, HALF-WARP per node ------------------------
// 2 nodes/warp: 16 lanes x uint2 (8B) = 128B row. Indices shuffled within half.
__global__ __launch_bounds__(256) void gather64bf_kernel(
    const int* __restrict__ rowptr, const int* __restrict__ deg,
    const int* __restrict__ csr, const uint2* __restrict__ xb,
    const float* __restrict__ dis, uint2* __restrict__ out, int n) {
    int lane = threadIdx.x & 31;
    int half = lane >> 4;               // 0 or 1
    int sub  = lane & 15;
    int node = ((blockIdx.x * 256 + threadIdx.x) >> 5) * 2 + half;
    if (node >= n) return;
    int start = rowptr[node], d = deg[node];
    int dm = min(d, 16);
    int uidx = (sub < dm) ? csr[start + sub] : 0;
    uint2 raw = xb[(size_t)node * 16 + sub];
    float2 p = unpack_bf2(raw.x), q = unpack_bf2(raw.y);
    float a0 = p.x, a1 = p.y, a2 = q.x, a3 = q.y;
    float b0 = 0.f, b1 = 0.f, b2 = 0.f, b3 = 0.f;
    int e = 0;
    for (; e + 2 <= dm; e += 2) {
        int u0 = __shfl_sync(FULLMASK, uidx, (half << 4) + e);
        int u1 = __shfl_sync(FULLMASK, uidx, (half << 4) + e + 1);
        uint2 r0 = xb[(size_t)u0 * 16 + sub];
        uint2 r1 = xb[(size_t)u1 * 16 + sub];
        float2 p0 = unpack_bf2(r0.x), q0 = unpack_bf2(r0.y);
        float2 p1 = unpack_bf2(r1.x), q1 = unpack_bf2(r1.y);
        a0 += p0.x; a1 += p0.y; a2 += q0.x; a3 += q0.y;
        b0 += p1.x; b1 += p1.y; b2 += q1.x; b3 += q1.y;
    }
    if (e < dm) {
        int u = __shfl_sync(FULLMASK, uidx, (half << 4) + e);
        uint2 r0 = xb[(size_t)u * 16 + sub];
        float2 p0 = unpack_bf2(r0.x), q0 = unpack_bf2(r0.y);
        a0 += p0.x; a1 += p0.y; a2 += q0.x; a3 += q0.y;
    }
    for (e = 16; e < d; e++) {          // rare fallback
        int u = csr[start + e];
        uint2 r0 = xb[(size_t)u * 16 + sub];
        float2 p0 = unpack_bf2(r0.x), q0 = unpack_bf2(r0.y);
        a0 += p0.x; a1 += p0.y; a2 += q0.x; a3 += q0.y;
    }
    float dn = dis[node];
    uint2 pk;
    pk.x = pack_bf2((a0 + b0) * dn, (a1 + b1) * dn);
    pk.y = pack_bf2((a2 + b2) * dn, (a3 + b3) * dn);
    out[(size_t)node * 16 + sub] = pk;
}

// ---------------- gather 128ch bf16, HALF-WARP per node -----------------------
// 2 nodes/warp: 16 lanes x uint4 (16B) = 256B row.
__global__ __launch_bounds__(256) void gather128bf_kernel(
    const int* __restrict__ rowptr, const int* __restrict__ deg,
    const int* __restrict__ csr, const __nv_bfloat16* __restrict__ hb,
    const float* __restrict__ dis, uint4* __restrict__ out, int n) {
    int lane = threadIdx.x & 31;
    int half = lane >> 4;
    int sub  = lane & 15;
    int node = ((blockIdx.x * 256 + threadIdx.x) >> 5) * 2 + half;
    if (node >= n) return;
    const uint4* h16 = (const uint4*)hb;   // 8 bf16 per uint4; 16 per row
    int start = rowptr[node], d = deg[node];
    int dm = min(d, 16);
    int uidx = (sub < dm) ? csr[start + sub] : 0;
    float acc[8];
    {
        uint4 raw = h16[(size_t)node * 16 + sub];
        float2 f0 = unpack_bf2(raw.x), f1 = unpack_bf2(raw.y);
        float2 f2 = unpack_bf2(raw.z), f3 = unpack_bf2(raw.w);
        acc[0] = f0.x; acc[1] = f0.y; acc[2] = f1.x; acc[3] = f1.y;
        acc[4] = f2.x; acc[5] = f2.y; acc[6] = f3.x; acc[7] = f3.y;
    }
    float acb[8] = {0.f, 0.f, 0.f, 0.f, 0.f, 0.f, 0.f, 0.f};
    int e = 0;
    for (; e + 2 <= dm; e += 2) {
        int u0 = __shfl_sync(FULLMASK, uidx, (half << 4) + e);
        int u1 = __shfl_sync(FULLMASK, uidx, (half << 4) + e + 1);
        uint4 r0 = h16[(size_t)u0 * 16 + sub];
        uint4 r1 = h16[(size_t)u1 * 16 + sub];
        float2 p0 = unpack_bf2(r0.x), p1 = unpack_bf2(r0.y);
        float2 p2 = unpack_bf2(r0.z), p3 = unpack_bf2(r0.w);
        float2 q0 = unpack_bf2(r1.x), q1 = unpack_bf2(r1.y);
        float2 q2 = unpack_bf2(r1.z), q3 = unpack_bf2(r1.w);
        acc[0] += p0.x; acc[1] += p0.y; acc[2] += p1.x; acc[3] += p1.y;
        acc[4] += p2.x; acc[5] += p2.y; acc[6] += p3.x; acc[7] += p3.y;
        acb[0] += q0.x; acb[1] += q0.y; acb[2] += q1.x; acb[3] += q1.y;
        acb[4] += q2.x; acb[5] += q2.y; acb[6] += q3.x; acb[7] += q3.y;
    }
    if (e < dm) {
        int u = __shfl_sync(FULLMASK, uidx, (half << 4) + e);
        uint4 r0 = h16[(size_t)u * 16 + sub];
        float2 p0 = unpack_bf2(r0.x), p1 = unpack_bf2(r0.y);
        float2 p2 = unpack_bf2(r0.z), p3 = unpack_bf2(r0.w);
        acc[0] += p0.x; acc[1] += p0.y; acc[2] += p1.x; acc[3] += p1.y;
        acc[4] += p2.x; acc[5] += p2.y; acc[6] += p3.x; acc[7] += p3.y;
    }
    for (e = 16; e < d; e++) {
        int u = csr[start + e];
        uint4 r0 = h16[(size_t)u * 16 + sub];
        float2 p0 = unpack_bf2(r0.x), p1 = unpack_bf2(r0.y);
        float2 p2 = unpack_bf2(r0.z), p3 = unpack_bf2(r0.w);
        acc[0] += p0.x; acc[1] += p0.y; acc[2] += p1.x; acc[3] += p1.y;
        acc[4] += p2.x; acc[5] += p2.y; acc[6] += p3.x; acc[7] += p3.y;
    }
    float dn = dis[node];
    uint4 pk;
    pk.x = pack_bf2((acc[0] + acb[0]) * dn, (acc[1] + acb[1]) * dn);
    pk.y = pack_bf2((acc[2] + acb[2]) * dn, (acc[3] + acb[3]) * dn);
    pk.z = pack_bf2((acc[4] + acb[4]) * dn, (acc[5] + acb[5]) * dn);
    pk.w = pack_bf2((acc[6] + acb[6]) * dn, (acc[7] + acb[7]) * dn);
    out[(size_t)node * 16 + sub] = pk;
}

// ---------------- gather 128ch fp32 (FCG), shuffle indices -------------------
__global__ __launch_bounds__(256) void gather128_kernel(
    const int* __restrict__ rowptr, const int* __restrict__ deg,
    const int* __restrict__ csr, const float* __restrict__ hs,
    const float* __restrict__ dis, float* __restrict__ out, int n) {
    int node = (blockIdx.x * 256 + threadIdx.x) >> 5;
    int lane = threadIdx.x & 31;
    if (node >= n) return;
    const float4* hs4 = (const float4*)hs;
    int start = rowptr[node], d = deg[node];
    int dm = min(d, 32);
    int uidx = (lane < dm) ? csr[start + lane] : 0;
    float dn = dis[node];
    float4 acc = hs4[(size_t)node * 32 + lane];
    acc.x *= dn; acc.y *= dn; acc.z *= dn; acc.w *= dn;
    for (int e = 0; e < dm; e++) {
        int u = __shfl_sync(FULLMASK, uidx, e);
        float du = dis[u];
        float4 v = hs4[(size_t)u * 32 + lane];
        acc.x += v.x * du; acc.y += v.y * du;
        acc.z += v.z * du; acc.w += v.w * du;
    }
    for (int e = 32; e < d; e++) {
        int u = csr[start + e];
        float du = dis[u];
        float4 v = hs4[(size_t)u * 32 + lane];
        acc.x += v.x * du; acc.y += v.y * du;
        acc.z += v.z * du; acc.w += v.w * du;
    }
    acc.x *= dn; acc.y *= dn; acc.z *= dn; acc.w *= dn;
    ((float4*)out)[(size_t)node * 32 + lane] = acc;
}

// ---------------- function-level mean pool (bf16 input) -----------------------
__global__ __launch_bounds__(256) void poolsegbf_kernel(
    const __nv_bfloat16* __restrict__ x, const int* __restrict__ start,
    float* __restrict__ pool, int nseg) {
    int f = (blockIdx.x * 256 + threadIdx.x) >> 5;
    int lane = threadIdx.x & 31;
    if (f >= nseg) return;
    int s = start[f], e = start[f + 1];
    const uint2* x8 = (const uint2*)x;
    float a0 = 0.f, a1 = 0.f, a2 = 0.f, a3 = 0.f;
    for (int i = s; i < e; i++) {
        uint2 raw = x8[(size_t)i * 32 + lane];
        float2 f0 = unpack_bf2(raw.x), f1 = unpack_bf2(raw.y);
        a0 += f0.x; a1 += f0.y; a2 += f1.x; a3 += f1.y;
    }
    float inv = 1.0f / (float)max(e - s, 1);
    ((float4*)pool)[(size_t)f * 32 + lane] = make_float4(a0 * inv, a1 * inv, a2 * inv, a3 * inv);
}

__global__ void assemble_kernel(const float* __restrict__ pool, const float* __restrict__ emb,
                                const int* __restrict__ src, const int* __restrict__ isext,
                                float* __restrict__ fx) {
    int i = blockIdx.x * blockDim.x + threadIdx.x;
    if (i >= N_FCG * D_H) return;
    int row = i >> 7, j = i & 127;
    int s = src[row];
    float v;
    if (isext[row] == 1) {
        int k = min(max(s, 0), VOCAB - 1);
        v = emb[(size_t)k * D_H + j];
    } else {
        int k = min(max(s, 0), N_FUNC - 1);
        v = pool[(size_t)k * D_H + j];
    }
    fx[i] = v;
}

__global__ __launch_bounds__(128) void gpool_kernel(
    const float* __restrict__ y, const int* __restrict__ start, float* __restrict__ g) {
    int b = blockIdx.x, col = threadIdx.x;
    int s = start[b], e = start[b + 1];
    float acc = 0.f;
    for (int i = s; i < e; i++) acc += y[(size_t)i * 128 + col];
    g[b * 128 + col] = acc / (float)max(e - s, 1);
}

__global__ __launch_bounds__(256) void head_kernel(
    const float* __restrict__ g,
    const float* __restrict__ Wp1, const float* __restrict__ bp1,
    const float* __restrict__ Wp2, const float* __restrict__ bp2,
    const float* __restrict__ Wp3, const float* __restrict__ bp3,
    float* __restrict__ out) {
    __shared__ float G[NB * 128], H1[NB * 64], H2[NB * 32];
    int t = threadIdx.x;
    for (int i = t; i < NB * 128; i += 256) G[i] = g[i];
    __syncthreads();
    for (int i = t; i < NB * 64; i += 256) {
        int r = i >> 6, c = i & 63;
        float a = bp1[c];
        for (int k = 0; k < 128; k++) a += G[r * 128 + k] * Wp1[k * 64 + c];
        H1[i] = fmaxf(a, 0.f);
    }
    __syncthreads();
    for (int i = t; i < NB * 32; i += 256) {
        int r = i >> 5, c = i & 31;
        float a = bp2[c];
        for (int k = 0; k < 64; k++) a += H1[r * 64 + k] * Wp2[k * 32 + c];
        H2[i] = fmaxf(a, 0.f);
    }
    __syncthreads();
    if (t < NB) {
        float a = bp3[0];
        for (int k = 0; k < 32; k++) a += H2[t * 32 + k] * Wp3[k];
        out[t] = 1.0f / (1.0f + expf(-a));
    }
}

// ---------------- launch ----------------------------------------------------
extern "C" void kernel_launch(void* const* d_in, const int* in_sizes, int n_in,
                              void* d_out, int out_size) {
    const float* cfg_x  = (const float*)d_in[0];
    const int*   cfg_ei = (const int*)  d_in[1];
    const int*   n2f    = (const int*)  d_in[2];
    const int*   fcg_ei = (const int*)  d_in[3];
    const int*   fbatch = (const int*)  d_in[4];
    const int*   fsrc   = (const int*)  d_in[5];
    const int*   fext   = (const int*)  d_in[6];
    const float* W1  = (const float*)d_in[7];
    const float* b1  = (const float*)d_in[8];
    const float* W2  = (const float*)d_in[9];
    const float* b2  = (const float*)d_in[10];
    const float* emb = (const float*)d_in[11];
    const float* Wf  = (const float*)d_in[12];
    const float* bf  = (const float*)d_in[13];
    const float* Wp1 = (const float*)d_in[14];
    const float* bp1 = (const float*)d_in[15];
    const float* Wp2 = (const float*)d_in[16];
    const float* bp2 = (const float*)d_in[17];
    const float* Wp3 = (const float*)d_in[18];
    const float* bp3 = (const float*)d_in[19];
    float* out = (float*)d_out;

    void *p;
    cudaGetSymbolAddress(&p, g_a);       float* A      = (float*)p;
    cudaGetSymbolAddress(&p, g_b);       float* Bb     = (float*)p;
    cudaGetSymbolAddress(&p, g_hb);      __nv_bfloat16* HB = (__nv_bfloat16*)p;
    cudaGetSymbolAddress(&p, g_wb1);     __nv_bfloat16* Wb1 = (__nv_bfloat16*)p;
    cudaGetSymbolAddress(&p, g_wb2);     __nv_bfloat16* Wb2 = (__nv_bfloat16*)p;
    cudaGetSymbolAddress(&p, g_deg);     int*   deg    = (int*)p;
    cudaGetSymbolAddress(&p, g_dis);     float* dis    = (float*)p;
    cudaGetSymbolAddress(&p, g_rowptr);  int*   rowptr = (int*)p;
    cudaGetSymbolAddress(&p, g_cursor);  int*   cursor = (int*)p;
    cudaGetSymbolAddress(&p, g_csr);     int*   csr    = (int*)p;
    cudaGetSymbolAddress(&p, g_fdeg);    int*   fdeg   = (int*)p;
    cudaGetSymbolAddress(&p, g_fdis);    float* fdis   = (float*)p;
    cudaGetSymbolAddress(&p, g_frowptr); int*   frowptr= (int*)p;
    cudaGetSymbolAddress(&p, g_fcursor); int*   fcursor= (int*)p;
    cudaGetSymbolAddress(&p, g_fcsr);    int*   fcsr   = (int*)p;
    cudaGetSymbolAddress(&p, g_bsum);    int*   bsum   = (int*)p;
    cudaGetSymbolAddress(&p, g_fstart);  int*   fstart = (int*)p;
    cudaGetSymbolAddress(&p, g_bstart);  int*   bstart = (int*)p;
    cudaGetSymbolAddress(&p, g_pool);    float* pool   = (float*)p;
    cudaGetSymbolAddress(&p, g_fx);      float* fx     = (float*)p;
    cudaGetSymbolAddress(&p, g_fz);      float* fz     = (float*)p;
    cudaGetSymbolAddress(&p, g_fy);      float* fy     = (float*)p;
    cudaGetSymbolAddress(&p, g_g);       float* gg     = (float*)p;

    unsigned* xb  = (unsigned*)Bb;
    unsigned* z1b = (unsigned*)Bb + (size_t)N_CFG * 32;
    uint4*    z2b = (uint4*)Bb;

    zerodeg_kernel<<<(N_CFG + 255) / 256, 256>>>();
    deg_all_kernel<<<(E_CFG + E_FCG + 255) / 256, 256>>>(cfg_ei, fcg_ei);
    dis_all_kernel<<<(N_CFG + N_FCG + 255) / 256, 256>>>();
    wtobf_kernel<<<(64 * 128 + 128 * 128 + 255) / 256, 256>>>(W1, W2);

    const int NBLK_CFG = (N_CFG + 1023) / 1024;
    scan_local<<<NBLK_CFG, 256>>>(deg, N_CFG, rowptr, bsum);
    scan_bsum<<<1, 512>>>(bsum, NBLK_CFG);
    scan_add<<<(N_CFG + 255) / 256, 256>>>(rowptr, bsum, N_CFG, cursor);
    fill_csr<<<(E_CFG + 255) / 256, 256>>>(cfg_ei, E_CFG, cursor, csr);

    const int NBLK_FCG = (N_FCG + 1023) / 1024;
    scan_local<<<NBLK_FCG, 256>>>(fdeg, N_FCG, frowptr, bsum);
    scan_bsum<<<1, 512>>>(bsum, NBLK_FCG);
    scan_add<<<(N_FCG + 255) / 256, 256>>>(frowptr, bsum, N_FCG, fcursor);
    fill_csr<<<(E_FCG + 255) / 256, 256>>>(fcg_ei, E_FCG, fcursor, fcsr);

    bounds_all_kernel<<<(N_FUNC + NB + 2 + 255) / 256, 256>>>(n2f, fbatch);

    // CFG layer 1 (half-warp gathers: 16 nodes per 256-thread block)
    tobf_kernel<<<(N_CFG * 32 + 255) / 256, 256>>>((const float2*)cfg_x, dis, xb);
    gather64bf_kernel<<<(N_CFG + 15) / 16, 256>>>(rowptr, deg, csr,
                                                  (const uint2*)xb, dis, (uint2*)z1b, N_CFG);
    gemmw_kernel<64, true, true><<<N_CFG / 128, 256>>>(
        (const __nv_bfloat16*)z1b, Wb1, b1, dis, nullptr, HB, N_CFG);

    // CFG layer 2
    gather128bf_kernel<<<(N_CFG + 15) / 16, 256>>>(rowptr, deg, csr, HB, dis, z2b, N_CFG);
    gemmw_kernel<128, false, true><<<N_CFG / 128, 256>>>(
        (const __nv_bfloat16*)z2b, Wb2, b2, dis, nullptr, HB, N_CFG);

    // function-level mean pool (bf16 input)
    poolsegbf_kernel<<<(N_FUNC * 32 + 255) / 256, 256>>>(HB, fstart, pool, N_FUNC);

    // FCG features + FCG layer (fp32)
    assemble_kernel<<<(N_FCG * D_H) / 256, 256>>>(pool, emb, fsrc, fext, fx);
    gather128_kernel<<<(N_FCG * 32 + 255) / 256, 256>>>(frowptr, fdeg, fcsr, fx, fdis, fz, N_FCG);
    gemmx_kernel<128, false><<<(N_FCG + 127) / 128, 256>>>(fz, Wf, bf, fdis, fy, N_FCG);

    // binary-level mean pool + head
    gpool_kernel<<<NB, 128>>>(fy, bstart, gg);
    head_kernel<<<1, 256>>>(gg, Wp1, bp1, Wp2, bp2, Wp3, bp3, out);
}

// round 11
// speedup vs baseline: 2.0073x; 1.0318x over previous
#include <cuda_runtime.h>
#include <cuda_bf16.h>
#include <mma.h>
#include <math.h>

using namespace nvcuda;

#define N_CFG 400000
#define E_CFG 1600000
#define N_FUNC 8000
#define N_FCG 9600
#define E_FCG 80000
#define NB 8
#define D_H 128
#define VOCAB 10002
#define FULLMASK 0xffffffffu

// ---------------- scratch (device globals) ----------------------------------
__device__ float g_a [(size_t)N_CFG * D_H];
__device__ float g_b [(size_t)N_CFG * D_H];
__device__ __nv_bfloat16 g_hb[(size_t)N_CFG * D_H];
__device__ __nv_bfloat16 g_wb1[64 * 128];
__device__ __nv_bfloat16 g_wb2[128 * 128];
__device__ int   g_deg[N_CFG];
__device__ float g_dis[N_CFG];
__device__ int   g_rowptr[N_CFG];
__device__ int   g_cursor[N_CFG];
__device__ int   g_csr[E_CFG];
__device__ int   g_fdeg[N_FCG];
__device__ float g_fdis[N_FCG];
__device__ int   g_frowptr[N_FCG];
__device__ int   g_fcursor[N_FCG];
__device__ int   g_fcsr[E_FCG];
__device__ int   g_bsum[512];
__device__ int   g_fstart[N_FUNC + 1];
__device__ int   g_bstart[NB + 1];
__device__ float g_pool[N_FUNC * D_H];
__device__ float g_fx [N_FCG * D_H];
__device__ float g_fz [N_FCG * D_H];
__device__ float g_fy [N_FCG * D_H];
__device__ float g_g  [NB * D_H];

static __device__ __forceinline__ unsigned pack_bf2(float a, float b) {
    __nv_bfloat162 h = __float22bfloat162_rn(make_float2(a, b));
    return *reinterpret_cast<unsigned*>(&h);
}
static __device__ __forceinline__ float2 unpack_bf2(unsigned u) {
    return __bfloat1622float2(*reinterpret_cast<const __nv_bfloat162*>(&u));
}

// ---------------- degree / norm (merged) --------------------------------------
__global__ void zerodeg_kernel() {
    int i = blockIdx.x * blockDim.x + threadIdx.x;
    if (i < N_CFG) g_deg[i] = 0;
    if (i < N_FCG) g_fdeg[i] = 0;
}
__global__ void deg_all_kernel(const int* __restrict__ cei, const int* __restrict__ fei) {
    int i = blockIdx.x * blockDim.x + threadIdx.x;
    if (i < E_CFG) {
        atomicAdd(&g_deg[cei[E_CFG + i]], 1);
    } else if (i < E_CFG + E_FCG) {
        atomicAdd(&g_fdeg[fei[E_FCG + (i - E_CFG)]], 1);
    }
}
__global__ void dis_all_kernel() {
    int i = blockIdx.x * blockDim.x + threadIdx.x;
    if (i < N_CFG) g_dis[i] = rsqrtf((float)g_deg[i] + 1.0f);
    else if (i < N_CFG + N_FCG) {
        int j = i - N_CFG;
        g_fdis[j] = rsqrtf((float)g_fdeg[j] + 1.0f);
    }
}
__global__ void wtobf_kernel(const float* __restrict__ W1, const float* __restrict__ W2) {
    int i = blockIdx.x * blockDim.x + threadIdx.x;
    if (i < 64 * 128) g_wb1[i] = __float2bfloat16(W1[i]);
    else if (i < 64 * 128 + 128 * 128) g_wb2[i - 64 * 128] = __float2bfloat16(W2[i - 64 * 128]);
}

// ---------------- CSR build ---------------------------------------------------
__global__ void scan_local(const int* __restrict__ cnt, int n, int* __restrict__ out,
                           int* __restrict__ bsum) {
    __shared__ int s[256];
    int base = blockIdx.x * 1024;
    int t = threadIdx.x;
    int v[4], sum = 0;
#pragma unroll
    for (int j = 0; j < 4; j++) {
        int i = base + t * 4 + j;
        v[j] = (i < n) ? cnt[i] : 0;
        sum += v[j];
    }
    s[t] = sum;
    __syncthreads();
    for (int off = 1; off < 256; off <<= 1) {
        int x = (t >= off) ? s[t - off] : 0;
        __syncthreads();
        s[t] += x;
        __syncthreads();
    }
    if (t == 255) bsum[blockIdx.x] = s[255];
    int run = (t > 0) ? s[t - 1] : 0;
#pragma unroll
    for (int j = 0; j < 4; j++) {
        int i = base + t * 4 + j;
        if (i < n) out[i] = run;
        run += v[j];
    }
}
__global__ void scan_bsum(int* __restrict__ bsum, int nb) {
    __shared__ int s[512];
    int t = threadIdx.x;
    s[t] = (t < nb) ? bsum[t] : 0;
    __syncthreads();
    for (int off = 1; off < 512; off <<= 1) {
        int x = (t >= off) ? s[t - off] : 0;
        __syncthreads();
        s[t] += x;
        __syncthreads();
    }
    if (t < nb) bsum[t] = (t > 0) ? s[t - 1] : 0;
}
__global__ void scan_add(int* __restrict__ out, const int* __restrict__ bsum, int n,
                         int* __restrict__ cursor) {
    int i = blockIdx.x * blockDim.x + threadIdx.x;
    if (i < n) {
        int v = out[i] + bsum[i >> 10];
        out[i] = v;
        cursor[i] = v;
    }
}
__global__ void fill_csr(const int* __restrict__ ei, int E, int* __restrict__ cursor,
                         int* __restrict__ csr) {
    int i = blockIdx.x * blockDim.x + threadIdx.x;
    if (i < E) {
        int r = ei[i], c = ei[E + i];
        int slot = atomicAdd(&cursor[c], 1);
        csr[slot] = r;
    }
}
__global__ void bounds_all_kernel(const int* __restrict__ n2f, const int* __restrict__ fbatch) {
    int i = blockIdx.x * blockDim.x + threadIdx.x;
    if (i <= N_FUNC) {
        int lo = 0, hi = N_CFG;
        while (lo < hi) {
            int mid = (lo + hi) >> 1;
            if (n2f[mid] < i) lo = mid + 1; else hi = mid;
        }
        g_fstart[i] = lo;
    } else {
        int f = i - (N_FUNC + 1);
        if (f <= NB) {
            int lo = 0, hi = N_FCG;
            while (lo < hi) {
                int mid = (lo + hi) >> 1;
                if (fbatch[mid] < f) lo = mid + 1; else hi = mid;
            }
            g_bstart[f] = lo;
        }
    }
}

// ---------------- cfg_x -> bf16 with dis prefolded ---------------------------
__global__ void tobf_kernel(const float2* __restrict__ x2, const float* __restrict__ dis,
                            unsigned* __restrict__ xb) {
    int i = blockIdx.x * blockDim.x + threadIdx.x;
    if (i >= N_CFG * 32) return;
    int row = i >> 5;
    float d = dis[row];
    float2 v = x2[i];
    xb[i] = pack_bf2(v.x * d, v.y * d);
}

// ---------------- WMMA bf16 GEMM ---------------------------------------------
template<int K, bool SCALE, bool OUTBF16>
__global__ __launch_bounds__(256, 2) void gemmw_kernel(
    const __nv_bfloat16* __restrict__ X, const __nv_bfloat16* __restrict__ Wb,
    const float* __restrict__ bias, const float* __restrict__ dis,
    float* __restrict__ H, __nv_bfloat16* __restrict__ HB, int N) {
    constexpr int AP = 40;
    constexpr int WP = 136;
    __shared__ __nv_bfloat16 As[128 * AP];
    __shared__ __nv_bfloat16 Ws[32 * WP];
    __shared__ float Eb[8][16 * 20];
    __shared__ float Bs[128];

    const int tid = threadIdx.x;
    const int warp = tid >> 5, lane = tid & 31;
    const int wr = warp >> 2;
    const int wc = warp & 3;
    const int row0 = blockIdx.x * 128;

    if (tid < 128) Bs[tid] = bias[tid];

    wmma::fragment<wmma::accumulator, 16, 16, 16, float> acc[4][2];
#pragma unroll
    for (int i = 0; i < 4; i++)
#pragma unroll
        for (int j = 0; j < 2; j++) wmma::fill_fragment(acc[i][j], 0.0f);

    const unsigned* Xu = (const unsigned*)X;
    const unsigned* Wu = (const unsigned*)Wb;
    unsigned* Asu = (unsigned*)As;
    unsigned* Wsu = (unsigned*)Ws;

    for (int kc = 0; kc < K; kc += 32) {
#pragma unroll
        for (int i = tid; i < 128 * 16; i += 256) {
            int r = i >> 4, k2 = i & 15;
            Asu[r * (AP / 2) + k2] = Xu[(size_t)(row0 + r) * (K / 2) + (kc >> 1) + k2];
        }
#pragma unroll
        for (int i = tid; i < 32 * 64; i += 256) {
            int k = i >> 6, c2 = i & 63;
            Wsu[k * (WP / 2) + c2] = Wu[(size_t)(kc + k) * 64 + c2];
        }
        __syncthreads();
#pragma unroll
        for (int ks = 0; ks < 32; ks += 16) {
            wmma::fragment<wmma::matrix_a, 16, 16, 16, __nv_bfloat16, wmma::row_major> af[4];
            wmma::fragment<wmma::matrix_b, 16, 16, 16, __nv_bfloat16, wmma::row_major> bf[2];
#pragma unroll
            for (int i = 0; i < 4; i++)
                wmma::load_matrix_sync(af[i], &As[(wr * 64 + i * 16) * AP + ks], AP);
#pragma unroll
            for (int j = 0; j < 2; j++)
                wmma::load_matrix_sync(bf[j], &Ws[ks * WP + wc * 32 + j * 16], WP);
#pragma unroll
            for (int i = 0; i < 4; i++)
#pragma unroll
                for (int j = 0; j < 2; j++)
                    wmma::mma_sync(acc[i][j], af[i], bf[j], acc[i][j]);
        }
        __syncthreads();
    }

    const int r = lane >> 1, c8 = (lane & 1) * 8;
#pragma unroll
    for (int i = 0; i < 4; i++) {
#pragma unroll
        for (int j = 0; j < 2; j++) {
            wmma::store_matrix_sync(&Eb[warp][0], acc[i][j], 20, wmma::mem_row_major);
            __syncwarp();
            int gr = row0 + wr * 64 + i * 16 + r;
            int gc = wc * 32 + j * 16 + c8;
            float s = SCALE ? dis[gr] : 1.0f;
            float o[8];
#pragma unroll
            for (int q = 0; q < 8; q++)
                o[q] = fmaxf(Eb[warp][r * 20 + c8 + q] + Bs[gc + q], 0.0f) * s;
            if (OUTBF16) {
                uint4 pk;
                pk.x = pack_bf2(o[0], o[1]); pk.y = pack_bf2(o[2], o[3]);
                pk.z = pack_bf2(o[4], o[5]); pk.w = pack_bf2(o[6], o[7]);
                *(uint4*)&HB[(size_t)gr * 128 + gc] = pk;
            } else {
                *(float4*)&H[(size_t)gr * 128 + gc]     = make_float4(o[0], o[1], o[2], o[3]);
                *(float4*)&H[(size_t)gr * 128 + gc + 4] = make_float4(o[4], o[5], o[6], o[7]);
            }
            __syncwarp();
        }
    }
}

// ---------------- FFMA2 GEMM (fp32, FCG) --------------------------------------
template<int K, bool SCALE>
__global__ __launch_bounds__(256, 2) void gemmx_kernel(
    const float* __restrict__ X, const float* __restrict__ W,
    const float* __restrict__ bias, const float* __restrict__ dis,
    float* __restrict__ H, int N) {
    __shared__ float Xs[32 * 132];
    __shared__ float Ws[32 * 128];
    const int row0 = blockIdx.x * 128;
    const int tx = threadIdx.x & 15;
    const int ty = threadIdx.x >> 4;
    const int c0 = tx * 8, r0 = ty * 8;

    unsigned long long acc2[8][4];
#pragma unroll
    for (int r = 0; r < 8; r++)
#pragma unroll
        for (int j = 0; j < 4; j++) acc2[r][j] = 0ULL;

    for (int kc = 0; kc < K; kc += 32) {
#pragma unroll
        for (int i = threadIdx.x; i < 128 * 32; i += 256) {
            int k = i & 31, r = i >> 5;
            int gr = row0 + r;
            Xs[k * 132 + r] = (gr < N) ? X[(size_t)gr * K + kc + k] : 0.f;
        }
#pragma unroll
        for (int i = threadIdx.x; i < 32 * 128; i += 256) {
            int c = i & 127, k = i >> 7;
            Ws[k * 128 + c] = W[(size_t)(kc + k) * 128 + c];
        }
        __syncthreads();
#pragma unroll 4
        for (int k = 0; k < 32; k++) {
            float4 al = *(const float4*)&Xs[k * 132 + r0];
            float4 ah = *(const float4*)&Xs[k * 132 + r0 + 4];
            ulonglong2 wl = *(const ulonglong2*)&Ws[k * 128 + c0];
            ulonglong2 wh = *(const ulonglong2*)&Ws[k * 128 + c0 + 4];
            unsigned long long w2[4];
            w2[0] = wl.x; w2[1] = wl.y; w2[2] = wh.x; w2[3] = wh.y;
            float a[8];
            a[0] = al.x; a[1] = al.y; a[2] = al.z; a[3] = al.w;
            a[4] = ah.x; a[5] = ah.y; a[6] = ah.z; a[7] = ah.w;
#pragma unroll
            for (int r = 0; r < 8; r++) {
                unsigned long long a2;
                asm("mov.b64 %0, {%1, %1};" : "=l"(a2) : "f"(a[r]));
#pragma unroll
                for (int j = 0; j < 4; j++)
                    asm("fma.rn.f32x2 %0, %1, %2, %0;"
                        : "+l"(acc2[r][j]) : "l"(a2), "l"(w2[j]));
            }
        }
        __syncthreads();
    }

    float bb[8];
#pragma unroll
    for (int j = 0; j < 8; j++) bb[j] = bias[c0 + j];
#pragma unroll
    for (int r = 0; r < 8; r++) {
        int gr = row0 + r0 + r;
        if (gr >= N) return;
        float s = SCALE ? dis[gr] : 1.0f;
        float o[8];
#pragma unroll
        for (int j = 0; j < 4; j++) {
            float lo, hi;
            asm("mov.b64 {%0, %1}, %2;" : "=f"(lo), "=f"(hi) : "l"(acc2[r][j]));
            o[2 * j]     = fmaxf(lo + bb[2 * j], 0.f) * s;
            o[2 * j + 1] = fmaxf(hi + bb[2 * j + 1], 0.f) * s;
        }
        *(float4*)&H[(size_t)gr * 128 + c0]     = make_float4(o[0], o[1], o[2], o[3]);
        *(float4*)&H[(size_t)gr * 128 + c0 + 4] = make_float4(o[4], o[5], o[6], o[7]);
    }
}

// ---------------- gather 64ch bf16, QUARTER-WARP per node ---------------------
// 4 nodes/warp: 8 lanes x uint4 (16B) = 128B row. Index window = 8 edges.
__global__ __launch_bounds__(256) void gather64bf_kernel(
    const int* __restrict__ rowptr, const int* __restrict__ deg,
    const int* __restrict__ csr, const uint4* __restrict__ xb,
    const float* __restrict__ dis, uint4* __restrict__ out, int n) {
    int lane = threadIdx.x & 31;
    int q = lane >> 3;                  // 0..3
    int sub = lane & 7;
    int node = ((blockIdx.x * 256 + threadIdx.x) >> 5) * 4 + q;
    if (node >= n) return;
    int start = rowptr[node], d = deg[node];
    int dm = min(d, 8);
    int uidx = (sub < dm) ? csr[start + sub] : 0;
    float a[8], b[8];
    {
        uint4 raw = xb[(size_t)node * 8 + sub];
        float2 f0 = unpack_bf2(raw.x), f1 = unpack_bf2(raw.y);
        float2 f2 = unpack_bf2(raw.z), f3 = unpack_bf2(raw.w);
        a[0] = f0.x; a[1] = f0.y; a[2] = f1.x; a[3] = f1.y;
        a[4] = f2.x; a[5] = f2.y; a[6] = f3.x; a[7] = f3.y;
    }
#pragma unroll
    for (int j = 0; j < 8; j++) b[j] = 0.f;
    int e = 0;
    for (; e + 2 <= dm; e += 2) {
        int u0 = __shfl_sync(FULLMASK, uidx, (q << 3) + e);
        int u1 = __shfl_sync(FULLMASK, uidx, (q << 3) + e + 1);
        uint4 r0 = xb[(size_t)u0 * 8 + sub];
        uint4 r1 = xb[(size_t)u1 * 8 + sub];
        float2 p0 = unpack_bf2(r0.x), p1 = unpack_bf2(r0.y);
        float2 p2 = unpack_bf2(r0.z), p3 = unpack_bf2(r0.w);
        float2 q0 = unpack_bf2(r1.x), q1 = unpack_bf2(r1.y);
        float2 q2 = unpack_bf2(r1.z), q3 = unpack_bf2(r1.w);
        a[0] += p0.x; a[1] += p0.y; a[2] += p1.x; a[3] += p1.y;
        a[4] += p2.x; a[5] += p2.y; a[6] += p3.x; a[7] += p3.y;
        b[0] += q0.x; b[1] += q0.y; b[2] += q1.x; b[3] += q1.y;
        b[4] += q2.x; b[5] += q2.y; b[6] += q3.x; b[7] += q3.y;
    }
    if (e < dm) {
        int u = __shfl_sync(FULLMASK, uidx, (q << 3) + e);
        uint4 r0 = xb[(size_t)u * 8 + sub];
        float2 p0 = unpack_bf2(r0.x), p1 = unpack_bf2(r0.y);
        float2 p2 = unpack_bf2(r0.z), p3 = unpack_bf2(r0.w);
        a[0] += p0.x; a[1] += p0.y; a[2] += p1.x; a[3] += p1.y;
        a[4] += p2.x; a[5] += p2.y; a[6] += p3.x; a[7] += p3.y;
    }
    for (e = 8; e < d; e++) {           // ~2% of nodes
        int u = csr[start + e];
        uint4 r0 = xb[(size_t)u * 8 + sub];
        float2 p0 = unpack_bf2(r0.x), p1 = unpack_bf2(r0.y);
        float2 p2 = unpack_bf2(r0.z), p3 = unpack_bf2(r0.w);
        a[0] += p0.x; a[1] += p0.y; a[2] += p1.x; a[3] += p1.y;
        a[4] += p2.x; a[5] += p2.y; a[6] += p3.x; a[7] += p3.y;
    }
    float dn = dis[node];
    uint4 pk;
    pk.x = pack_bf2((a[0] + b[0]) * dn, (a[1] + b[1]) * dn);
    pk.y = pack_bf2((a[2] + b[2]) * dn, (a[3] + b[3]) * dn);
    pk.z = pack_bf2((a[4] + b[4]) * dn, (a[5] + b[5]) * dn);
    pk.w = pack_bf2((a[6] + b[6]) * dn, (a[7] + b[7]) * dn);
    out[(size_t)node * 8 + sub] = pk;
}

// ---------------- gather 128ch bf16, QUARTER-WARP per node --------------------
// 4 nodes/warp: 8 lanes x 2x uint4 (32B) = 256B row. Index window = 8 edges.
__global__ __launch_bounds__(256) void gather128bf_kernel(
    const int* __restrict__ rowptr, const int* __restrict__ deg,
    const int* __restrict__ csr, const __nv_bfloat16* __restrict__ hb,
    const float* __restrict__ dis, uint4* __restrict__ out, int n) {
    int lane = threadIdx.x & 31;
    int q = lane >> 3;
    int sub = lane & 7;
    int node = ((blockIdx.x * 256 + threadIdx.x) >> 5) * 4 + q;
    if (node >= n) return;
    const uint4* h16 = (const uint4*)hb;   // 16 uint4 per row
    int start = rowptr[node], d = deg[node];
    int dm = min(d, 8);
    int uidx = (sub < dm) ? csr[start + sub] : 0;
    float acc[16];
    {
        uint4 r0 = h16[(size_t)node * 16 + sub];
        uint4 r1 = h16[(size_t)node * 16 + 8 + sub];
        float2 f0 = unpack_bf2(r0.x), f1 = unpack_bf2(r0.y);
        float2 f2 = unpack_bf2(r0.z), f3 = unpack_bf2(r0.w);
        float2 g0 = unpack_bf2(r1.x), g1 = unpack_bf2(r1.y);
        float2 g2 = unpack_bf2(r1.z), g3 = unpack_bf2(r1.w);
        acc[0] = f0.x;  acc[1] = f0.y;  acc[2] = f1.x;  acc[3] = f1.y;
        acc[4] = f2.x;  acc[5] = f2.y;  acc[6] = f3.x;  acc[7] = f3.y;
        acc[8] = g0.x;  acc[9] = g0.y;  acc[10] = g1.x; acc[11] = g1.y;
        acc[12] = g2.x; acc[13] = g2.y; acc[14] = g3.x; acc[15] = g3.y;
    }
    for (int e = 0; e < dm; e++) {
        int u = __shfl_sync(FULLMASK, uidx, (q << 3) + e);
        uint4 r0 = h16[(size_t)u * 16 + sub];
        uint4 r1 = h16[(size_t)u * 16 + 8 + sub];
        float2 f0 = unpack_bf2(r0.x), f1 = unpack_bf2(r0.y);
        float2 f2 = unpack_bf2(r0.z), f3 = unpack_bf2(r0.w);
        float2 g0 = unpack_bf2(r1.x), g1 = unpack_bf2(r1.y);
        float2 g2 = unpack_bf2(r1.z), g3 = unpack_bf2(r1.w);
        acc[0] += f0.x;  acc[1] += f0.y;  acc[2] += f1.x;  acc[3] += f1.y;
        acc[4] += f2.x;  acc[5] += f2.y;  acc[6] += f3.x;  acc[7] += f3.y;
        acc[8] += g0.x;  acc[9] += g0.y;  acc[10] += g1.x; acc[11] += g1.y;
        acc[12] += g2.x; acc[13] += g2.y; acc[14] += g3.x; acc[15] += g3.y;
    }
    for (int e = 8; e < d; e++) {
        int u = csr[start + e];
        uint4 r0 = h16[(size_t)u * 16 + sub];
        uint4 r1 = h16[(size_t)u * 16 + 8 + sub];
        float2 f0 = unpack_bf2(r0.x), f1 = unpack_bf2(r0.y);
        float2 f2 = unpack_bf2(r0.z), f3 = unpack_bf2(r0.w);
        float2 g0 = unpack_bf2(r1.x), g1 = unpack_bf2(r1.y);
        float2 g2 = unpack_bf2(r1.z), g3 = unpack_bf2(r1.w);
        acc[0] += f0.x;  acc[1] += f0.y;  acc[2] += f1.x;  acc[3] += f1.y;
        acc[4] += f2.x;  acc[5] += f2.y;  acc[6] += f3.x;  acc[7] += f3.y;
        acc[8] += g0.x;  acc[9] += g0.y;  acc[10] += g1.x; acc[11] += g1.y;
        acc[12] += g2.x; acc[13] += g2.y; acc[14] += g3.x; acc[15] += g3.y;
    }
    float dn = dis[node];
    uint4 pk0, pk1;
    pk0.x = pack_bf2(acc[0] * dn, acc[1] * dn);
    pk0.y = pack_bf2(acc[2] * dn, acc[3] * dn);
    pk0.z = pack_bf2(acc[4] * dn, acc[5] * dn);
    pk0.w = pack_bf2(acc[6] * dn, acc[7] * dn);
    pk1.x = pack_bf2(acc[8] * dn, acc[9] * dn);
    pk1.y = pack_bf2(acc[10] * dn, acc[11] * dn);
    pk1.z = pack_bf2(acc[12] * dn, acc[13] * dn);
    pk1.w = pack_bf2(acc[14] * dn, acc[15] * dn);
    out[(size_t)node * 16 + sub] = pk0;
    out[(size_t)node * 16 + 8 + sub] = pk1;
}

// ---------------- gather 128ch fp32 (FCG), shuffle indices -------------------
__global__ __launch_bounds__(256) void gather128_kernel(
    const int* __restrict__ rowptr, const int* __restrict__ deg,
    const int* __restrict__ csr, const float* __restrict__ hs,
    const float* __restrict__ dis, float* __restrict__ out, int n) {
    int node = (blockIdx.x * 256 + threadIdx.x) >> 5;
    int lane = threadIdx.x & 31;
    if (node >= n) return;
    const float4* hs4 = (const float4*)hs;
    int start = rowptr[node], d = deg[node];
    int dm = min(d, 32);
    int uidx = (lane < dm) ? csr[start + lane] : 0;
    float dn = dis[node];
    float4 acc = hs4[(size_t)node * 32 + lane];
    acc.x *= dn; acc.y *= dn; acc.z *= dn; acc.w *= dn;
    for (int e = 0; e < dm; e++) {
        int u = __shfl_sync(FULLMASK, uidx, e);
        float du = dis[u];
        float4 v = hs4[(size_t)u * 32 + lane];
        acc.x += v.x * du; acc.y += v.y * du;
        acc.z += v.z * du; acc.w += v.w * du;
    }
    for (int e = 32; e < d; e++) {
        int u = csr[start + e];
        float du = dis[u];
        float4 v = hs4[(size_t)u * 32 + lane];
        acc.x += v.x * du; acc.y += v.y * du;
        acc.z += v.z * du; acc.w += v.w * du;
    }
    acc.x *= dn; acc.y *= dn; acc.z *= dn; acc.w *= dn;
    ((float4*)out)[(size_t)node * 32 + lane] = acc;
}

// ---------------- function-level mean pool (bf16 input) -----------------------
__global__ __launch_bounds__(256) void poolsegbf_kernel(
    const __nv_bfloat16* __restrict__ x, const int* __restrict__ start,
    float* __restrict__ pool, int nseg) {
    int f = (blockIdx.x * 256 + threadIdx.x) >> 5;
    int lane = threadIdx.x & 31;
    if (f >= nseg) return;
    int s = start[f], e = start[f + 1];
    const uint2* x8 = (const uint2*)x;
    float a0 = 0.f, a1 = 0.f, a2 = 0.f, a3 = 0.f;
    for (int i = s; i < e; i++) {
        uint2 raw = x8[(size_t)i * 32 + lane];
        float2 f0 = unpack_bf2(raw.x), f1 = unpack_bf2(raw.y);
        a0 += f0.x; a1 += f0.y; a2 += f1.x; a3 += f1.y;
    }
    float inv = 1.0f / (float)max(e - s, 1);
    ((float4*)pool)[(size_t)f * 32 + lane] = make_float4(a0 * inv, a1 * inv, a2 * inv, a3 * inv);
}

__global__ void assemble_kernel(const float* __restrict__ pool, const float* __restrict__ emb,
                                const int* __restrict__ src, const int* __restrict__ isext,
                                float* __restrict__ fx) {
    int i = blockIdx.x * blockDim.x + threadIdx.x;
    if (i >= N_FCG * D_H) return;
    int row = i >> 7, j = i & 127;
    int s = src[row];
    float v;
    if (isext[row] == 1) {
        int k = min(max(s, 0), VOCAB - 1);
        v = emb[(size_t)k * D_H + j];
    } else {
        int k = min(max(s, 0), N_FUNC - 1);
        v = pool[(size_t)k * D_H + j];
    }
    fx[i] = v;
}

__global__ __launch_bounds__(128) void gpool_kernel(
    const float* __restrict__ y, const int* __restrict__ start, float* __restrict__ g) {
    int b = blockIdx.x, col = threadIdx.x;
    int s = start[b], e = start[b + 1];
    float acc = 0.f;
    for (int i = s; i < e; i++) acc += y[(size_t)i * 128 + col];
    g[b * 128 + col] = acc / (float)max(e - s, 1);
}

__global__ __launch_bounds__(256) void head_kernel(
    const float* __restrict__ g,
    const float* __restrict__ Wp1, const float* __restrict__ bp1,
    const float* __restrict__ Wp2, const float* __restrict__ bp2,
    const float* __restrict__ Wp3, const float* __restrict__ bp3,
    float* __restrict__ out) {
    __shared__ float G[NB * 128], H1[NB * 64], H2[NB * 32];
    int t = threadIdx.x;
    for (int i = t; i < NB * 128; i += 256) G[i] = g[i];
    __syncthreads();
    for (int i = t; i < NB * 64; i += 256) {
        int r = i >> 6, c = i & 63;
        float a = bp1[c];
        for (int k = 0; k < 128; k++) a += G[r * 128 + k] * Wp1[k * 64 + c];
        H1[i] = fmaxf(a, 0.f);
    }
    __syncthreads();
    for (int i = t; i < NB * 32; i += 256) {
        int r = i >> 5, c = i & 31;
        float a = bp2[c];
        for (int k = 0; k < 64; k++) a += H1[r * 64 + k] * Wp2[k * 32 + c];
        H2[i] = fmaxf(a, 0.f);
    }
    __syncthreads();
    if (t < NB) {
        float a = bp3[0];
        for (int k = 0; k < 32; k++) a += H2[t * 32 + k] * Wp3[k];
        out[t] = 1.0f / (1.0f + expf(-a));
    }
}

// ---------------- launch ----------------------------------------------------
extern "C" void kernel_launch(void* const* d_in, const int* in_sizes, int n_in,
                              void* d_out, int out_size) {
    const float* cfg_x  = (const float*)d_in[0];
    const int*   cfg_ei = (const int*)  d_in[1];
    const int*   n2f    = (const int*)  d_in[2];
    const int*   fcg_ei = (const int*)  d_in[3];
    const int*   fbatch = (const int*)  d_in[4];
    const int*   fsrc   = (const int*)  d_in[5];
    const int*   fext   = (const int*)  d_in[6];
    const float* W1  = (const float*)d_in[7];
    const float* b1  = (const float*)d_in[8];
    const float* W2  = (const float*)d_in[9];
    const float* b2  = (const float*)d_in[10];
    const float* emb = (const float*)d_in[11];
    const float* Wf  = (const float*)d_in[12];
    const float* bf  = (const float*)d_in[13];
    const float* Wp1 = (const float*)d_in[14];
    const float* bp1 = (const float*)d_in[15];
    const float* Wp2 = (const float*)d_in[16];
    const float* bp2 = (const float*)d_in[17];
    const float* Wp3 = (const float*)d_in[18];
    const float* bp3 = (const float*)d_in[19];
    float* out = (float*)d_out;

    void *p;
    cudaGetSymbolAddress(&p, g_a);       float* A      = (float*)p;
    cudaGetSymbolAddress(&p, g_b);       float* Bb     = (float*)p;
    cudaGetSymbolAddress(&p, g_hb);      __nv_bfloat16* HB = (__nv_bfloat16*)p;
    cudaGetSymbolAddress(&p, g_wb1);     __nv_bfloat16* Wb1 = (__nv_bfloat16*)p;
    cudaGetSymbolAddress(&p, g_wb2);     __nv_bfloat16* Wb2 = (__nv_bfloat16*)p;
    cudaGetSymbolAddress(&p, g_deg);     int*   deg    = (int*)p;
    cudaGetSymbolAddress(&p, g_dis);     float* dis    = (float*)p;
    cudaGetSymbolAddress(&p, g_rowptr);  int*   rowptr = (int*)p;
    cudaGetSymbolAddress(&p, g_cursor);  int*   cursor = (int*)p;
    cudaGetSymbolAddress(&p, g_csr);     int*   csr    = (int*)p;
    cudaGetSymbolAddress(&p, g_fdeg);    int*   fdeg   = (int*)p;
    cudaGetSymbolAddress(&p, g_fdis);    float* fdis   = (float*)p;
    cudaGetSymbolAddress(&p, g_frowptr); int*   frowptr= (int*)p;
    cudaGetSymbolAddress(&p, g_fcursor); int*   fcursor= (int*)p;
    cudaGetSymbolAddress(&p, g_fcsr);    int*   fcsr   = (int*)p;
    cudaGetSymbolAddress(&p, g_bsum);    int*   bsum   = (int*)p;
    cudaGetSymbolAddress(&p, g_fstart);  int*   fstart = (int*)p;
    cudaGetSymbolAddress(&p, g_bstart);  int*   bstart = (int*)p;
    cudaGetSymbolAddress(&p, g_pool);    float* pool   = (float*)p;
    cudaGetSymbolAddress(&p, g_fx);      float* fx     = (float*)p;
    cudaGetSymbolAddress(&p, g_fz);      float* fz     = (float*)p;
    cudaGetSymbolAddress(&p, g_fy);      float* fy     = (float*)p;
    cudaGetSymbolAddress(&p, g_g);       float* gg     = (float*)p;

    unsigned* xb  = (unsigned*)Bb;
    unsigned* z1b = (unsigned*)Bb + (size_t)N_CFG * 32;
    uint4*    z2b = (uint4*)Bb;

    zerodeg_kernel<<<(N_CFG + 255) / 256, 256>>>();
    deg_all_kernel<<<(E_CFG + E_FCG + 255) / 256, 256>>>(cfg_ei, fcg_ei);
    dis_all_kernel<<<(N_CFG + N_FCG + 255) / 256, 256>>>();
    wtobf_kernel<<<(64 * 128 + 128 * 128 + 255) / 256, 256>>>(W1, W2);

    const int NBLK_CFG = (N_CFG + 1023) / 1024;
    scan_local<<<NBLK_CFG, 256>>>(deg, N_CFG, rowptr, bsum);
    scan_bsum<<<1, 512>>>(bsum, NBLK_CFG);
    scan_add<<<(N_CFG + 255) / 256, 256>>>(rowptr, bsum, N_CFG, cursor);
    fill_csr<<<(E_CFG + 255) / 256, 256>>>(cfg_ei, E_CFG, cursor, csr);

    const int NBLK_FCG = (N_FCG + 1023) / 1024;
    scan_local<<<NBLK_FCG, 256>>>(fdeg, N_FCG, frowptr, bsum);
    scan_bsum<<<1, 512>>>(bsum, NBLK_FCG);
    scan_add<<<(N_FCG + 255) / 256, 256>>>(frowptr, bsum, N_FCG, fcursor);
    fill_csr<<<(E_FCG + 255) / 256, 256>>>(fcg_ei, E_FCG, fcursor, fcsr);

    bounds_all_kernel<<<(N_FUNC + NB + 2 + 255) / 256, 256>>>(n2f, fbatch);

    // CFG layer 1 (quarter-warp gathers: 32 nodes per 256-thread block)
    tobf_kernel<<<(N_CFG * 32 + 255) / 256, 256>>>((const float2*)cfg_x, dis, xb);
    gather64bf_kernel<<<(N_CFG + 31) / 32, 256>>>(rowptr, deg, csr,
                                                  (const uint4*)xb, dis, (uint4*)z1b, N_CFG);
    gemmw_kernel<64, true, true><<<N_CFG / 128, 256>>>(
        (const __nv_bfloat16*)z1b, Wb1, b1, dis, nullptr, HB, N_CFG);

    // CFG layer 2
    gather128bf_kernel<<<(N_CFG + 31) / 32, 256>>>(rowptr, deg, csr, HB, dis, z2b, N_CFG);
    gemmw_kernel<128, false, true><<<N_CFG / 128, 256>>>(
        (const __nv_bfloat16*)z2b, Wb2, b2, dis, nullptr, HB, N_CFG);

    // function-level mean pool (bf16 input)
    poolsegbf_kernel<<<(N_FUNC * 32 + 255) / 256, 256>>>(HB, fstart, pool, N_FUNC);

    // FCG features + FCG layer (fp32)
    assemble_kernel<<<(N_FCG * D_H) / 256, 256>>>(pool, emb, fsrc, fext, fx);
    gather128_kernel<<<(N_FCG * 32 + 255) / 256, 256>>>(frowptr, fdeg, fcsr, fx, fdis, fz, N_FCG);
    gemmx_kernel<128, false><<<(N_FCG + 127) / 128, 256>>>(fz, Wf, bf, fdis, fy, N_FCG);

    // binary-level mean pool + head
    gpool_kernel<<<NB, 128>>>(fy, bstart, gg);
    head_kernel<<<1, 256>>>(gg, Wp1, bp1, Wp2, bp2, Wp3, bp3, out);
}

// round 12
// speedup vs baseline: 2.1916x; 1.0918x over previous
#include <cuda_runtime.h>
#include <cuda_bf16.h>
#include <mma.h>
#include <math.h>

using namespace nvcuda;

#define N_CFG 400000
#define E_CFG 1600000
#define N_FUNC 8000
#define N_FCG 9600
#define E_FCG 80000
#define NB 8
#define D_H 128
#define VOCAB 10002
#define FULLMASK 0xffffffffu

// ---------------- scratch (device globals) ----------------------------------
__device__ float g_a [(size_t)N_CFG * D_H];
__device__ float g_b [(size_t)N_CFG * D_H];
__device__ __nv_bfloat16 g_hb[(size_t)N_CFG * D_H];
__device__ __nv_bfloat16 g_wb1[64 * 128];
__device__ __nv_bfloat16 g_wb2[128 * 128];
__device__ int   g_deg[N_CFG];
__device__ float g_dis[N_CFG];
__device__ int   g_rowptr[N_CFG];
__device__ int   g_cursor[N_CFG];
__device__ int   g_csr[E_CFG];
__device__ int   g_fdeg[N_FCG];
__device__ float g_fdis[N_FCG];
__device__ int   g_frowptr[N_FCG];
__device__ int   g_fcursor[N_FCG];
__device__ int   g_fcsr[E_FCG];
__device__ int   g_bsum[512];          // [0..399]=CFG blocks, [400..]=FCG blocks
__device__ int   g_fstart[N_FUNC + 1];
__device__ int   g_bstart[NB + 1];
__device__ float g_pool[N_FUNC * D_H];
__device__ float g_fx [N_FCG * D_H];
__device__ float g_fz [N_FCG * D_H];
__device__ float g_fy [N_FCG * D_H];
__device__ float g_g  [NB * D_H];

#define NBLK_CFG ((N_CFG + 1023) / 1024)   // 391
#define NBLK_FCG ((N_FCG + 1023) / 1024)   // 10
#define FBSUM 400

static __device__ __forceinline__ unsigned pack_bf2(float a, float b) {
    __nv_bfloat162 h = __float22bfloat162_rn(make_float2(a, b));
    return *reinterpret_cast<unsigned*>(&h);
}
static __device__ __forceinline__ float2 unpack_bf2(unsigned u) {
    return __bfloat1622float2(*reinterpret_cast<const __nv_bfloat162*>(&u));
}

// ---------------- init: zero degs + weight->bf16 ------------------------------
__global__ void init_kernel(const float* __restrict__ W1, const float* __restrict__ W2) {
    int i = blockIdx.x * blockDim.x + threadIdx.x;
    if (i < N_CFG) g_deg[i] = 0;
    if (i < N_FCG) g_fdeg[i] = 0;
    if (i < 64 * 128) g_wb1[i] = __float2bfloat16(W1[i]);
    if (i >= 64 * 128 && i < 64 * 128 + 128 * 128)
        g_wb2[i - 64 * 128] = __float2bfloat16(W2[i - 64 * 128]);
}
__global__ void deg_all_kernel(const int* __restrict__ cei, const int* __restrict__ fei) {
    int i = blockIdx.x * blockDim.x + threadIdx.x;
    if (i < E_CFG) {
        atomicAdd(&g_deg[cei[E_CFG + i]], 1);
    } else if (i < E_CFG + E_FCG) {
        atomicAdd(&g_fdeg[fei[E_FCG + (i - E_CFG)]], 1);
    }
}
__global__ void dis_all_kernel() {
    int i = blockIdx.x * blockDim.x + threadIdx.x;
    if (i < N_CFG) g_dis[i] = rsqrtf((float)g_deg[i] + 1.0f);
    else if (i < N_CFG + N_FCG) {
        int j = i - N_CFG;
        g_fdis[j] = rsqrtf((float)g_fdeg[j] + 1.0f);
    }
}

// ---------------- CSR build (CFG+FCG merged per stage) ------------------------
__device__ __forceinline__ void scan_local_body(const int* cnt, int n, int* out,
                                                int* bsum, int blk, int t) {
    __shared__ int s[256];
    int base = blk * 1024;
    int v[4], sum = 0;
#pragma unroll
    for (int j = 0; j < 4; j++) {
        int i = base + t * 4 + j;
        v[j] = (i < n) ? cnt[i] : 0;
        sum += v[j];
    }
    s[t] = sum;
    __syncthreads();
    for (int off = 1; off < 256; off <<= 1) {
        int x = (t >= off) ? s[t - off] : 0;
        __syncthreads();
        s[t] += x;
        __syncthreads();
    }
    if (t == 255) bsum[blk] = s[255];
    int run = (t > 0) ? s[t - 1] : 0;
#pragma unroll
    for (int j = 0; j < 4; j++) {
        int i = base + t * 4 + j;
        if (i < n) out[i] = run;
        run += v[j];
    }
}
__global__ void scan_local_all() {
    if (blockIdx.x < NBLK_CFG)
        scan_local_body(g_deg, N_CFG, g_rowptr, g_bsum, blockIdx.x, threadIdx.x);
    else
        scan_local_body(g_fdeg, N_FCG, g_frowptr, g_bsum + FBSUM,
                        blockIdx.x - NBLK_CFG, threadIdx.x);
}
__global__ void scan_bsum_all() {
    __shared__ int s[512];
    int* bsum = (blockIdx.x == 0) ? g_bsum : g_bsum + FBSUM;
    int nb = (blockIdx.x == 0) ? NBLK_CFG : NBLK_FCG;
    int t = threadIdx.x;
    s[t] = (t < nb) ? bsum[t] : 0;
    __syncthreads();
    for (int off = 1; off < 512; off <<= 1) {
        int x = (t >= off) ? s[t - off] : 0;
        __syncthreads();
        s[t] += x;
        __syncthreads();
    }
    if (t < nb) bsum[t] = (t > 0) ? s[t - 1] : 0;
}
__global__ void scan_add_all() {
    int i = blockIdx.x * blockDim.x + threadIdx.x;
    if (i < N_CFG) {
        int v = g_rowptr[i] + g_bsum[i >> 10];
        g_rowptr[i] = v;
        g_cursor[i] = v;
    } else if (i < N_CFG + N_FCG) {
        int j = i - N_CFG;
        int v = g_frowptr[j] + g_bsum[FBSUM + (j >> 10)];
        g_frowptr[j] = v;
        g_fcursor[j] = v;
    }
}
__global__ void fill_csr_all(const int* __restrict__ cei, const int* __restrict__ fei) {
    int i = blockIdx.x * blockDim.x + threadIdx.x;
    if (i < E_CFG) {
        int r = cei[i], c = cei[E_CFG + i];
        int slot = atomicAdd(&g_cursor[c], 1);
        g_csr[slot] = r;
    } else if (i < E_CFG + E_FCG) {
        int j = i - E_CFG;
        int r = fei[j], c = fei[E_FCG + j];
        int slot = atomicAdd(&g_fcursor[c], 1);
        g_fcsr[slot] = r;
    }
}
__global__ void bounds_all_kernel(const int* __restrict__ n2f, const int* __restrict__ fbatch) {
    int i = blockIdx.x * blockDim.x + threadIdx.x;
    if (i <= N_FUNC) {
        int lo = 0, hi = N_CFG;
        while (lo < hi) {
            int mid = (lo + hi) >> 1;
            if (n2f[mid] < i) lo = mid + 1; else hi = mid;
        }
        g_fstart[i] = lo;
    } else {
        int f = i - (N_FUNC + 1);
        if (f <= NB) {
            int lo = 0, hi = N_FCG;
            while (lo < hi) {
                int mid = (lo + hi) >> 1;
                if (fbatch[mid] < f) lo = mid + 1; else hi = mid;
            }
            g_bstart[f] = lo;
        }
    }
}

// ---------------- cfg_x -> bf16 with dis prefolded ---------------------------
__global__ void tobf_kernel(const float2* __restrict__ x2, const float* __restrict__ dis,
                            unsigned* __restrict__ xb) {
    int i = blockIdx.x * blockDim.x + threadIdx.x;
    if (i >= N_CFG * 32) return;
    int row = i >> 5;
    float d = dis[row];
    float2 v = x2[i];
    xb[i] = pack_bf2(v.x * d, v.y * d);
}

// ---------------- WMMA bf16 GEMM ---------------------------------------------
template<int K, bool SCALE, bool OUTBF16>
__global__ __launch_bounds__(256, 2) void gemmw_kernel(
    const __nv_bfloat16* __restrict__ X, const __nv_bfloat16* __restrict__ Wb,
    const float* __restrict__ bias, const float* __restrict__ dis,
    float* __restrict__ H, __nv_bfloat16* __restrict__ HB, int N) {
    constexpr int AP = 40;
    constexpr int WP = 136;
    __shared__ __nv_bfloat16 As[128 * AP];
    __shared__ __nv_bfloat16 Ws[32 * WP];
    __shared__ float Eb[8][16 * 20];
    __shared__ float Bs[128];

    const int tid = threadIdx.x;
    const int warp = tid >> 5, lane = tid & 31;
    const int wr = warp >> 2;
    const int wc = warp & 3;
    const int row0 = blockIdx.x * 128;

    if (tid < 128) Bs[tid] = bias[tid];

    wmma::fragment<wmma::accumulator, 16, 16, 16, float> acc[4][2];
#pragma unroll
    for (int i = 0; i < 4; i++)
#pragma unroll
        for (int j = 0; j < 2; j++) wmma::fill_fragment(acc[i][j], 0.0f);

    const unsigned* Xu = (const unsigned*)X;
    const unsigned* Wu = (const unsigned*)Wb;
    unsigned* Asu = (unsigned*)As;
    unsigned* Wsu = (unsigned*)Ws;

    for (int kc = 0; kc < K; kc += 32) {
#pragma unroll
        for (int i = tid; i < 128 * 16; i += 256) {
            int r = i >> 4, k2 = i & 15;
            Asu[r * (AP / 2) + k2] = Xu[(size_t)(row0 + r) * (K / 2) + (kc >> 1) + k2];
        }
#pragma unroll
        for (int i = tid; i < 32 * 64; i += 256) {
            int k = i >> 6, c2 = i & 63;
            Wsu[k * (WP / 2) + c2] = Wu[(size_t)(kc + k) * 64 + c2];
        }
        __syncthreads();
#pragma unroll
        for (int ks = 0; ks < 32; ks += 16) {
            wmma::fragment<wmma::matrix_a, 16, 16, 16, __nv_bfloat16, wmma::row_major> af[4];
            wmma::fragment<wmma::matrix_b, 16, 16, 16, __nv_bfloat16, wmma::row_major> bf[2];
#pragma unroll
            for (int i = 0; i < 4; i++)
                wmma::load_matrix_sync(af[i], &As[(wr * 64 + i * 16) * AP + ks], AP);
#pragma unroll
            for (int j = 0; j < 2; j++)
                wmma::load_matrix_sync(bf[j], &Ws[ks * WP + wc * 32 + j * 16], WP);
#pragma unroll
            for (int i = 0; i < 4; i++)
#pragma unroll
                for (int j = 0; j < 2; j++)
                    wmma::mma_sync(acc[i][j], af[i], bf[j], acc[i][j]);
        }
        __syncthreads();
    }

    const int r = lane >> 1, c8 = (lane & 1) * 8;
#pragma unroll
    for (int i = 0; i < 4; i++) {
#pragma unroll
        for (int j = 0; j < 2; j++) {
            wmma::store_matrix_sync(&Eb[warp][0], acc[i][j], 20, wmma::mem_row_major);
            __syncwarp();
            int gr = row0 + wr * 64 + i * 16 + r;
            int gc = wc * 32 + j * 16 + c8;
            float s = SCALE ? dis[gr] : 1.0f;
            float o[8];
#pragma unroll
            for (int q = 0; q < 8; q++)
                o[q] = fmaxf(Eb[warp][r * 20 + c8 + q] + Bs[gc + q], 0.0f) * s;
            if (OUTBF16) {
                uint4 pk;
                pk.x = pack_bf2(o[0], o[1]); pk.y = pack_bf2(o[2], o[3]);
                pk.z = pack_bf2(o[4], o[5]); pk.w = pack_bf2(o[6], o[7]);
                *(uint4*)&HB[(size_t)gr * 128 + gc] = pk;
            } else {
                *(float4*)&H[(size_t)gr * 128 + gc]     = make_float4(o[0], o[1], o[2], o[3]);
                *(float4*)&H[(size_t)gr * 128 + gc + 4] = make_float4(o[4], o[5], o[6], o[7]);
            }
            __syncwarp();
        }
    }
}

// ---------------- FFMA2 GEMM (fp32, FCG) --------------------------------------
template<int K, bool SCALE>
__global__ __launch_bounds__(256, 2) void gemmx_kernel(
    const float* __restrict__ X, const float* __restrict__ W,
    const float* __restrict__ bias, const float* __restrict__ dis,
    float* __restrict__ H, int N) {
    __shared__ float Xs[32 * 132];
    __shared__ float Ws[32 * 128];
    const int row0 = blockIdx.x * 128;
    const int tx = threadIdx.x & 15;
    const int ty = threadIdx.x >> 4;
    const int c0 = tx * 8, r0 = ty * 8;

    unsigned long long acc2[8][4];
#pragma unroll
    for (int r = 0; r < 8; r++)
#pragma unroll
        for (int j = 0; j < 4; j++) acc2[r][j] = 0ULL;

    for (int kc = 0; kc < K; kc += 32) {
#pragma unroll
        for (int i = threadIdx.x; i < 128 * 32; i += 256) {
            int k = i & 31, r = i >> 5;
            int gr = row0 + r;
            Xs[k * 132 + r] = (gr < N) ? X[(size_t)gr * K + kc + k] : 0.f;
        }
#pragma unroll
        for (int i = threadIdx.x; i < 32 * 128; i += 256) {
            int c = i & 127, k = i >> 7;
            Ws[k * 128 + c] = W[(size_t)(kc + k) * 128 + c];
        }
        __syncthreads();
#pragma unroll 4
        for (int k = 0; k < 32; k++) {
            float4 al = *(const float4*)&Xs[k * 132 + r0];
            float4 ah = *(const float4*)&Xs[k * 132 + r0 + 4];
            ulonglong2 wl = *(const ulonglong2*)&Ws[k * 128 + c0];
            ulonglong2 wh = *(const ulonglong2*)&Ws[k * 128 + c0 + 4];
            unsigned long long w2[4];
            w2[0] = wl.x; w2[1] = wl.y; w2[2] = wh.x; w2[3] = wh.y;
            float a[8];
            a[0] = al.x; a[1] = al.y; a[2] = al.z; a[3] = al.w;
            a[4] = ah.x; a[5] = ah.y; a[6] = ah.z; a[7] = ah.w;
#pragma unroll
            for (int r = 0; r < 8; r++) {
                unsigned long long a2;
                asm("mov.b64 %0, {%1, %1};" : "=l"(a2) : "f"(a[r]));
#pragma unroll
                for (int j = 0; j < 4; j++)
                    asm("fma.rn.f32x2 %0, %1, %2, %0;"
                        : "+l"(acc2[r][j]) : "l"(a2), "l"(w2[j]));
            }
        }
        __syncthreads();
    }

    float bb[8];
#pragma unroll
    for (int j = 0; j < 8; j++) bb[j] = bias[c0 + j];
#pragma unroll
    for (int r = 0; r < 8; r++) {
        int gr = row0 + r0 + r;
        if (gr >= N) return;
        float s = SCALE ? dis[gr] : 1.0f;
        float o[8];
#pragma unroll
        for (int j = 0; j < 4; j++) {
            float lo, hi;
            asm("mov.b64 {%0, %1}, %2;" : "=f"(lo), "=f"(hi) : "l"(acc2[r][j]));
            o[2 * j]     = fmaxf(lo + bb[2 * j], 0.f) * s;
            o[2 * j + 1] = fmaxf(hi + bb[2 * j + 1], 0.f) * s;
        }
        *(float4*)&H[(size_t)gr * 128 + c0]     = make_float4(o[0], o[1], o[2], o[3]);
        *(float4*)&H[(size_t)gr * 128 + c0 + 4] = make_float4(o[4], o[5], o[6], o[7]);
    }
}

// ---------------- gather 64ch bf16, quarter-warp, FULLY UNROLLED --------------
__global__ __launch_bounds__(256) void gather64bf_kernel(
    const int* __restrict__ rowptr, const int* __restrict__ deg,
    const int* __restrict__ csr, const uint4* __restrict__ xb,
    const float* __restrict__ dis, uint4* __restrict__ out, int n) {
    int lane = threadIdx.x & 31;
    int q = lane >> 3;
    int sub = lane & 7;
    int node = ((blockIdx.x * 256 + threadIdx.x) >> 5) * 4 + q;
    if (node >= n) return;
    int start = rowptr[node], d = deg[node];
    int dm = min(d, 8);
    int uidx = (sub < dm) ? csr[start + sub] : 0;
    int u[8];
#pragma unroll
    for (int j = 0; j < 8; j++) u[j] = __shfl_sync(FULLMASK, uidx, (q << 3) + j);
    float a[8];
    {
        uint4 raw = xb[(size_t)node * 8 + sub];
        float2 f0 = unpack_bf2(raw.x), f1 = unpack_bf2(raw.y);
        float2 f2 = unpack_bf2(raw.z), f3 = unpack_bf2(raw.w);
        a[0] = f0.x; a[1] = f0.y; a[2] = f1.x; a[3] = f1.y;
        a[4] = f2.x; a[5] = f2.y; a[6] = f3.x; a[7] = f3.y;
    }
#pragma unroll
    for (int j = 0; j < 8; j++) {
        if (j < dm) {
            uint4 r0 = xb[(size_t)u[j] * 8 + sub];
            float2 p0 = unpack_bf2(r0.x), p1 = unpack_bf2(r0.y);
            float2 p2 = unpack_bf2(r0.z), p3 = unpack_bf2(r0.w);
            a[0] += p0.x; a[1] += p0.y; a[2] += p1.x; a[3] += p1.y;
            a[4] += p2.x; a[5] += p2.y; a[6] += p3.x; a[7] += p3.y;
        }
    }
    for (int e = 8; e < d; e++) {       // ~2% of nodes
        int uu = csr[start + e];
        uint4 r0 = xb[(size_t)uu * 8 + sub];
        float2 p0 = unpack_bf2(r0.x), p1 = unpack_bf2(r0.y);
        float2 p2 = unpack_bf2(r0.z), p3 = unpack_bf2(r0.w);
        a[0] += p0.x; a[1] += p0.y; a[2] += p1.x; a[3] += p1.y;
        a[4] += p2.x; a[5] += p2.y; a[6] += p3.x; a[7] += p3.y;
    }
    float dn = dis[node];
    uint4 pk;
    pk.x = pack_bf2(a[0] * dn, a[1] * dn);
    pk.y = pack_bf2(a[2] * dn, a[3] * dn);
    pk.z = pack_bf2(a[4] * dn, a[5] * dn);
    pk.w = pack_bf2(a[6] * dn, a[7] * dn);
    out[(size_t)node * 8 + sub] = pk;
}

// ---------------- gather 128ch bf16, quarter-warp, FULLY UNROLLED -------------
__global__ __launch_bounds__(256) void gather128bf_kernel(
    const int* __restrict__ rowptr, const int* __restrict__ deg,
    const int* __restrict__ csr, const __nv_bfloat16* __restrict__ hb,
    const float* __restrict__ dis, uint4* __restrict__ out, int n) {
    int lane = threadIdx.x & 31;
    int q = lane >> 3;
    int sub = lane & 7;
    int node = ((blockIdx.x * 256 + threadIdx.x) >> 5) * 4 + q;
    if (node >= n) return;
    const uint4* h16 = (const uint4*)hb;
    int start = rowptr[node], d = deg[node];
    int dm = min(d, 8);
    int uidx = (sub < dm) ? csr[start + sub] : 0;
    int u[8];
#pragma unroll
    for (int j = 0; j < 8; j++) u[j] = __shfl_sync(FULLMASK, uidx, (q << 3) + j);
    float acc[16];
    {
        uint4 r0 = h16[(size_t)node * 16 + sub];
        uint4 r1 = h16[(size_t)node * 16 + 8 + sub];
        float2 f0 = unpack_bf2(r0.x), f1 = unpack_bf2(r0.y);
        float2 f2 = unpack_bf2(r0.z), f3 = unpack_bf2(r0.w);
        float2 g0 = unpack_bf2(r1.x), g1 = unpack_bf2(r1.y);
        float2 g2 = unpack_bf2(r1.z), g3 = unpack_bf2(r1.w);
        acc[0] = f0.x;  acc[1] = f0.y;  acc[2] = f1.x;  acc[3] = f1.y;
        acc[4] = f2.x;  acc[5] = f2.y;  acc[6] = f3.x;  acc[7] = f3.y;
        acc[8] = g0.x;  acc[9] = g0.y;  acc[10] = g1.x; acc[11] = g1.y;
        acc[12] = g2.x; acc[13] = g2.y; acc[14] = g3.x; acc[15] = g3.y;
    }
#pragma unroll
    for (int j = 0; j < 8; j++) {
        if (j < dm) {
            uint4 r0 = h16[(size_t)u[j] * 16 + sub];
            uint4 r1 = h16[(size_t)u[j] * 16 + 8 + sub];
            float2 f0 = unpack_bf2(r0.x), f1 = unpack_bf2(r0.y);
            float2 f2 = unpack_bf2(r0.z), f3 = unpack_bf2(r0.w);
            float2 g0 = unpack_bf2(r1.x), g1 = unpack_bf2(r1.y);
            float2 g2 = unpack_bf2(r1.z), g3 = unpack_bf2(r1.w);
            acc[0] += f0.x;  acc[1] += f0.y;  acc[2] += f1.x;  acc[3] += f1.y;
            acc[4] += f2.x;  acc[5] += f2.y;  acc[6] += f3.x;  acc[7] += f3.y;
            acc[8] += g0.x;  acc[9] += g0.y;  acc[10] += g1.x; acc[11] += g1.y;
            acc[12] += g2.x; acc[13] += g2.y; acc[14] += g3.x; acc[15] += g3.y;
        }
    }
    for (int e = 8; e < d; e++) {
        int uu = csr[start + e];
        uint4 r0 = h16[(size_t)uu * 16 + sub];
        uint4 r1 = h16[(size_t)uu * 16 + 8 + sub];
        float2 f0 = unpack_bf2(r0.x), f1 = unpack_bf2(r0.y);
        float2 f2 = unpack_bf2(r0.z), f3 = unpack_bf2(r0.w);
        float2 g0 = unpack_bf2(r1.x), g1 = unpack_bf2(r1.y);
        float2 g2 = unpack_bf2(r1.z), g3 = unpack_bf2(r1.w);
        acc[0] += f0.x;  acc[1] += f0.y;  acc[2] += f1.x;  acc[3] += f1.y;
        acc[4] += f2.x;  acc[5] += f2.y;  acc[6] += f3.x;  acc[7] += f3.y;
        acc[8] += g0.x;  acc[9] += g0.y;  acc[10] += g1.x; acc[11] += g1.y;
        acc[12] += g2.x; acc[13] += g2.y; acc[14] += g3.x; acc[15] += g3.y;
    }
    float dn = dis[node];
    uint4 pk0, pk1;
    pk0.x = pack_bf2(acc[0] * dn, acc[1] * dn);
    pk0.y = pack_bf2(acc[2] * dn, acc[3] * dn);
    pk0.z = pack_bf2(acc[4] * dn, acc[5] * dn);
    pk0.w = pack_bf2(acc[6] * dn, acc[7] * dn);
    pk1.x = pack_bf2(acc[8] * dn, acc[9] * dn);
    pk1.y = pack_bf2(acc[10] * dn, acc[11] * dn);
    pk1.z = pack_bf2(acc[12] * dn, acc[13] * dn);
    pk1.w = pack_bf2(acc[14] * dn, acc[15] * dn);
    out[(size_t)node * 16 + sub] = pk0;
    out[(size_t)node * 16 + 8 + sub] = pk1;
}

// ---------------- gather 128ch fp32 (FCG), shuffle indices -------------------
__global__ __launch_bounds__(256) void gather128_kernel(
    const int* __restrict__ rowptr, const int* __restrict__ deg,
    const int* __restrict__ csr, const float* __restrict__ hs,
    const float* __restrict__ dis, float* __restrict__ out, int n) {
    int node = (blockIdx.x * 256 + threadIdx.x) >> 5;
    int lane = threadIdx.x & 31;
    if (node >= n) return;
    const float4* hs4 = (const float4*)hs;
    int start = rowptr[node], d = deg[node];
    int dm = min(d, 32);
    int uidx = (lane < dm) ? csr[start + lane] : 0;
    float dn = dis[node];
    float4 acc = hs4[(size_t)node * 32 + lane];
    acc.x *= dn; acc.y *= dn; acc.z *= dn; acc.w *= dn;
    for (int e = 0; e < dm; e++) {
        int u = __shfl_sync(FULLMASK, uidx, e);
        float du = dis[u];
        float4 v = hs4[(size_t)u * 32 + lane];
        acc.x += v.x * du; acc.y += v.y * du;
        acc.z += v.z * du; acc.w += v.w * du;
    }
    for (int e = 32; e < d; e++) {
        int u = csr[start + e];
        float du = dis[u];
        float4 v = hs4[(size_t)u * 32 + lane];
        acc.x += v.x * du; acc.y += v.y * du;
        acc.z += v.z * du; acc.w += v.w * du;
    }
    acc.x *= dn; acc.y *= dn; acc.z *= dn; acc.w *= dn;
    ((float4*)out)[(size_t)node * 32 + lane] = acc;
}

// ---------------- function-level mean pool (bf16 input) -----------------------
__global__ __launch_bounds__(256) void poolsegbf_kernel(
    const __nv_bfloat16* __restrict__ x, const int* __restrict__ start,
    float* __restrict__ pool, int nseg) {
    int f = (blockIdx.x * 256 + threadIdx.x) >> 5;
    int lane = threadIdx.x & 31;
    if (f >= nseg) return;
    int s = start[f], e = start[f + 1];
    const uint2* x8 = (const uint2*)x;
    float a0 = 0.f, a1 = 0.f, a2 = 0.f, a3 = 0.f;
    for (int i = s; i < e; i++) {
        uint2 raw = x8[(size_t)i * 32 + lane];
        float2 f0 = unpack_bf2(raw.x), f1 = unpack_bf2(raw.y);
        a0 += f0.x; a1 += f0.y; a2 += f1.x; a3 += f1.y;
    }
    float inv = 1.0f / (float)max(e - s, 1);
    ((float4*)pool)[(size_t)f * 32 + lane] = make_float4(a0 * inv, a1 * inv, a2 * inv, a3 * inv);
}

__global__ void assemble_kernel(const float* __restrict__ pool, const float* __restrict__ emb,
                                const int* __restrict__ src, const int* __restrict__ isext,
                                float* __restrict__ fx) {
    int i = blockIdx.x * blockDim.x + threadIdx.x;
    if (i >= N_FCG * D_H) return;
    int row = i >> 7, j = i & 127;
    int s = src[row];
    float v;
    if (isext[row] == 1) {
        int k = min(max(s, 0), VOCAB - 1);
        v = emb[(size_t)k * D_H + j];
    } else {
        int k = min(max(s, 0), N_FUNC - 1);
        v = pool[(size_t)k * D_H + j];
    }
    fx[i] = v;
}

__global__ __launch_bounds__(128) void gpool_kernel(
    const float* __restrict__ y, const int* __restrict__ start, float* __restrict__ g) {
    int b = blockIdx.x, col = threadIdx.x;
    int s = start[b], e = start[b + 1];
    float acc = 0.f;
    for (int i = s; i < e; i++) acc += y[(size_t)i * 128 + col];
    g[b * 128 + col] = acc / (float)max(e - s, 1);
}

__global__ __launch_bounds__(256) void head_kernel(
    const float* __restrict__ g,
    const float* __restrict__ Wp1, const float* __restrict__ bp1,
    const float* __restrict__ Wp2, const float* __restrict__ bp2,
    const float* __restrict__ Wp3, const float* __restrict__ bp3,
    float* __restrict__ out) {
    __shared__ float G[NB * 128], H1[NB * 64], H2[NB * 32];
    int t = threadIdx.x;
    for (int i = t; i < NB * 128; i += 256) G[i] = g[i];
    __syncthreads();
    for (int i = t; i < NB * 64; i += 256) {
        int r = i >> 6, c = i & 63;
        float a = bp1[c];
        for (int k = 0; k < 128; k++) a += G[r * 128 + k] * Wp1[k * 64 + c];
        H1[i] = fmaxf(a, 0.f);
    }
    __syncthreads();
    for (int i = t; i < NB * 32; i += 256) {
        int r = i >> 5, c = i & 31;
        float a = bp2[c];
        for (int k = 0; k < 64; k++) a += H1[r * 64 + k] * Wp2[k * 32 + c];
        H2[i] = fmaxf(a, 0.f);
    }
    __syncthreads();
    if (t < NB) {
        float a = bp3[0];
        for (int k = 0; k < 32; k++) a += H2[t * 32 + k] * Wp3[k];
        out[t] = 1.0f / (1.0f + expf(-a));
    }
}

// ---------------- launch ----------------------------------------------------
extern "C" void kernel_launch(void* const* d_in, const int* in_sizes, int n_in,
                              void* d_out, int out_size) {
    const float* cfg_x  = (const float*)d_in[0];
    const int*   cfg_ei = (const int*)  d_in[1];
    const int*   n2f    = (const int*)  d_in[2];
    const int*   fcg_ei = (const int*)  d_in[3];
    const int*   fbatch = (const int*)  d_in[4];
    const int*   fsrc   = (const int*)  d_in[5];
    const int*   fext   = (const int*)  d_in[6];
    const float* W1  = (const float*)d_in[7];
    const float* b1  = (const float*)d_in[8];
    const float* W2  = (const float*)d_in[9];
    const float* b2  = (const float*)d_in[10];
    const float* emb = (const float*)d_in[11];
    const float* Wf  = (const float*)d_in[12];
    const float* bf  = (const float*)d_in[13];
    const float* Wp1 = (const float*)d_in[14];
    const float* bp1 = (const float*)d_in[15];
    const float* Wp2 = (const float*)d_in[16];
    const float* bp2 = (const float*)d_in[17];
    const float* Wp3 = (const float*)d_in[18];
    const float* bp3 = (const float*)d_in[19];
    float* out = (float*)d_out;

    void *p;
    cudaGetSymbolAddress(&p, g_b);       float* Bb     = (float*)p;
    cudaGetSymbolAddress(&p, g_hb);      __nv_bfloat16* HB = (__nv_bfloat16*)p;
    cudaGetSymbolAddress(&p, g_wb1);     __nv_bfloat16* Wb1 = (__nv_bfloat16*)p;
    cudaGetSymbolAddress(&p, g_wb2);     __nv_bfloat16* Wb2 = (__nv_bfloat16*)p;
    cudaGetSymbolAddress(&p, g_deg);     int*   deg    = (int*)p;
    cudaGetSymbolAddress(&p, g_dis);     float* dis    = (float*)p;
    cudaGetSymbolAddress(&p, g_rowptr);  int*   rowptr = (int*)p;
    cudaGetSymbolAddress(&p, g_csr);     int*   csr    = (int*)p;
    cudaGetSymbolAddress(&p, g_fdeg);    int*   fdeg   = (int*)p;
    cudaGetSymbolAddress(&p, g_fdis);    float* fdis   = (float*)p;
    cudaGetSymbolAddress(&p, g_frowptr); int*   frowptr= (int*)p;
    cudaGetSymbolAddress(&p, g_fcsr);    int*   fcsr   = (int*)p;
    cudaGetSymbolAddress(&p, g_fstart);  int*   fstart = (int*)p;
    cudaGetSymbolAddress(&p, g_bstart);  int*   bstart = (int*)p;
    cudaGetSymbolAddress(&p, g_pool);    float* pool   = (float*)p;
    cudaGetSymbolAddress(&p, g_fx);      float* fx     = (float*)p;
    cudaGetSymbolAddress(&p, g_fz);      float* fz     = (float*)p;
    cudaGetSymbolAddress(&p, g_fy);      float* fy     = (float*)p;
    cudaGetSymbolAddress(&p, g_g);       float* gg     = (float*)p;

    unsigned* xb  = (unsigned*)Bb;
    unsigned* z1b = (unsigned*)Bb + (size_t)N_CFG * 32;
    uint4*    z2b = (uint4*)Bb;

    // prolog: init + degrees + norms
    init_kernel<<<(N_CFG + 255) / 256, 256>>>(W1, W2);
    deg_all_kernel<<<(E_CFG + E_FCG + 255) / 256, 256>>>(cfg_ei, fcg_ei);
    dis_all_kernel<<<(N_CFG + N_FCG + 255) / 256, 256>>>();

    // CSR build (CFG+FCG merged per stage)
    scan_local_all<<<NBLK_CFG + NBLK_FCG, 256>>>();
    scan_bsum_all<<<2, 512>>>();
    scan_add_all<<<(N_CFG + N_FCG + 255) / 256, 256>>>();
    fill_csr_all<<<(E_CFG + E_FCG + 255) / 256, 256>>>(cfg_ei, fcg_ei);
    bounds_all_kernel<<<(N_FUNC + NB + 2 + 255) / 256, 256>>>(n2f, fbatch);

    // CFG layer 1 (quarter-warp unrolled gathers)
    tobf_kernel<<<(N_CFG * 32 + 255) / 256, 256>>>((const float2*)cfg_x, dis, xb);
    gather64bf_kernel<<<(N_CFG + 31) / 32, 256>>>(rowptr, deg, csr,
                                                  (const uint4*)xb, dis, (uint4*)z1b, N_CFG);
    gemmw_kernel<64, true, true><<<N_CFG / 128, 256>>>(
        (const __nv_bfloat16*)z1b, Wb1, b1, dis, nullptr, HB, N_CFG);

    // CFG layer 2
    gather128bf_kernel<<<(N_CFG + 31) / 32, 256>>>(rowptr, deg, csr, HB, dis, z2b, N_CFG);
    gemmw_kernel<128, false, true><<<N_CFG / 128, 256>>>(
        (const __nv_bfloat16*)z2b, Wb2, b2, dis, nullptr, HB, N_CFG);

    // function-level mean pool (bf16 input)
    poolsegbf_kernel<<<(N_FUNC * 32 + 255) / 256, 256>>>(HB, fstart, pool, N_FUNC);

    // FCG features + FCG layer (fp32)
    assemble_kernel<<<(N_FCG * D_H) / 256, 256>>>(pool, emb, fsrc, fext, fx);
    gather128_kernel<<<(N_FCG * 32 + 255) / 256, 256>>>(frowptr, fdeg, fcsr, fx, fdis, fz, N_FCG);
    gemmx_kernel<128, false><<<(N_FCG + 127) / 128, 256>>>(fz, Wf, bf, fdis, fy, N_FCG);

    // binary-level mean pool + head
    gpool_kernel<<<NB, 128>>>(fy, bstart, gg);
    head_kernel<<<1, 256>>>(gg, Wp1, bp1, Wp2, bp2, Wp3, bp3, out);
}

// round 13
// speedup vs baseline: 2.2766x; 1.0388x over previous
#include <cuda_runtime.h>
#include <cuda_bf16.h>
#include <mma.h>
#include <math.h>

using namespace nvcuda;

#define N_CFG 400000
#define E_CFG 1600000
#define N_FUNC 8000
#define N_FCG 9600
#define E_FCG 80000
#define NB 8
#define D_H 128
#define VOCAB 10002
#define FULLMASK 0xffffffffu

// ---------------- scratch (device globals) ----------------------------------
__device__ float g_b [(size_t)N_CFG * D_H];
__device__ __nv_bfloat16 g_hb[(size_t)N_CFG * D_H];
__device__ __nv_bfloat16 g_wb1[64 * 128];
__device__ __nv_bfloat16 g_wb2[128 * 128];
__device__ int   g_deg[N_CFG];
__device__ float g_dis[N_CFG];
__device__ int   g_rowptr[N_CFG];
__device__ int   g_cursor[N_CFG];
__device__ int   g_csr[E_CFG];
__device__ int   g_fdeg[N_FCG];
__device__ float g_fdis[N_FCG];
__device__ int   g_frowptr[N_FCG];
__device__ int   g_fcursor[N_FCG];
__device__ int   g_fcsr[E_FCG];
__device__ int   g_bsum[512];          // [0..399]=CFG blocks, [400..]=FCG blocks
__device__ int   g_fstart[N_FUNC + 1];
__device__ int   g_bstart[NB + 1];
__device__ float g_pool[N_FUNC * D_H];
__device__ float g_fx [N_FCG * D_H];
__device__ float g_fz [N_FCG * D_H];
__device__ float g_fy [N_FCG * D_H];
__device__ float g_g  [NB * D_H];

#define NBLK_CFG ((N_CFG + 1023) / 1024)   // 391
#define NBLK_FCG ((N_FCG + 1023) / 1024)   // 10
#define FBSUM 400

static __device__ __forceinline__ unsigned pack_bf2(float a, float b) {
    __nv_bfloat162 h = __float22bfloat162_rn(make_float2(a, b));
    return *reinterpret_cast<unsigned*>(&h);
}
static __device__ __forceinline__ float2 unpack_bf2(unsigned u) {
    return __bfloat1622float2(*reinterpret_cast<const __nv_bfloat162*>(&u));
}

// ---------------- init: zero degs + weight->bf16 ------------------------------
__global__ void init_kernel(const float* __restrict__ W1, const float* __restrict__ W2) {
    int i = blockIdx.x * blockDim.x + threadIdx.x;
    if (i < N_CFG) g_deg[i] = 0;
    if (i < N_FCG) g_fdeg[i] = 0;
    if (i < 64 * 128) g_wb1[i] = __float2bfloat16(W1[i]);
    if (i >= 64 * 128 && i < 64 * 128 + 128 * 128)
        g_wb2[i - 64 * 128] = __float2bfloat16(W2[i - 64 * 128]);
}
__global__ void deg_all_kernel(const int* __restrict__ cei, const int* __restrict__ fei) {
    int i = blockIdx.x * blockDim.x + threadIdx.x;
    if (i < E_CFG) {
        atomicAdd(&g_deg[cei[E_CFG + i]], 1);
    } else if (i < E_CFG + E_FCG) {
        atomicAdd(&g_fdeg[fei[E_FCG + (i - E_CFG)]], 1);
    }
}

// ---------------- CSR build (CFG+FCG merged per stage; dis fused in) ---------
__device__ __forceinline__ void scan_local_body(const int* cnt, int n, int* out,
                                                int* bsum, float* dis, int blk, int t) {
    __shared__ int s[256];
    int base = blk * 1024;
    int v[4], sum = 0;
#pragma unroll
    for (int j = 0; j < 4; j++) {
        int i = base + t * 4 + j;
        v[j] = (i < n) ? cnt[i] : 0;
        if (i < n) dis[i] = rsqrtf((float)v[j] + 1.0f);   // fused norm
        sum += v[j];
    }
    s[t] = sum;
    __syncthreads();
    for (int off = 1; off < 256; off <<= 1) {
        int x = (t >= off) ? s[t - off] : 0;
        __syncthreads();
        s[t] += x;
        __syncthreads();
    }
    if (t == 255) bsum[blk] = s[255];
    int run = (t > 0) ? s[t - 1] : 0;
#pragma unroll
    for (int j = 0; j < 4; j++) {
        int i = base + t * 4 + j;
        if (i < n) out[i] = run;
        run += v[j];
    }
}
__global__ void scan_local_all() {
    if (blockIdx.x < NBLK_CFG)
        scan_local_body(g_deg, N_CFG, g_rowptr, g_bsum, g_dis, blockIdx.x, threadIdx.x);
    else
        scan_local_body(g_fdeg, N_FCG, g_frowptr, g_bsum + FBSUM, g_fdis,
                        blockIdx.x - NBLK_CFG, threadIdx.x);
}
__global__ void scan_bsum_all() {
    __shared__ int s[512];
    int* bsum = (blockIdx.x == 0) ? g_bsum : g_bsum + FBSUM;
    int nb = (blockIdx.x == 0) ? NBLK_CFG : NBLK_FCG;
    int t = threadIdx.x;
    s[t] = (t < nb) ? bsum[t] : 0;
    __syncthreads();
    for (int off = 1; off < 512; off <<= 1) {
        int x = (t >= off) ? s[t - off] : 0;
        __syncthreads();
        s[t] += x;
        __syncthreads();
    }
    if (t < nb) bsum[t] = (t > 0) ? s[t - 1] : 0;
}
// scan_add + segment bounds, one grid
__global__ void scan_add_all(const int* __restrict__ n2f, const int* __restrict__ fbatch) {
    int i = blockIdx.x * blockDim.x + threadIdx.x;
    if (i < N_CFG) {
        int v = g_rowptr[i] + g_bsum[i >> 10];
        g_rowptr[i] = v;
        g_cursor[i] = v;
    } else if (i < N_CFG + N_FCG) {
        int j = i - N_CFG;
        int v = g_frowptr[j] + g_bsum[FBSUM + (j >> 10)];
        g_frowptr[j] = v;
        g_fcursor[j] = v;
    } else if (i <= N_CFG + N_FCG + N_FUNC) {
        int f = i - (N_CFG + N_FCG);
        int lo = 0, hi = N_CFG;
        while (lo < hi) {
            int mid = (lo + hi) >> 1;
            if (n2f[mid] < f) lo = mid + 1; else hi = mid;
        }
        g_fstart[f] = lo;
    } else if (i <= N_CFG + N_FCG + N_FUNC + 1 + NB) {
        int f = i - (N_CFG + N_FCG + N_FUNC + 1);
        int lo = 0, hi = N_FCG;
        while (lo < hi) {
            int mid = (lo + hi) >> 1;
            if (fbatch[mid] < f) lo = mid + 1; else hi = mid;
        }
        g_bstart[f] = lo;
    }
}
__global__ void fill_csr_all(const int* __restrict__ cei, const int* __restrict__ fei) {
    int i = blockIdx.x * blockDim.x + threadIdx.x;
    if (i < E_CFG) {
        int r = cei[i], c = cei[E_CFG + i];
        int slot = atomicAdd(&g_cursor[c], 1);
        g_csr[slot] = r;
    } else if (i < E_CFG + E_FCG) {
        int j = i - E_CFG;
        int r = fei[j], c = fei[E_FCG + j];
        int slot = atomicAdd(&g_fcursor[c], 1);
        g_fcsr[slot] = r;
    }
}

// ---------------- WMMA bf16 GEMM ---------------------------------------------
template<int K, bool SCALE, bool OUTBF16>
__global__ __launch_bounds__(256, 2) void gemmw_kernel(
    const __nv_bfloat16* __restrict__ X, const __nv_bfloat16* __restrict__ Wb,
    const float* __restrict__ bias, const float* __restrict__ dis,
    float* __restrict__ H, __nv_bfloat16* __restrict__ HB, int N) {
    constexpr int AP = 40;
    constexpr int WP = 136;
    __shared__ __nv_bfloat16 As[128 * AP];
    __shared__ __nv_bfloat16 Ws[32 * WP];
    __shared__ float Eb[8][16 * 20];
    __shared__ float Bs[128];

    const int tid = threadIdx.x;
    const int warp = tid >> 5, lane = tid & 31;
    const int wr = warp >> 2;
    const int wc = warp & 3;
    const int row0 = blockIdx.x * 128;

    if (tid < 128) Bs[tid] = bias[tid];

    wmma::fragment<wmma::accumulator, 16, 16, 16, float> acc[4][2];
#pragma unroll
    for (int i = 0; i < 4; i++)
#pragma unroll
        for (int j = 0; j < 2; j++) wmma::fill_fragment(acc[i][j], 0.0f);

    const unsigned* Xu = (const unsigned*)X;
    const unsigned* Wu = (const unsigned*)Wb;
    unsigned* Asu = (unsigned*)As;
    unsigned* Wsu = (unsigned*)Ws;

    for (int kc = 0; kc < K; kc += 32) {
#pragma unroll
        for (int i = tid; i < 128 * 16; i += 256) {
            int r = i >> 4, k2 = i & 15;
            Asu[r * (AP / 2) + k2] = Xu[(size_t)(row0 + r) * (K / 2) + (kc >> 1) + k2];
        }
#pragma unroll
        for (int i = tid; i < 32 * 64; i += 256) {
            int k = i >> 6, c2 = i & 63;
            Wsu[k * (WP / 2) + c2] = Wu[(size_t)(kc + k) * 64 + c2];
        }
        __syncthreads();
#pragma unroll
        for (int ks = 0; ks < 32; ks += 16) {
            wmma::fragment<wmma::matrix_a, 16, 16, 16, __nv_bfloat16, wmma::row_major> af[4];
            wmma::fragment<wmma::matrix_b, 16, 16, 16, __nv_bfloat16, wmma::row_major> bf[2];
#pragma unroll
            for (int i = 0; i < 4; i++)
                wmma::load_matrix_sync(af[i], &As[(wr * 64 + i * 16) * AP + ks], AP);
#pragma unroll
            for (int j = 0; j < 2; j++)
                wmma::load_matrix_sync(bf[j], &Ws[ks * WP + wc * 32 + j * 16], WP);
#pragma unroll
            for (int i = 0; i < 4; i++)
#pragma unroll
                for (int j = 0; j < 2; j++)
                    wmma::mma_sync(acc[i][j], af[i], bf[j], acc[i][j]);
        }
        __syncthreads();
    }

    const int r = lane >> 1, c8 = (lane & 1) * 8;
#pragma unroll
    for (int i = 0; i < 4; i++) {
#pragma unroll
        for (int j = 0; j < 2; j++) {
            wmma::store_matrix_sync(&Eb[warp][0], acc[i][j], 20, wmma::mem_row_major);
            __syncwarp();
            int gr = row0 + wr * 64 + i * 16 + r;
            int gc = wc * 32 + j * 16 + c8;
            float s = SCALE ? dis[gr] : 1.0f;
            float o[8];
#pragma unroll
            for (int q = 0; q < 8; q++)
                o[q] = fmaxf(Eb[warp][r * 20 + c8 + q] + Bs[gc + q], 0.0f) * s;
            if (OUTBF16) {
                uint4 pk;
                pk.x = pack_bf2(o[0], o[1]); pk.y = pack_bf2(o[2], o[3]);
                pk.z = pack_bf2(o[4], o[5]); pk.w = pack_bf2(o[6], o[7]);
                *(uint4*)&HB[(size_t)gr * 128 + gc] = pk;
            } else {
                *(float4*)&H[(size_t)gr * 128 + gc]     = make_float4(o[0], o[1], o[2], o[3]);
                *(float4*)&H[(size_t)gr * 128 + gc + 4] = make_float4(o[4], o[5], o[6], o[7]);
            }
            __syncwarp();
        }
    }
}

// ---------------- FFMA2 GEMM (fp32, FCG) --------------------------------------
template<int K, bool SCALE>
__global__ __launch_bounds__(256, 2) void gemmx_kernel(
    const float* __restrict__ X, const float* __restrict__ W,
    const float* __restrict__ bias, const float* __restrict__ dis,
    float* __restrict__ H, int N) {
    __shared__ float Xs[32 * 132];
    __shared__ float Ws[32 * 128];
    const int row0 = blockIdx.x * 128;
    const int tx = threadIdx.x & 15;
    const int ty = threadIdx.x >> 4;
    const int c0 = tx * 8, r0 = ty * 8;

    unsigned long long acc2[8][4];
#pragma unroll
    for (int r = 0; r < 8; r++)
#pragma unroll
        for (int j = 0; j < 4; j++) acc2[r][j] = 0ULL;

    for (int kc = 0; kc < K; kc += 32) {
#pragma unroll
        for (int i = threadIdx.x; i < 128 * 32; i += 256) {
            int k = i & 31, r = i >> 5;
            int gr = row0 + r;
            Xs[k * 132 + r] = (gr < N) ? X[(size_t)gr * K + kc + k] : 0.f;
        }
#pragma unroll
        for (int i = threadIdx.x; i < 32 * 128; i += 256) {
            int c = i & 127, k = i >> 7;
            Ws[k * 128 + c] = W[(size_t)(kc + k) * 128 + c];
        }
        __syncthreads();
#pragma unroll 4
        for (int k = 0; k < 32; k++) {
            float4 al = *(const float4*)&Xs[k * 132 + r0];
            float4 ah = *(const float4*)&Xs[k * 132 + r0 + 4];
            ulonglong2 wl = *(const ulonglong2*)&Ws[k * 128 + c0];
            ulonglong2 wh = *(const ulonglong2*)&Ws[k * 128 + c0 + 4];
            unsigned long long w2[4];
            w2[0] = wl.x; w2[1] = wl.y; w2[2] = wh.x; w2[3] = wh.y;
            float a[8];
            a[0] = al.x; a[1] = al.y; a[2] = al.z; a[3] = al.w;
            a[4] = ah.x; a[5] = ah.y; a[6] = ah.z; a[7] = ah.w;
#pragma unroll
            for (int r = 0; r < 8; r++) {
                unsigned long long a2;
                asm("mov.b64 %0, {%1, %1};" : "=l"(a2) : "f"(a[r]));
#pragma unroll
                for (int j = 0; j < 4; j++)
                    asm("fma.rn.f32x2 %0, %1, %2, %0;"
                        : "+l"(acc2[r][j]) : "l"(a2), "l"(w2[j]));
            }
        }
        __syncthreads();
    }

    float bb[8];
#pragma unroll
    for (int j = 0; j < 8; j++) bb[j] = bias[c0 + j];
#pragma unroll
    for (int r = 0; r < 8; r++) {
        int gr = row0 + r0 + r;
        if (gr >= N) return;
        float s = SCALE ? dis[gr] : 1.0f;
        float o[8];
#pragma unroll
        for (int j = 0; j < 4; j++) {
            float lo, hi;
            asm("mov.b64 {%0, %1}, %2;" : "=f"(lo), "=f"(hi) : "l"(acc2[r][j]));
            o[2 * j]     = fmaxf(lo + bb[2 * j], 0.f) * s;
            o[2 * j + 1] = fmaxf(hi + bb[2 * j + 1], 0.f) * s;
        }
        *(float4*)&H[(size_t)gr * 128 + c0]     = make_float4(o[0], o[1], o[2], o[3]);
        *(float4*)&H[(size_t)gr * 128 + c0 + 4] = make_float4(o[4], o[5], o[6], o[7]);
    }
}

// ---------------- gather 64ch direct from fp32 cfg_x (tobf fused) -------------
// quarter-warp per node: 8 lanes x 2 float4 (32B) = 256B fp32 row.
// z1[v] = (x[v]*dis[v] + sum_u x[u]*dis[u]) * dis[v] -> bf16 out
__global__ __launch_bounds__(256) void gather64f_kernel(
    const int* __restrict__ rowptr, const int* __restrict__ deg,
    const int* __restrict__ csr, const float4* __restrict__ x,
    const float* __restrict__ dis, uint4* __restrict__ out, int n) {
    int lane = threadIdx.x & 31;
    int q = lane >> 3;
    int sub = lane & 7;
    int node = ((blockIdx.x * 256 + threadIdx.x) >> 5) * 4 + q;
    if (node >= n) return;
    int start = rowptr[node], d = deg[node];
    int dm = min(d, 8);
    int uidx = (sub < dm) ? csr[start + sub] : 0;
    int u[8];
#pragma unroll
    for (int j = 0; j < 8; j++) u[j] = __shfl_sync(FULLMASK, uidx, (q << 3) + j);
    float dn = dis[node];
    float a[8];
    {
        float4 s0 = x[(size_t)node * 16 + sub * 2];
        float4 s1 = x[(size_t)node * 16 + sub * 2 + 1];
        a[0] = s0.x * dn; a[1] = s0.y * dn; a[2] = s0.z * dn; a[3] = s0.w * dn;
        a[4] = s1.x * dn; a[5] = s1.y * dn; a[6] = s1.z * dn; a[7] = s1.w * dn;
    }
#pragma unroll
    for (int j = 0; j < 8; j++) {
        if (j < dm) {
            float du = dis[u[j]];
            float4 r0 = x[(size_t)u[j] * 16 + sub * 2];
            float4 r1 = x[(size_t)u[j] * 16 + sub * 2 + 1];
            a[0] += r0.x * du; a[1] += r0.y * du; a[2] += r0.z * du; a[3] += r0.w * du;
            a[4] += r1.x * du; a[5] += r1.y * du; a[6] += r1.z * du; a[7] += r1.w * du;
        }
    }
    for (int e = 8; e < d; e++) {       // ~2% of nodes
        int uu = csr[start + e];
        float du = dis[uu];
        float4 r0 = x[(size_t)uu * 16 + sub * 2];
        float4 r1 = x[(size_t)uu * 16 + sub * 2 + 1];
        a[0] += r0.x * du; a[1] += r0.y * du; a[2] += r0.z * du; a[3] += r0.w * du;
        a[4] += r1.x * du; a[5] += r1.y * du; a[6] += r1.z * du; a[7] += r1.w * du;
    }
    uint4 pk;
    pk.x = pack_bf2(a[0] * dn, a[1] * dn);
    pk.y = pack_bf2(a[2] * dn, a[3] * dn);
    pk.z = pack_bf2(a[4] * dn, a[5] * dn);
    pk.w = pack_bf2(a[6] * dn, a[7] * dn);
    out[(size_t)node * 8 + sub] = pk;
}

// ---------------- gather 128ch bf16, quarter-warp, fully unrolled -------------
__global__ __launch_bounds__(256) void gather128bf_kernel(
    const int* __restrict__ rowptr, const int* __restrict__ deg,
    const int* __restrict__ csr, const __nv_bfloat16* __restrict__ hb,
    const float* __restrict__ dis, uint4* __restrict__ out, int n) {
    int lane = threadIdx.x & 31;
    int q = lane >> 3;
    int sub = lane & 7;
    int node = ((blockIdx.x * 256 + threadIdx.x) >> 5) * 4 + q;
    if (node >= n) return;
    const uint4* h16 = (const uint4*)hb;
    int start = rowptr[node], d = deg[node];
    int dm = min(d, 8);
    int uidx = (sub < dm) ? csr[start + sub] : 0;
    int u[8];
#pragma unroll
    for (int j = 0; j < 8; j++) u[j] = __shfl_sync(FULLMASK, uidx, (q << 3) + j);
    float acc[16];
    {
        uint4 r0 = h16[(size_t)node * 16 + sub];
        uint4 r1 = h16[(size_t)node * 16 + 8 + sub];
        float2 f0 = unpack_bf2(r0.x), f1 = unpack_bf2(r0.y);
        float2 f2 = unpack_bf2(r0.z), f3 = unpack_bf2(r0.w);
        float2 g0 = unpack_bf2(r1.x), g1 = unpack_bf2(r1.y);
        float2 g2 = unpack_bf2(r1.z), g3 = unpack_bf2(r1.w);
        acc[0] = f0.x;  acc[1] = f0.y;  acc[2] = f1.x;  acc[3] = f1.y;
        acc[4] = f2.x;  acc[5] = f2.y;  acc[6] = f3.x;  acc[7] = f3.y;
        acc[8] = g0.x;  acc[9] = g0.y;  acc[10] = g1.x; acc[11] = g1.y;
        acc[12] = g2.x; acc[13] = g2.y; acc[14] = g3.x; acc[15] = g3.y;
    }
#pragma unroll
    for (int j = 0; j < 8; j++) {
        if (j < dm) {
            uint4 r0 = h16[(size_t)u[j] * 16 + sub];
            uint4 r1 = h16[(size_t)u[j] * 16 + 8 + sub];
            float2 f0 = unpack_bf2(r0.x), f1 = unpack_bf2(r0.y);
            float2 f2 = unpack_bf2(r0.z), f3 = unpack_bf2(r0.w);
            float2 g0 = unpack_bf2(r1.x), g1 = unpack_bf2(r1.y);
            float2 g2 = unpack_bf2(r1.z), g3 = unpack_bf2(r1.w);
            acc[0] += f0.x;  acc[1] += f0.y;  acc[2] += f1.x;  acc[3] += f1.y;
            acc[4] += f2.x;  acc[5] += f2.y;  acc[6] += f3.x;  acc[7] += f3.y;
            acc[8] += g0.x;  acc[9] += g0.y;  acc[10] += g1.x; acc[11] += g1.y;
            acc[12] += g2.x; acc[13] += g2.y; acc[14] += g3.x; acc[15] += g3.y;
        }
    }
    for (int e = 8; e < d; e++) {
        int uu = csr[start + e];
        uint4 r0 = h16[(size_t)uu * 16 + sub];
        uint4 r1 = h16[(size_t)uu * 16 + 8 + sub];
        float2 f0 = unpack_bf2(r0.x), f1 = unpack_bf2(r0.y);
        float2 f2 = unpack_bf2(r0.z), f3 = unpack_bf2(r0.w);
        float2 g0 = unpack_bf2(r1.x), g1 = unpack_bf2(r1.y);
        float2 g2 = unpack_bf2(r1.z), g3 = unpack_bf2(r1.w);
        acc[0] += f0.x;  acc[1] += f0.y;  acc[2] += f1.x;  acc[3] += f1.y;
        acc[4] += f2.x;  acc[5] += f2.y;  acc[6] += f3.x;  acc[7] += f3.y;
        acc[8] += g0.x;  acc[9] += g0.y;  acc[10] += g1.x; acc[11] += g1.y;
        acc[12] += g2.x; acc[13] += g2.y; acc[14] += g3.x; acc[15] += g3.y;
    }
    float dn = dis[node];
    uint4 pk0, pk1;
    pk0.x = pack_bf2(acc[0] * dn, acc[1] * dn);
    pk0.y = pack_bf2(acc[2] * dn, acc[3] * dn);
    pk0.z = pack_bf2(acc[4] * dn, acc[5] * dn);
    pk0.w = pack_bf2(acc[6] * dn, acc[7] * dn);
    pk1.x = pack_bf2(acc[8] * dn, acc[9] * dn);
    pk1.y = pack_bf2(acc[10] * dn, acc[11] * dn);
    pk1.z = pack_bf2(acc[12] * dn, acc[13] * dn);
    pk1.w = pack_bf2(acc[14] * dn, acc[15] * dn);
    out[(size_t)node * 16 + sub] = pk0;
    out[(size_t)node * 16 + 8 + sub] = pk1;
}

// ---------------- gather 128ch fp32 (FCG), shuffle indices -------------------
__global__ __launch_bounds__(256) void gather128_kernel(
    const int* __restrict__ rowptr, const int* __restrict__ deg,
    const int* __restrict__ csr, const float* __restrict__ hs,
    const float* __restrict__ dis, float* __restrict__ out, int n) {
    int node = (blockIdx.x * 256 + threadIdx.x) >> 5;
    int lane = threadIdx.x & 31;
    if (node >= n) return;
    const float4* hs4 = (const float4*)hs;
    int start = rowptr[node], d = deg[node];
    int dm = min(d, 32);
    int uidx = (lane < dm) ? csr[start + lane] : 0;
    float dn = dis[node];
    float4 acc = hs4[(size_t)node * 32 + lane];
    acc.x *= dn; acc.y *= dn; acc.z *= dn; acc.w *= dn;
    for (int e = 0; e < dm; e++) {
        int u = __shfl_sync(FULLMASK, uidx, e);
        float du = dis[u];
        float4 v = hs4[(size_t)u * 32 + lane];
        acc.x += v.x * du; acc.y += v.y * du;
        acc.z += v.z * du; acc.w += v.w * du;
    }
    for (int e = 32; e < d; e++) {
        int u = csr[start + e];
        float du = dis[u];
        float4 v = hs4[(size_t)u * 32 + lane];
        acc.x += v.x * du; acc.y += v.y * du;
        acc.z += v.z * du; acc.w += v.w * du;
    }
    acc.x *= dn; acc.y *= dn; acc.z *= dn; acc.w *= dn;
    ((float4*)out)[(size_t)node * 32 + lane] = acc;
}

// ---------------- function-level mean pool (bf16 input) -----------------------
__global__ __launch_bounds__(256) void poolsegbf_kernel(
    const __nv_bfloat16* __restrict__ x, const int* __restrict__ start,
    float* __restrict__ pool, int nseg) {
    int f = (blockIdx.x * 256 + threadIdx.x) >> 5;
    int lane = threadIdx.x & 31;
    if (f >= nseg) return;
    int s = start[f], e = start[f + 1];
    const uint2* x8 = (const uint2*)x;
    float a0 = 0.f, a1 = 0.f, a2 = 0.f, a3 = 0.f;
    for (int i = s; i < e; i++) {
        uint2 raw = x8[(size_t)i * 32 + lane];
        float2 f0 = unpack_bf2(raw.x), f1 = unpack_bf2(raw.y);
        a0 += f0.x; a1 += f0.y; a2 += f1.x; a3 += f1.y;
    }
    float inv = 1.0f / (float)max(e - s, 1);
    ((float4*)pool)[(size_t)f * 32 + lane] = make_float4(a0 * inv, a1 * inv, a2 * inv, a3 * inv);
}

__global__ void assemble_kernel(const float* __restrict__ pool, const float* __restrict__ emb,
                                const int* __restrict__ src, const int* __restrict__ isext,
                                float* __restrict__ fx) {
    int i = blockIdx.x * blockDim.x + threadIdx.x;
    if (i >= N_FCG * D_H) return;
    int row = i >> 7, j = i & 127;
    int s = src[row];
    float v;
    if (isext[row] == 1) {
        int k = min(max(s, 0), VOCAB - 1);
        v = emb[(size_t)k * D_H + j];
    } else {
        int k = min(max(s, 0), N_FUNC - 1);
        v = pool[(size_t)k * D_H + j];
    }
    fx[i] = v;
}

__global__ __launch_bounds__(128) void gpool_kernel(
    const float* __restrict__ y, const int* __restrict__ start, float* __restrict__ g) {
    int b = blockIdx.x, col = threadIdx.x;
    int s = start[b], e = start[b + 1];
    float acc = 0.f;
    for (int i = s; i < e; i++) acc += y[(size_t)i * 128 + col];
    g[b * 128 + col] = acc / (float)max(e - s, 1);
}

__global__ __launch_bounds__(256) void head_kernel(
    const float* __restrict__ g,
    const float* __restrict__ Wp1, const float* __restrict__ bp1,
    const float* __restrict__ Wp2, const float* __restrict__ bp2,
    const float* __restrict__ Wp3, const float* __restrict__ bp3,
    float* __restrict__ out) {
    __shared__ float G[NB * 128], H1[NB * 64], H2[NB * 32];
    int t = threadIdx.x;
    for (int i = t; i < NB * 128; i += 256) G[i] = g[i];
    __syncthreads();
    for (int i = t; i < NB * 64; i += 256) {
        int r = i >> 6, c = i & 63;
        float a = bp1[c];
        for (int k = 0; k < 128; k++) a += G[r * 128 + k] * Wp1[k * 64 + c];
        H1[i] = fmaxf(a, 0.f);
    }
    __syncthreads();
    for (int i = t; i < NB * 32; i += 256) {
        int r = i >> 5, c = i & 31;
        float a = bp2[c];
        for (int k = 0; k < 64; k++) a += H1[r * 64 + k] * Wp2[k * 32 + c];
        H2[i] = fmaxf(a, 0.f);
    }
    __syncthreads();
    if (t < NB) {
        float a = bp3[0];
        for (int k = 0; k < 32; k++) a += H2[t * 32 + k] * Wp3[k];
        out[t] = 1.0f / (1.0f + expf(-a));
    }
}

// ---------------- launch ----------------------------------------------------
extern "C" void kernel_launch(void* const* d_in, const int* in_sizes, int n_in,
                              void* d_out, int out_size) {
    const float* cfg_x  = (const float*)d_in[0];
    const int*   cfg_ei = (const int*)  d_in[1];
    const int*   n2f    = (const int*)  d_in[2];
    const int*   fcg_ei = (const int*)  d_in[3];
    const int*   fbatch = (const int*)  d_in[4];
    const int*   fsrc   = (const int*)  d_in[5];
    const int*   fext   = (const int*)  d_in[6];
    const float* W1  = (const float*)d_in[7];
    const float* b1  = (const float*)d_in[8];
    const float* W2  = (const float*)d_in[9];
    const float* b2  = (const float*)d_in[10];
    const float* emb = (const float*)d_in[11];
    const float* Wf  = (const float*)d_in[12];
    const float* bf  = (const float*)d_in[13];
    const float* Wp1 = (const float*)d_in[14];
    const float* bp1 = (const float*)d_in[15];
    const float* Wp2 = (const float*)d_in[16];
    const float* bp2 = (const float*)d_in[17];
    const float* Wp3 = (const float*)d_in[18];
    const float* bp3 = (const float*)d_in[19];
    float* out = (float*)d_out;

    void *p;
    cudaGetSymbolAddress(&p, g_b);       float* Bb     = (float*)p;
    cudaGetSymbolAddress(&p, g_hb);      __nv_bfloat16* HB = (__nv_bfloat16*)p;
    cudaGetSymbolAddress(&p, g_wb1);     __nv_bfloat16* Wb1 = (__nv_bfloat16*)p;
    cudaGetSymbolAddress(&p, g_wb2);     __nv_bfloat16* Wb2 = (__nv_bfloat16*)p;
    cudaGetSymbolAddress(&p, g_deg);     int*   deg    = (int*)p;
    cudaGetSymbolAddress(&p, g_dis);     float* dis    = (float*)p;
    cudaGetSymbolAddress(&p, g_rowptr);  int*   rowptr = (int*)p;
    cudaGetSymbolAddress(&p, g_csr);     int*   csr    = (int*)p;
    cudaGetSymbolAddress(&p, g_fdeg);    int*   fdeg   = (int*)p;
    cudaGetSymbolAddress(&p, g_fdis);    float* fdis   = (float*)p;
    cudaGetSymbolAddress(&p, g_frowptr); int*   frowptr= (int*)p;
    cudaGetSymbolAddress(&p, g_fcsr);    int*   fcsr   = (int*)p;
    cudaGetSymbolAddress(&p, g_fstart);  int*   fstart = (int*)p;
    cudaGetSymbolAddress(&p, g_bstart);  int*   bstart = (int*)p;
    cudaGetSymbolAddress(&p, g_pool);    float* pool   = (float*)p;
    cudaGetSymbolAddress(&p, g_fx);      float* fx     = (float*)p;
    cudaGetSymbolAddress(&p, g_fz);      float* fz     = (float*)p;
    cudaGetSymbolAddress(&p, g_fy);      float* fy     = (float*)p;
    cudaGetSymbolAddress(&p, g_g);       float* gg     = (float*)p;

    unsigned* z1b = (unsigned*)Bb;                 // gather1 out, 64ch bf16
    uint4*    z2b = (uint4*)Bb + (size_t)N_CFG * 8;  // gather2 out, 128ch bf16 (disjoint region)

    // prolog: init + degrees (dis fused into scan)
    init_kernel<<<(N_CFG + 255) / 256, 256>>>(W1, W2);
    deg_all_kernel<<<(E_CFG + E_FCG + 255) / 256, 256>>>(cfg_ei, fcg_ei);

    // CSR build (CFG+FCG merged per stage; dis in scan_local; bounds in scan_add)
    scan_local_all<<<NBLK_CFG + NBLK_FCG, 256>>>();
    scan_bsum_all<<<2, 512>>>();
    scan_add_all<<<(N_CFG + N_FCG + N_FUNC + NB + 2 + 255) / 256, 256>>>(n2f, fbatch);
    fill_csr_all<<<(E_CFG + E_FCG + 255) / 256, 256>>>(cfg_ei, fcg_ei);

    // CFG layer 1 (direct fp32 gather, tobf fused)
    gather64f_kernel<<<(N_CFG + 31) / 32, 256>>>(rowptr, deg, csr,
                                                 (const float4*)cfg_x, dis, (uint4*)z1b, N_CFG);
    gemmw_kernel<64, true, true><<<N_CFG / 128, 256>>>(
        (const __nv_bfloat16*)z1b, Wb1, b1, dis, nullptr, HB, N_CFG);

    // CFG layer 2
    gather128bf_kernel<<<(N_CFG + 31) / 32, 256>>>(rowptr, deg, csr, HB, dis, z2b, N_CFG);
    gemmw_kernel<128, false, true><<<N_CFG / 128, 256>>>(
        (const __nv_bfloat16*)z2b, Wb2, b2, dis, nullptr, HB, N_CFG);

    // function-level mean pool (bf16 input)
    poolsegbf_kernel<<<(N_FUNC * 32 + 255) / 256, 256>>>(HB, fstart, pool, N_FUNC);

    // FCG features + FCG layer (fp32)
    assemble_kernel<<<(N_FCG * D_H) / 256, 256>>>(pool, emb, fsrc, fext, fx);
    gather128_kernel<<<(N_FCG * 32 + 255) / 256, 256>>>(frowptr, fdeg, fcsr, fx, fdis, fz, N_FCG);
    gemmx_kernel<128, false><<<(N_FCG + 127) / 128, 256>>>(fz, Wf, bf, fdis, fy, N_FCG);

    // binary-level mean pool + head
    gpool_kernel<<<NB, 128>>>(fy, bstart, gg);
    head_kernel<<<1, 256>>>(gg, Wp1, bp1, Wp2, bp2, Wp3, bp3, out);
}